// round 1
// baseline (speedup 1.0000x reference)
#include <cuda_runtime.h>
#include <math.h>

static constexpr int SEQ   = 2048;
static constexpr int DM    = 2048;
static constexpr int NHEAD = 16;
static constexpr int HDIM  = 128;
static constexpr int NROWS = 4096;   // B * L

// ---------------- scratch (device globals; no allocation allowed) ----------
__device__ __align__(16) float g_h  [(size_t)NROWS * DM];          // rmsnorm out (reused)
__device__ __align__(16) float g_qkv[(size_t)NROWS * 3 * DM];      // qkv proj
__device__ __align__(16) float g_q  [(size_t)NROWS * DM];          // [B,H,L,HD]
__device__ __align__(16) float g_k  [(size_t)NROWS * DM];
__device__ __align__(16) float g_v  [(size_t)NROWS * DM];
__device__ __align__(16) float g_o  [(size_t)NROWS * DM];          // attn out [B,L,D]
__device__ __align__(16) float g_x1 [(size_t)NROWS * DM];          // post-attn residual
__device__ __align__(16) float g_p  [(size_t)NROWS * 8 * DM];      // ffn proj
__device__ __align__(16) float g_ff [(size_t)NROWS * 4 * DM];      // swiglu out

// ---------------- RMSNorm: one block per row --------------------------------
__global__ __launch_bounds__(256)
void rmsnorm_kernel(const float* __restrict__ x, const float* __restrict__ g,
                    float* __restrict__ out)
{
    int row = blockIdx.x;
    int tid = threadIdx.x;
    const float4* xr = (const float4*)(x + (size_t)row * DM);
    const float4* gr = (const float4*)g;
    float4* orow = (float4*)(out + (size_t)row * DM);
    float4 v0 = xr[tid];
    float4 v1 = xr[tid + 256];
    float ss = v0.x*v0.x + v0.y*v0.y + v0.z*v0.z + v0.w*v0.w
             + v1.x*v1.x + v1.y*v1.y + v1.z*v1.z + v1.w*v1.w;
    #pragma unroll
    for (int off = 16; off > 0; off >>= 1)
        ss += __shfl_xor_sync(0xffffffffu, ss, off);
    __shared__ float wsum[8];
    if ((tid & 31) == 0) wsum[tid >> 5] = ss;
    __syncthreads();
    float tot = wsum[0]+wsum[1]+wsum[2]+wsum[3]+wsum[4]+wsum[5]+wsum[6]+wsum[7];
    float sc = rsqrtf(tot * (1.0f / (float)DM) + 1e-8f);
    float4 ga = gr[tid], gb = gr[tid + 256];
    float4 o0 = make_float4(v0.x*sc*ga.x, v0.y*sc*ga.y, v0.z*sc*ga.z, v0.w*sc*ga.w);
    float4 o1 = make_float4(v1.x*sc*gb.x, v1.y*sc*gb.y, v1.z*sc*gb.z, v1.w*sc*gb.w);
    orow[tid]       = o0;
    orow[tid + 256] = o1;
}

// ---------------- SGEMM: C[M,N] = A[M,K] @ B[K,N] + bias (+ residual) -------
// 128x128 block tile, BK=16, 8x8 per thread, 256 threads.
__global__ __launch_bounds__(256)
void sgemm_kernel(const float* __restrict__ A, const float* __restrict__ B,
                  const float* __restrict__ bias, const float* __restrict__ res,
                  float* __restrict__ C, int M, int N, int K)
{
    __shared__ float As[16][128];   // transposed: As[k][m]
    __shared__ float Bs[16][128];   // Bs[k][n]
    int tid = threadIdx.x;
    const float* Ab = A + (size_t)blockIdx.y * 128 * K;
    const float* Bb = B + (size_t)blockIdx.x * 128;
    int tx = tid & 15;        // 16 col-groups of 8
    int ty = tid >> 4;        // 16 row-groups of 8
    int aRow = tid >> 2;          // 0..63
    int aCol = (tid & 3) * 4;     // 0,4,8,12
    int bRow = tid >> 5;          // 0..7
    int bCol = (tid & 31) * 4;    // 0..124

    float acc[8][8];
    #pragma unroll
    for (int i = 0; i < 8; i++)
        #pragma unroll
        for (int j = 0; j < 8; j++) acc[i][j] = 0.0f;

    for (int k0 = 0; k0 < K; k0 += 16) {
        float4 a0 = *(const float4*)(Ab + (size_t)aRow        * K + k0 + aCol);
        float4 a1 = *(const float4*)(Ab + (size_t)(aRow + 64) * K + k0 + aCol);
        float4 b0 = *(const float4*)(Bb + (size_t)(k0 + bRow)     * N + bCol);
        float4 b1 = *(const float4*)(Bb + (size_t)(k0 + bRow + 8) * N + bCol);
        As[aCol+0][aRow] = a0.x; As[aCol+1][aRow] = a0.y;
        As[aCol+2][aRow] = a0.z; As[aCol+3][aRow] = a0.w;
        As[aCol+0][aRow+64] = a1.x; As[aCol+1][aRow+64] = a1.y;
        As[aCol+2][aRow+64] = a1.z; As[aCol+3][aRow+64] = a1.w;
        *(float4*)&Bs[bRow][bCol]     = b0;
        *(float4*)&Bs[bRow + 8][bCol] = b1;
        __syncthreads();
        #pragma unroll
        for (int k = 0; k < 16; k++) {
            float rm[8], rn[8];
            *(float4*)&rm[0] = *(const float4*)&As[k][ty*8];
            *(float4*)&rm[4] = *(const float4*)&As[k][ty*8+4];
            *(float4*)&rn[0] = *(const float4*)&Bs[k][tx*8];
            *(float4*)&rn[4] = *(const float4*)&Bs[k][tx*8+4];
            #pragma unroll
            for (int i = 0; i < 8; i++)
                #pragma unroll
                for (int j = 0; j < 8; j++)
                    acc[i][j] = fmaf(rm[i], rn[j], acc[i][j]);
        }
        __syncthreads();
    }

    int row0 = blockIdx.y * 128 + ty * 8;
    int col0 = blockIdx.x * 128 + tx * 8;
    #pragma unroll
    for (int i = 0; i < 8; i++) {
        size_t off = (size_t)(row0 + i) * N + col0;
        #pragma unroll
        for (int j = 0; j < 8; j += 4) {
            float4 o;
            o.x = acc[i][j+0] + bias[col0+j+0];
            o.y = acc[i][j+1] + bias[col0+j+1];
            o.z = acc[i][j+2] + bias[col0+j+2];
            o.w = acc[i][j+3] + bias[col0+j+3];
            if (res) {
                float4 r = *(const float4*)(res + off + j);
                o.x += r.x; o.y += r.y; o.z += r.z; o.w += r.w;
            }
            *(float4*)(C + off + j) = o;
        }
    }
}

// ---------------- RoPE + head split: qkv[B,L,3D] -> Q/K/V [B,H,L,HD] --------
__global__ __launch_bounds__(256)
void rope_split_kernel(const float* __restrict__ qkv)
{
    int idx = blockIdx.x * 256 + threadIdx.x;   // NROWS * NHEAD * 64 threads
    int i   = idx & 63;
    int h   = (idx >> 6) & 15;
    int row = idx >> 10;          // b*SEQ + l
    int l   = row & (SEQ - 1);
    int b   = row >> 11;
    const float* base = qkv + (size_t)row * (3 * DM) + h * HDIM;
    float q0 = base[i],          q1 = base[i + 64];
    float k0 = base[DM + i],     k1 = base[DM + i + 64];
    float v0 = base[2*DM + i],   v1 = base[2*DM + i + 64];
    float invf = powf(10000.0f, -(float)(2 * i) * (1.0f / 128.0f));
    float ang = (float)l * invf;
    float sn, cs;
    sincosf(ang, &sn, &cs);
    size_t ob = ((size_t)((b * NHEAD + h) * SEQ + l)) * HDIM;
    g_q[ob + i]      = q0 * cs - q1 * sn;
    g_q[ob + i + 64] = q1 * cs + q0 * sn;
    g_k[ob + i]      = k0 * cs - k1 * sn;
    g_k[ob + i + 64] = k1 * cs + k0 * sn;
    g_v[ob + i]      = v0;
    g_v[ob + i + 64] = v1;
}

// ---------------- causal flash attention ------------------------------------
// CTA: 128 threads, 16 queries x full HD. Key tiles of 32. Online softmax.
// Thread (m = tid/8, g = tid%8): owns query row m, d-columns {g*4 + 32*w}.
__global__ __launch_bounds__(128)
void attn_kernel(const float* __restrict__ Q, const float* __restrict__ K,
                 const float* __restrict__ V, float* __restrict__ O)
{
    __shared__ __align__(16) float Qs[16][132];
    __shared__ __align__(16) float Ks[32][132];
    __shared__ __align__(16) float Vs[32][132];
    __shared__ float Ps[16][33];

    int tid = threadIdx.x;
    int bh  = blockIdx.y;               // b*NHEAD + h
    int q0  = blockIdx.x * 16;
    const float* Qb = Q + (size_t)bh * SEQ * HDIM;
    const float* Kb = K + (size_t)bh * SEQ * HDIM;
    const float* Vb = V + (size_t)bh * SEQ * HDIM;

    {   // load Q tile: 16 rows, 8 threads/row, 4 float4 each
        int r = tid >> 3, lane = tid & 7;
        const float* src = Qb + (size_t)(q0 + r) * HDIM;
        #pragma unroll
        for (int t = 0; t < 4; t++) {
            int f4 = lane + 8 * t;
            *(float4*)&Qs[r][f4 * 4] = *(const float4*)(src + f4 * 4);
        }
    }

    int m = tid >> 3;
    int g = tid & 7;
    int qg = q0 + m;
    float mrow = -INFINITY, lrow = 0.0f;
    float4 o0 = make_float4(0,0,0,0), o1 = o0, o2 = o0, o3 = o0;
    const float scale = 0.08838834764831845f;   // 1/sqrt(128)
    int kend = q0 + 16;
    int kr = tid >> 2, klane = tid & 3;

    for (int n0 = 0; n0 < kend; n0 += 32) {
        __syncthreads();
        {
            const float* ksrc = Kb + (size_t)(n0 + kr) * HDIM;
            const float* vsrc = Vb + (size_t)(n0 + kr) * HDIM;
            #pragma unroll
            for (int t = 0; t < 8; t++) {
                int f4 = klane + 4 * t;
                *(float4*)&Ks[kr][f4 * 4] = *(const float4*)(ksrc + f4 * 4);
                *(float4*)&Vs[kr][f4 * 4] = *(const float4*)(vsrc + f4 * 4);
            }
        }
        __syncthreads();

        // scores: thread handles keys n = n0 + j*8 + g
        float s[4] = {0, 0, 0, 0};
        const float4* qrow = (const float4*)&Qs[m][0];
        #pragma unroll 8
        for (int d4 = 0; d4 < 32; d4++) {
            float4 q4 = qrow[d4];
            #pragma unroll
            for (int j = 0; j < 4; j++) {
                float4 k4 = *(const float4*)&Ks[j*8 + g][d4 * 4];
                s[j] = fmaf(q4.x, k4.x, s[j]);
                s[j] = fmaf(q4.y, k4.y, s[j]);
                s[j] = fmaf(q4.z, k4.z, s[j]);
                s[j] = fmaf(q4.w, k4.w, s[j]);
            }
        }
        float tmax = -INFINITY;
        #pragma unroll
        for (int j = 0; j < 4; j++) {
            int n = n0 + j*8 + g;
            s[j] = (n <= qg) ? s[j] * scale : -INFINITY;
            tmax = fmaxf(tmax, s[j]);
        }
        #pragma unroll
        for (int off = 4; off > 0; off >>= 1)
            tmax = fmaxf(tmax, __shfl_xor_sync(0xffffffffu, tmax, off));
        float mnew = fmaxf(mrow, tmax);
        float corr = expf(mrow - mnew);
        float p[4], psum = 0.0f;
        #pragma unroll
        for (int j = 0; j < 4; j++) { p[j] = expf(s[j] - mnew); psum += p[j]; }
        #pragma unroll
        for (int off = 4; off > 0; off >>= 1)
            psum += __shfl_xor_sync(0xffffffffu, psum, off);
        lrow = lrow * corr + psum;
        mrow = mnew;
        o0.x *= corr; o0.y *= corr; o0.z *= corr; o0.w *= corr;
        o1.x *= corr; o1.y *= corr; o1.z *= corr; o1.w *= corr;
        o2.x *= corr; o2.y *= corr; o2.z *= corr; o2.w *= corr;
        o3.x *= corr; o3.y *= corr; o3.z *= corr; o3.w *= corr;
        #pragma unroll
        for (int j = 0; j < 4; j++) Ps[m][j*8 + g] = p[j];
        __syncwarp();
        #pragma unroll 4
        for (int n = 0; n < 32; n++) {
            float pv = Ps[m][n];
            float4 v;
            v = *(const float4*)&Vs[n][(g +  0) * 4];
            o0.x = fmaf(pv, v.x, o0.x); o0.y = fmaf(pv, v.y, o0.y);
            o0.z = fmaf(pv, v.z, o0.z); o0.w = fmaf(pv, v.w, o0.w);
            v = *(const float4*)&Vs[n][(g +  8) * 4];
            o1.x = fmaf(pv, v.x, o1.x); o1.y = fmaf(pv, v.y, o1.y);
            o1.z = fmaf(pv, v.z, o1.z); o1.w = fmaf(pv, v.w, o1.w);
            v = *(const float4*)&Vs[n][(g + 16) * 4];
            o2.x = fmaf(pv, v.x, o2.x); o2.y = fmaf(pv, v.y, o2.y);
            o2.z = fmaf(pv, v.z, o2.z); o2.w = fmaf(pv, v.w, o2.w);
            v = *(const float4*)&Vs[n][(g + 24) * 4];
            o3.x = fmaf(pv, v.x, o3.x); o3.y = fmaf(pv, v.y, o3.y);
            o3.z = fmaf(pv, v.z, o3.z); o3.w = fmaf(pv, v.w, o3.w);
        }
    }

    float inv = 1.0f / lrow;
    o0.x *= inv; o0.y *= inv; o0.z *= inv; o0.w *= inv;
    o1.x *= inv; o1.y *= inv; o1.z *= inv; o1.w *= inv;
    o2.x *= inv; o2.y *= inv; o2.z *= inv; o2.w *= inv;
    o3.x *= inv; o3.y *= inv; o3.z *= inv; o3.w *= inv;

    int b = bh >> 4, h = bh & 15;
    float* dst = O + ((size_t)(b * SEQ + qg)) * DM + h * HDIM;
    *(float4*)(dst + (g +  0) * 4) = o0;
    *(float4*)(dst + (g +  8) * 4) = o1;
    *(float4*)(dst + (g + 16) * 4) = o2;
    *(float4*)(dst + (g + 24) * 4) = o3;
}

// ---------------- SwiGLU: ff = silu(p[:, :4D]) * p[:, 4D:] ------------------
__global__ __launch_bounds__(256)
void swiglu_kernel()
{
    size_t idx = (size_t)blockIdx.x * 256 + threadIdx.x;  // NROWS*2048 float4s
    size_t row = idx >> 11;
    int c4 = (int)(idx & 2047);
    const float4* Pr = (const float4*)(g_p + row * (size_t)(8 * DM));
    float4 gt = Pr[c4];
    float4 vl = Pr[c4 + 2048];
    float4 r;
    r.x = gt.x / (1.0f + expf(-gt.x)) * vl.x;
    r.y = gt.y / (1.0f + expf(-gt.y)) * vl.y;
    r.z = gt.z / (1.0f + expf(-gt.z)) * vl.z;
    r.w = gt.w / (1.0f + expf(-gt.w)) * vl.w;
    ((float4*)g_ff)[idx] = r;
}

// ---------------- launch -----------------------------------------------------
extern "C" void kernel_launch(void* const* d_in, const int* in_sizes, int n_in,
                              void* d_out, int out_size)
{
    const float* x    = (const float*)d_in[0];
    const float* Wqkv = (const float*)d_in[1];
    const float* bqkv = (const float*)d_in[2];
    const float* Wo   = (const float*)d_in[3];
    const float* bo   = (const float*)d_in[4];
    const float* g1   = (const float*)d_in[5];
    const float* g2   = (const float*)d_in[6];
    const float* Wp   = (const float*)d_in[7];
    const float* bp   = (const float*)d_in[8];
    const float* Wff  = (const float*)d_in[9];
    const float* bff  = (const float*)d_in[10];
    float* out = (float*)d_out;

    float *pH, *pQKV, *pQ, *pK, *pV, *pO, *pX1, *pP, *pFF;
    cudaGetSymbolAddress((void**)&pH,   g_h);
    cudaGetSymbolAddress((void**)&pQKV, g_qkv);
    cudaGetSymbolAddress((void**)&pQ,   g_q);
    cudaGetSymbolAddress((void**)&pK,   g_k);
    cudaGetSymbolAddress((void**)&pV,   g_v);
    cudaGetSymbolAddress((void**)&pO,   g_o);
    cudaGetSymbolAddress((void**)&pX1,  g_x1);
    cudaGetSymbolAddress((void**)&pP,   g_p);
    cudaGetSymbolAddress((void**)&pFF,  g_ff);

    // 1. h = rms(x, g1)
    rmsnorm_kernel<<<NROWS, 256>>>(x, g1, pH);
    // 2. qkv = h @ Wqkv + bqkv            [4096, 6144]
    sgemm_kernel<<<dim3(6144/128, NROWS/128), 256>>>(pH, Wqkv, bqkv, nullptr, pQKV,
                                                     NROWS, 3*DM, DM);
    // 3. rope + split into Q/K/V [B,H,L,HD]
    rope_split_kernel<<<(NROWS * NHEAD * 64) / 256, 256>>>(pQKV);
    // 4. causal attention -> O [B,L,D]
    attn_kernel<<<dim3(SEQ/16, 2*NHEAD), 128>>>(pQ, pK, pV, pO);
    // 5. x1 = O @ Wo + bo + x
    sgemm_kernel<<<dim3(DM/128, NROWS/128), 256>>>(pO, Wo, bo, x, pX1,
                                                   NROWS, DM, DM);
    // 6. h2 = rms(x1, g2)
    rmsnorm_kernel<<<NROWS, 256>>>(pX1, g2, pH);
    // 7. p = h2 @ Wp + bp                 [4096, 16384]
    sgemm_kernel<<<dim3(16384/128, NROWS/128), 256>>>(pH, Wp, bp, nullptr, pP,
                                                      NROWS, 8*DM, DM);
    // 8. ff = silu(gate) * value          [4096, 8192]
    swiglu_kernel<<<(NROWS * 2048) / 256, 256>>>();
    // 9. out = ff @ Wff_out + bff + x1
    sgemm_kernel<<<dim3(DM/128, NROWS/128), 256>>>(pFF, Wff, bff, pX1, out,
                                                   NROWS, DM, 4*DM);
}

// round 2
// speedup vs baseline: 2.1498x; 2.1498x over previous
#include <cuda_runtime.h>
#include <math.h>
#include <stdint.h>

static constexpr int SEQ   = 2048;
static constexpr int DM    = 2048;
static constexpr int NHEAD = 16;
static constexpr int HDIM  = 128;
static constexpr int NROWS = 4096;   // B * L

// ---------------- scratch (device globals; no allocation allowed) ----------
__device__ __align__(16) float g_h  [(size_t)NROWS * DM];
__device__ __align__(16) float g_qkv[(size_t)NROWS * 3 * DM];
__device__ __align__(16) float g_q  [(size_t)NROWS * DM];
__device__ __align__(16) float g_k  [(size_t)NROWS * DM];
__device__ __align__(16) float g_v  [(size_t)NROWS * DM];
__device__ __align__(16) float g_o  [(size_t)NROWS * DM];
__device__ __align__(16) float g_x1 [(size_t)NROWS * DM];
__device__ __align__(16) float g_p  [(size_t)NROWS * 8 * DM];
__device__ __align__(16) float g_ff [(size_t)NROWS * 4 * DM];

__device__ __forceinline__ uint32_t f2tf32(float f) {
    uint32_t u;
    asm("cvt.rna.tf32.f32 %0, %1;" : "=r"(u) : "f"(f));
    return u;
}

// ---------------- RMSNorm: one block per row --------------------------------
__global__ __launch_bounds__(256)
void rmsnorm_kernel(const float* __restrict__ x, const float* __restrict__ g,
                    float* __restrict__ out)
{
    int row = blockIdx.x;
    int tid = threadIdx.x;
    const float4* xr = (const float4*)(x + (size_t)row * DM);
    const float4* gr = (const float4*)g;
    float4* orow = (float4*)(out + (size_t)row * DM);
    float4 v0 = xr[tid];
    float4 v1 = xr[tid + 256];
    float ss = v0.x*v0.x + v0.y*v0.y + v0.z*v0.z + v0.w*v0.w
             + v1.x*v1.x + v1.y*v1.y + v1.z*v1.z + v1.w*v1.w;
    #pragma unroll
    for (int off = 16; off > 0; off >>= 1)
        ss += __shfl_xor_sync(0xffffffffu, ss, off);
    __shared__ float wsum[8];
    if ((tid & 31) == 0) wsum[tid >> 5] = ss;
    __syncthreads();
    float tot = wsum[0]+wsum[1]+wsum[2]+wsum[3]+wsum[4]+wsum[5]+wsum[6]+wsum[7];
    float sc = rsqrtf(tot * (1.0f / (float)DM) + 1e-8f);
    float4 ga = gr[tid], gb = gr[tid + 256];
    float4 o0 = make_float4(v0.x*sc*ga.x, v0.y*sc*ga.y, v0.z*sc*ga.z, v0.w*sc*ga.w);
    float4 o1 = make_float4(v1.x*sc*gb.x, v1.y*sc*gb.y, v1.z*sc*gb.z, v1.w*sc*gb.w);
    orow[tid]       = o0;
    orow[tid + 256] = o1;
}

// ---------------- TF32 tensor-core GEMM -------------------------------------
// C[M,N] = A[M,K] @ B[K,N] + bias (+ residual)
// 128x128 CTA tile, BK=32, 256 threads = 8 warps (2 x 4), warp tile 64x32.
// mma.sync.aligned.m16n8k8.row.col.f32.tf32.tf32.f32
__global__ __launch_bounds__(256, 2)
void tgemm_kernel(const float* __restrict__ A, const float* __restrict__ B,
                  const float* __restrict__ bias, const float* __restrict__ res,
                  float* __restrict__ C, int M, int N, int K)
{
    __shared__ uint32_t As[128][36];    // [m][k], pad 36: frag loads conflict-free
    __shared__ uint32_t Bs[32][132];    // [k][n], pad 132

    int tid  = threadIdx.x;
    int wid  = tid >> 5, lane = tid & 31;
    int wm   = wid & 1;          // 0..1  -> 64 rows each
    int wn   = wid >> 1;         // 0..3  -> 32 cols each
    int g    = lane >> 2;        // 0..7
    int tig  = lane & 3;         // 0..3

    const float* Ab = A + (size_t)blockIdx.y * 128 * K;
    const float* Bb = B + (size_t)blockIdx.x * 128;

    float acc[4][4][4];
    #pragma unroll
    for (int i = 0; i < 4; i++)
        #pragma unroll
        for (int j = 0; j < 4; j++) {
            acc[i][j][0] = 0.f; acc[i][j][1] = 0.f;
            acc[i][j][2] = 0.f; acc[i][j][3] = 0.f;
        }

    for (int k0 = 0; k0 < K; k0 += 32) {
        // load A tile: 128 x 32, each thread 4 float4
        #pragma unroll
        for (int i = 0; i < 4; i++) {
            int idx = tid + 256 * i;
            int r   = idx >> 3;
            int c   = (idx & 7) * 4;
            float4 v = *(const float4*)(Ab + (size_t)r * K + k0 + c);
            As[r][c+0] = f2tf32(v.x); As[r][c+1] = f2tf32(v.y);
            As[r][c+2] = f2tf32(v.z); As[r][c+3] = f2tf32(v.w);
        }
        // load B tile: 32 x 128
        #pragma unroll
        for (int i = 0; i < 4; i++) {
            int idx = tid + 256 * i;
            int r   = idx >> 5;
            int c   = (idx & 31) * 4;
            float4 v = *(const float4*)(Bb + (size_t)(k0 + r) * N + c);
            Bs[r][c+0] = f2tf32(v.x); Bs[r][c+1] = f2tf32(v.y);
            Bs[r][c+2] = f2tf32(v.z); Bs[r][c+3] = f2tf32(v.w);
        }
        __syncthreads();

        #pragma unroll
        for (int ks = 0; ks < 4; ks++) {
            int kb = ks * 8;
            uint32_t af[4][4], bf[4][2];
            #pragma unroll
            for (int mi = 0; mi < 4; mi++) {
                int row = wm * 64 + mi * 16 + g;
                af[mi][0] = As[row    ][kb + tig];
                af[mi][1] = As[row + 8][kb + tig];
                af[mi][2] = As[row    ][kb + tig + 4];
                af[mi][3] = As[row + 8][kb + tig + 4];
            }
            #pragma unroll
            for (int ni = 0; ni < 4; ni++) {
                int col = wn * 32 + ni * 8 + g;
                bf[ni][0] = Bs[kb + tig    ][col];
                bf[ni][1] = Bs[kb + tig + 4][col];
            }
            #pragma unroll
            for (int mi = 0; mi < 4; mi++)
                #pragma unroll
                for (int ni = 0; ni < 4; ni++) {
                    asm volatile(
                        "mma.sync.aligned.m16n8k8.row.col.f32.tf32.tf32.f32 "
                        "{%0,%1,%2,%3}, {%4,%5,%6,%7}, {%8,%9}, {%0,%1,%2,%3};"
                        : "+f"(acc[mi][ni][0]), "+f"(acc[mi][ni][1]),
                          "+f"(acc[mi][ni][2]), "+f"(acc[mi][ni][3])
                        : "r"(af[mi][0]), "r"(af[mi][1]),
                          "r"(af[mi][2]), "r"(af[mi][3]),
                          "r"(bf[ni][0]), "r"(bf[ni][1]));
                }
        }
        __syncthreads();
    }

    // epilogue
    #pragma unroll
    for (int mi = 0; mi < 4; mi++) {
        #pragma unroll
        for (int ni = 0; ni < 4; ni++) {
            int row = blockIdx.y * 128 + wm * 64 + mi * 16 + g;
            int col = blockIdx.x * 128 + wn * 32 + ni * 8 + 2 * tig;
            float bx = bias[col], by = bias[col + 1];
            size_t off0 = (size_t)row * N + col;
            size_t off1 = (size_t)(row + 8) * N + col;
            float2 r0 = make_float2(acc[mi][ni][0] + bx, acc[mi][ni][1] + by);
            float2 r1 = make_float2(acc[mi][ni][2] + bx, acc[mi][ni][3] + by);
            if (res) {
                float2 q0 = *(const float2*)(res + off0);
                float2 q1 = *(const float2*)(res + off1);
                r0.x += q0.x; r0.y += q0.y;
                r1.x += q1.x; r1.y += q1.y;
            }
            *(float2*)(C + off0) = r0;
            *(float2*)(C + off1) = r1;
        }
    }
}

// ---------------- RoPE + head split: qkv[B,L,3D] -> Q/K/V [B,H,L,HD] --------
__global__ __launch_bounds__(256)
void rope_split_kernel(const float* __restrict__ qkv)
{
    int idx = blockIdx.x * 256 + threadIdx.x;
    int i   = idx & 63;
    int h   = (idx >> 6) & 15;
    int row = idx >> 10;          // b*SEQ + l
    int l   = row & (SEQ - 1);
    int b   = row >> 11;
    const float* base = qkv + (size_t)row * (3 * DM) + h * HDIM;
    float q0 = base[i],          q1 = base[i + 64];
    float k0 = base[DM + i],     k1 = base[DM + i + 64];
    float v0 = base[2*DM + i],   v1 = base[2*DM + i + 64];
    float invf = powf(10000.0f, -(float)(2 * i) * (1.0f / 128.0f));
    float ang = (float)l * invf;
    float sn, cs;
    sincosf(ang, &sn, &cs);
    size_t ob = ((size_t)((b * NHEAD + h) * SEQ + l)) * HDIM;
    g_q[ob + i]      = q0 * cs - q1 * sn;
    g_q[ob + i + 64] = q1 * cs + q0 * sn;
    g_k[ob + i]      = k0 * cs - k1 * sn;
    g_k[ob + i + 64] = k1 * cs + k0 * sn;
    g_v[ob + i]      = v0;
    g_v[ob + i + 64] = v1;
}

// ---------------- causal flash attention ------------------------------------
__global__ __launch_bounds__(128)
void attn_kernel(const float* __restrict__ Q, const float* __restrict__ K,
                 const float* __restrict__ V, float* __restrict__ O)
{
    __shared__ __align__(16) float Qs[16][132];
    __shared__ __align__(16) float Ks[32][132];
    __shared__ __align__(16) float Vs[32][132];
    __shared__ float Ps[16][33];

    int tid = threadIdx.x;
    int bh  = blockIdx.y;
    int q0  = blockIdx.x * 16;
    const float* Qb = Q + (size_t)bh * SEQ * HDIM;
    const float* Kb = K + (size_t)bh * SEQ * HDIM;
    const float* Vb = V + (size_t)bh * SEQ * HDIM;

    {
        int r = tid >> 3, lane = tid & 7;
        const float* src = Qb + (size_t)(q0 + r) * HDIM;
        #pragma unroll
        for (int t = 0; t < 4; t++) {
            int f4 = lane + 8 * t;
            *(float4*)&Qs[r][f4 * 4] = *(const float4*)(src + f4 * 4);
        }
    }

    int m = tid >> 3;
    int g = tid & 7;
    int qg = q0 + m;
    float mrow = -INFINITY, lrow = 0.0f;
    float4 o0 = make_float4(0,0,0,0), o1 = o0, o2 = o0, o3 = o0;
    const float scale = 0.08838834764831845f;
    int kend = q0 + 16;
    int kr = tid >> 2, klane = tid & 3;

    for (int n0 = 0; n0 < kend; n0 += 32) {
        __syncthreads();
        {
            const float* ksrc = Kb + (size_t)(n0 + kr) * HDIM;
            const float* vsrc = Vb + (size_t)(n0 + kr) * HDIM;
            #pragma unroll
            for (int t = 0; t < 8; t++) {
                int f4 = klane + 4 * t;
                *(float4*)&Ks[kr][f4 * 4] = *(const float4*)(ksrc + f4 * 4);
                *(float4*)&Vs[kr][f4 * 4] = *(const float4*)(vsrc + f4 * 4);
            }
        }
        __syncthreads();

        float s[4] = {0, 0, 0, 0};
        const float4* qrow = (const float4*)&Qs[m][0];
        #pragma unroll 8
        for (int d4 = 0; d4 < 32; d4++) {
            float4 q4 = qrow[d4];
            #pragma unroll
            for (int j = 0; j < 4; j++) {
                float4 k4 = *(const float4*)&Ks[j*8 + g][d4 * 4];
                s[j] = fmaf(q4.x, k4.x, s[j]);
                s[j] = fmaf(q4.y, k4.y, s[j]);
                s[j] = fmaf(q4.z, k4.z, s[j]);
                s[j] = fmaf(q4.w, k4.w, s[j]);
            }
        }
        float tmax = -INFINITY;
        #pragma unroll
        for (int j = 0; j < 4; j++) {
            int n = n0 + j*8 + g;
            s[j] = (n <= qg) ? s[j] * scale : -INFINITY;
            tmax = fmaxf(tmax, s[j]);
        }
        #pragma unroll
        for (int off = 4; off > 0; off >>= 1)
            tmax = fmaxf(tmax, __shfl_xor_sync(0xffffffffu, tmax, off));
        float mnew = fmaxf(mrow, tmax);
        float corr = expf(mrow - mnew);
        float p[4], psum = 0.0f;
        #pragma unroll
        for (int j = 0; j < 4; j++) { p[j] = expf(s[j] - mnew); psum += p[j]; }
        #pragma unroll
        for (int off = 4; off > 0; off >>= 1)
            psum += __shfl_xor_sync(0xffffffffu, psum, off);
        lrow = lrow * corr + psum;
        mrow = mnew;
        o0.x *= corr; o0.y *= corr; o0.z *= corr; o0.w *= corr;
        o1.x *= corr; o1.y *= corr; o1.z *= corr; o1.w *= corr;
        o2.x *= corr; o2.y *= corr; o2.z *= corr; o2.w *= corr;
        o3.x *= corr; o3.y *= corr; o3.z *= corr; o3.w *= corr;
        #pragma unroll
        for (int j = 0; j < 4; j++) Ps[m][j*8 + g] = p[j];
        __syncwarp();
        #pragma unroll 4
        for (int n = 0; n < 32; n++) {
            float pv = Ps[m][n];
            float4 v;
            v = *(const float4*)&Vs[n][(g +  0) * 4];
            o0.x = fmaf(pv, v.x, o0.x); o0.y = fmaf(pv, v.y, o0.y);
            o0.z = fmaf(pv, v.z, o0.z); o0.w = fmaf(pv, v.w, o0.w);
            v = *(const float4*)&Vs[n][(g +  8) * 4];
            o1.x = fmaf(pv, v.x, o1.x); o1.y = fmaf(pv, v.y, o1.y);
            o1.z = fmaf(pv, v.z, o1.z); o1.w = fmaf(pv, v.w, o1.w);
            v = *(const float4*)&Vs[n][(g + 16) * 4];
            o2.x = fmaf(pv, v.x, o2.x); o2.y = fmaf(pv, v.y, o2.y);
            o2.z = fmaf(pv, v.z, o2.z); o2.w = fmaf(pv, v.w, o2.w);
            v = *(const float4*)&Vs[n][(g + 24) * 4];
            o3.x = fmaf(pv, v.x, o3.x); o3.y = fmaf(pv, v.y, o3.y);
            o3.z = fmaf(pv, v.z, o3.z); o3.w = fmaf(pv, v.w, o3.w);
        }
    }

    float inv = 1.0f / lrow;
    o0.x *= inv; o0.y *= inv; o0.z *= inv; o0.w *= inv;
    o1.x *= inv; o1.y *= inv; o1.z *= inv; o1.w *= inv;
    o2.x *= inv; o2.y *= inv; o2.z *= inv; o2.w *= inv;
    o3.x *= inv; o3.y *= inv; o3.z *= inv; o3.w *= inv;

    int b = bh >> 4, h = bh & 15;
    float* dst = O + ((size_t)(b * SEQ + qg)) * DM + h * HDIM;
    *(float4*)(dst + (g +  0) * 4) = o0;
    *(float4*)(dst + (g +  8) * 4) = o1;
    *(float4*)(dst + (g + 16) * 4) = o2;
    *(float4*)(dst + (g + 24) * 4) = o3;
}

// ---------------- SwiGLU: ff = silu(p[:, :4D]) * p[:, 4D:] ------------------
__global__ __launch_bounds__(256)
void swiglu_kernel()
{
    size_t idx = (size_t)blockIdx.x * 256 + threadIdx.x;
    size_t row = idx >> 11;
    int c4 = (int)(idx & 2047);
    const float4* Pr = (const float4*)(g_p + row * (size_t)(8 * DM));
    float4 gt = Pr[c4];
    float4 vl = Pr[c4 + 2048];
    float4 r;
    r.x = gt.x / (1.0f + expf(-gt.x)) * vl.x;
    r.y = gt.y / (1.0f + expf(-gt.y)) * vl.y;
    r.z = gt.z / (1.0f + expf(-gt.z)) * vl.z;
    r.w = gt.w / (1.0f + expf(-gt.w)) * vl.w;
    ((float4*)g_ff)[idx] = r;
}

// ---------------- launch -----------------------------------------------------
extern "C" void kernel_launch(void* const* d_in, const int* in_sizes, int n_in,
                              void* d_out, int out_size)
{
    const float* x    = (const float*)d_in[0];
    const float* Wqkv = (const float*)d_in[1];
    const float* bqkv = (const float*)d_in[2];
    const float* Wo   = (const float*)d_in[3];
    const float* bo   = (const float*)d_in[4];
    const float* g1   = (const float*)d_in[5];
    const float* g2   = (const float*)d_in[6];
    const float* Wp   = (const float*)d_in[7];
    const float* bp   = (const float*)d_in[8];
    const float* Wff  = (const float*)d_in[9];
    const float* bff  = (const float*)d_in[10];
    float* out = (float*)d_out;

    float *pH, *pQKV, *pQ, *pK, *pV, *pO, *pX1, *pP, *pFF;
    cudaGetSymbolAddress((void**)&pH,   g_h);
    cudaGetSymbolAddress((void**)&pQKV, g_qkv);
    cudaGetSymbolAddress((void**)&pQ,   g_q);
    cudaGetSymbolAddress((void**)&pK,   g_k);
    cudaGetSymbolAddress((void**)&pV,   g_v);
    cudaGetSymbolAddress((void**)&pO,   g_o);
    cudaGetSymbolAddress((void**)&pX1,  g_x1);
    cudaGetSymbolAddress((void**)&pP,   g_p);
    cudaGetSymbolAddress((void**)&pFF,  g_ff);

    // 1. h = rms(x, g1)
    rmsnorm_kernel<<<NROWS, 256>>>(x, g1, pH);
    // 2. qkv = h @ Wqkv + bqkv            [4096, 6144]
    tgemm_kernel<<<dim3(6144/128, NROWS/128), 256>>>(pH, Wqkv, bqkv, nullptr, pQKV,
                                                     NROWS, 3*DM, DM);
    // 3. rope + split into Q/K/V [B,H,L,HD]
    rope_split_kernel<<<(NROWS * NHEAD * 64) / 256, 256>>>(pQKV);
    // 4. causal attention -> O [B,L,D]
    attn_kernel<<<dim3(SEQ/16, 2*NHEAD), 128>>>(pQ, pK, pV, pO);
    // 5. x1 = O @ Wo + bo + x
    tgemm_kernel<<<dim3(DM/128, NROWS/128), 256>>>(pO, Wo, bo, x, pX1,
                                                   NROWS, DM, DM);
    // 6. h2 = rms(x1, g2)
    rmsnorm_kernel<<<NROWS, 256>>>(pX1, g2, pH);
    // 7. p = h2 @ Wp + bp                 [4096, 16384]
    tgemm_kernel<<<dim3(16384/128, NROWS/128), 256>>>(pH, Wp, bp, nullptr, pP,
                                                      NROWS, 8*DM, DM);
    // 8. ff = silu(gate) * value          [4096, 8192]
    swiglu_kernel<<<(NROWS * 2048) / 256, 256>>>();
    // 9. out = ff @ Wff_out + bff + x1
    tgemm_kernel<<<dim3(DM/128, NROWS/128), 256>>>(pFF, Wff, bff, pX1, out,
                                                   NROWS, DM, 4*DM);
}

// round 3
// speedup vs baseline: 2.3659x; 1.1005x over previous
#include <cuda_runtime.h>
#include <math.h>
#include <stdint.h>

static constexpr int SEQ   = 2048;
static constexpr int DM    = 2048;
static constexpr int NHEAD = 16;
static constexpr int HDIM  = 128;
static constexpr int NROWS = 4096;   // B * L

// ---------------- scratch (device globals; no allocation allowed) ----------
__device__ __align__(16) float g_h  [(size_t)NROWS * DM];
__device__ __align__(16) float g_qkv[(size_t)NROWS * 3 * DM];
__device__ __align__(16) float g_q  [(size_t)NROWS * DM];
__device__ __align__(16) float g_k  [(size_t)NROWS * DM];
__device__ __align__(16) float g_v  [(size_t)NROWS * DM];
__device__ __align__(16) float g_o  [(size_t)NROWS * DM];
__device__ __align__(16) float g_x1 [(size_t)NROWS * DM];
__device__ __align__(16) float g_p  [(size_t)NROWS * 8 * DM];
__device__ __align__(16) float g_ff [(size_t)NROWS * 4 * DM];
// tf32-rounded weight copies: Wqkv | Wo | Wp | Wff  (67,108,864 floats)
__device__ __align__(16) float g_w  [(size_t)67108864];

__device__ __forceinline__ uint32_t f2tf32(float f) {
    uint32_t u;
    asm("cvt.rna.tf32.f32 %0, %1;" : "=r"(u) : "f"(f));
    return u;
}
__device__ __forceinline__ float tf32r(float f) { return __uint_as_float(f2tf32(f)); }

__device__ __forceinline__ void cp_async16(uint32_t smem, const void* g) {
    asm volatile("cp.async.cg.shared.global [%0], [%1], 16;" :: "r"(smem), "l"(g));
}
__device__ __forceinline__ void cp_commit() {
    asm volatile("cp.async.commit_group;");
}
template<int N> __device__ __forceinline__ void cp_wait() {
    asm volatile("cp.async.wait_group %0;" :: "n"(N));
}

// ---------------- weight tf32 pre-rounding ----------------------------------
__global__ __launch_bounds__(256)
void cvtw_kernel(const float4* __restrict__ src, float4* __restrict__ dst)
{
    int i = blockIdx.x * 256 + threadIdx.x;
    float4 v = src[i];
    v.x = tf32r(v.x); v.y = tf32r(v.y); v.z = tf32r(v.z); v.w = tf32r(v.w);
    dst[i] = v;
}

// ---------------- RMSNorm (tf32-rounded output) ------------------------------
__global__ __launch_bounds__(256)
void rmsnorm_kernel(const float* __restrict__ x, const float* __restrict__ g,
                    float* __restrict__ out)
{
    int row = blockIdx.x;
    int tid = threadIdx.x;
    const float4* xr = (const float4*)(x + (size_t)row * DM);
    const float4* gr = (const float4*)g;
    float4* orow = (float4*)(out + (size_t)row * DM);
    float4 v0 = xr[tid];
    float4 v1 = xr[tid + 256];
    float ss = v0.x*v0.x + v0.y*v0.y + v0.z*v0.z + v0.w*v0.w
             + v1.x*v1.x + v1.y*v1.y + v1.z*v1.z + v1.w*v1.w;
    #pragma unroll
    for (int off = 16; off > 0; off >>= 1)
        ss += __shfl_xor_sync(0xffffffffu, ss, off);
    __shared__ float wsum[8];
    if ((tid & 31) == 0) wsum[tid >> 5] = ss;
    __syncthreads();
    float tot = wsum[0]+wsum[1]+wsum[2]+wsum[3]+wsum[4]+wsum[5]+wsum[6]+wsum[7];
    float sc = rsqrtf(tot * (1.0f / (float)DM) + 1e-8f);
    float4 ga = gr[tid], gb = gr[tid + 256];
    float4 o0 = make_float4(tf32r(v0.x*sc*ga.x), tf32r(v0.y*sc*ga.y),
                            tf32r(v0.z*sc*ga.z), tf32r(v0.w*sc*ga.w));
    float4 o1 = make_float4(tf32r(v1.x*sc*gb.x), tf32r(v1.y*sc*gb.y),
                            tf32r(v1.z*sc*gb.z), tf32r(v1.w*sc*gb.w));
    orow[tid]       = o0;
    orow[tid + 256] = o1;
}

// ---------------- TF32 tensor-core GEMM, cp.async double-buffered ------------
// C[M,N] = A[M,K] @ B[K,N] + bias (+ residual)
// 128x128 CTA tile, BK=32, 2-stage pipeline, 256 threads = 8 warps (2x4),
// warp tile 64x32.  A/B are pre-rounded to tf32 values (raw bits fed to MMA).
__global__ __launch_bounds__(256, 2)
void tgemm_kernel(const float* __restrict__ A, const float* __restrict__ B,
                  const float* __restrict__ bias, const float* __restrict__ res,
                  float* __restrict__ C, int M, int N, int K)
{
    __shared__ float As[2][128][36];    // [stage][m][k], pad->conflict-free frags
    __shared__ float Bs[2][32][132];    // [stage][k][n]

    int tid  = threadIdx.x;
    int wid  = tid >> 5, lane = tid & 31;
    int wm   = wid & 1;          // 0..1  -> 64 rows each
    int wn   = wid >> 1;         // 0..3  -> 32 cols each
    int g    = lane >> 2;        // 0..7
    int tig  = lane & 3;         // 0..3

    const float* Ab = A + (size_t)blockIdx.y * 128 * K;
    const float* Bb = B + (size_t)blockIdx.x * 128;

    uint32_t as_base = (uint32_t)__cvta_generic_to_shared(&As[0][0][0]);
    uint32_t bs_base = (uint32_t)__cvta_generic_to_shared(&Bs[0][0][0]);

    // per-thread load chunk coordinates (4 x 16B for A, 4 x 16B for B)
    int arow[4], acol[4], brow[4], bcol[4];
    #pragma unroll
    for (int i = 0; i < 4; i++) {
        int c = tid + 256 * i;
        arow[i] = c >> 3;  acol[i] = (c & 7) * 4;
        brow[i] = c >> 5;  bcol[i] = (c & 31) * 4;
    }

    float acc[4][4][4];
    #pragma unroll
    for (int i = 0; i < 4; i++)
        #pragma unroll
        for (int j = 0; j < 4; j++) {
            acc[i][j][0] = 0.f; acc[i][j][1] = 0.f;
            acc[i][j][2] = 0.f; acc[i][j][3] = 0.f;
        }

    const int NT = K >> 5;

    // prologue: stage 0
    #pragma unroll
    for (int i = 0; i < 4; i++) {
        cp_async16(as_base + (uint32_t)((arow[i] * 36 + acol[i]) * 4),
                   Ab + (size_t)arow[i] * K + acol[i]);
        cp_async16(bs_base + (uint32_t)((brow[i] * 132 + bcol[i]) * 4),
                   Bb + (size_t)brow[i] * N + bcol[i]);
    }
    cp_commit();

    for (int t = 0; t < NT; t++) {
        int buf = t & 1;
        if (t + 1 < NT) {
            int nbuf = (t + 1) & 1;
            int k0   = (t + 1) * 32;
            uint32_t aoff = as_base + (uint32_t)(nbuf * 128 * 36 * 4);
            uint32_t boff = bs_base + (uint32_t)(nbuf * 32 * 132 * 4);
            #pragma unroll
            for (int i = 0; i < 4; i++) {
                cp_async16(aoff + (uint32_t)((arow[i] * 36 + acol[i]) * 4),
                           Ab + (size_t)arow[i] * K + k0 + acol[i]);
                cp_async16(boff + (uint32_t)((brow[i] * 132 + bcol[i]) * 4),
                           Bb + (size_t)(k0 + brow[i]) * N + bcol[i]);
            }
            cp_commit();
            cp_wait<1>();
        } else {
            cp_wait<0>();
        }
        __syncthreads();

        #pragma unroll
        for (int ks = 0; ks < 4; ks++) {
            int kb = ks * 8;
            uint32_t af[4][4], bf[4][2];
            #pragma unroll
            for (int mi = 0; mi < 4; mi++) {
                int row = wm * 64 + mi * 16 + g;
                af[mi][0] = __float_as_uint(As[buf][row    ][kb + tig]);
                af[mi][1] = __float_as_uint(As[buf][row + 8][kb + tig]);
                af[mi][2] = __float_as_uint(As[buf][row    ][kb + tig + 4]);
                af[mi][3] = __float_as_uint(As[buf][row + 8][kb + tig + 4]);
            }
            #pragma unroll
            for (int ni = 0; ni < 4; ni++) {
                int col = wn * 32 + ni * 8 + g;
                bf[ni][0] = __float_as_uint(Bs[buf][kb + tig    ][col]);
                bf[ni][1] = __float_as_uint(Bs[buf][kb + tig + 4][col]);
            }
            #pragma unroll
            for (int mi = 0; mi < 4; mi++)
                #pragma unroll
                for (int ni = 0; ni < 4; ni++) {
                    asm volatile(
                        "mma.sync.aligned.m16n8k8.row.col.f32.tf32.tf32.f32 "
                        "{%0,%1,%2,%3}, {%4,%5,%6,%7}, {%8,%9}, {%0,%1,%2,%3};"
                        : "+f"(acc[mi][ni][0]), "+f"(acc[mi][ni][1]),
                          "+f"(acc[mi][ni][2]), "+f"(acc[mi][ni][3])
                        : "r"(af[mi][0]), "r"(af[mi][1]),
                          "r"(af[mi][2]), "r"(af[mi][3]),
                          "r"(bf[ni][0]), "r"(bf[ni][1]));
                }
        }
        __syncthreads();
    }

    // epilogue
    #pragma unroll
    for (int mi = 0; mi < 4; mi++) {
        #pragma unroll
        for (int ni = 0; ni < 4; ni++) {
            int row = blockIdx.y * 128 + wm * 64 + mi * 16 + g;
            int col = blockIdx.x * 128 + wn * 32 + ni * 8 + 2 * tig;
            float bx = bias[col], by = bias[col + 1];
            size_t off0 = (size_t)row * N + col;
            size_t off1 = (size_t)(row + 8) * N + col;
            float2 r0 = make_float2(acc[mi][ni][0] + bx, acc[mi][ni][1] + by);
            float2 r1 = make_float2(acc[mi][ni][2] + bx, acc[mi][ni][3] + by);
            if (res) {
                float2 q0 = *(const float2*)(res + off0);
                float2 q1 = *(const float2*)(res + off1);
                r0.x += q0.x; r0.y += q0.y;
                r1.x += q1.x; r1.y += q1.y;
            }
            *(float2*)(C + off0) = r0;
            *(float2*)(C + off1) = r1;
        }
    }
}

// ---------------- RoPE + head split: qkv[B,L,3D] -> Q/K/V [B,H,L,HD] --------
__global__ __launch_bounds__(256)
void rope_split_kernel(const float* __restrict__ qkv)
{
    int idx = blockIdx.x * 256 + threadIdx.x;
    int i   = idx & 63;
    int h   = (idx >> 6) & 15;
    int row = idx >> 10;          // b*SEQ + l
    int l   = row & (SEQ - 1);
    int b   = row >> 11;
    const float* base = qkv + (size_t)row * (3 * DM) + h * HDIM;
    float q0 = base[i],          q1 = base[i + 64];
    float k0 = base[DM + i],     k1 = base[DM + i + 64];
    float v0 = base[2*DM + i],   v1 = base[2*DM + i + 64];
    float invf = powf(10000.0f, -(float)(2 * i) * (1.0f / 128.0f));
    float ang = (float)l * invf;
    float sn, cs;
    sincosf(ang, &sn, &cs);
    size_t ob = ((size_t)((b * NHEAD + h) * SEQ + l)) * HDIM;
    g_q[ob + i]      = q0 * cs - q1 * sn;
    g_q[ob + i + 64] = q1 * cs + q0 * sn;
    g_k[ob + i]      = k0 * cs - k1 * sn;
    g_k[ob + i + 64] = k1 * cs + k0 * sn;
    g_v[ob + i]      = v0;
    g_v[ob + i + 64] = v1;
}

// ---------------- causal flash attention (fp32; tf32-rounded O store) --------
__global__ __launch_bounds__(128)
void attn_kernel(const float* __restrict__ Q, const float* __restrict__ K,
                 const float* __restrict__ V, float* __restrict__ O)
{
    __shared__ __align__(16) float Qs[16][132];
    __shared__ __align__(16) float Ks[32][132];
    __shared__ __align__(16) float Vs[32][132];
    __shared__ float Ps[16][33];

    int tid = threadIdx.x;
    int bh  = blockIdx.y;
    int q0  = blockIdx.x * 16;
    const float* Qb = Q + (size_t)bh * SEQ * HDIM;
    const float* Kb = K + (size_t)bh * SEQ * HDIM;
    const float* Vb = V + (size_t)bh * SEQ * HDIM;

    {
        int r = tid >> 3, lane = tid & 7;
        const float* src = Qb + (size_t)(q0 + r) * HDIM;
        #pragma unroll
        for (int t = 0; t < 4; t++) {
            int f4 = lane + 8 * t;
            *(float4*)&Qs[r][f4 * 4] = *(const float4*)(src + f4 * 4);
        }
    }

    int m = tid >> 3;
    int g = tid & 7;
    int qg = q0 + m;
    float mrow = -INFINITY, lrow = 0.0f;
    float4 o0 = make_float4(0,0,0,0), o1 = o0, o2 = o0, o3 = o0;
    const float scale = 0.08838834764831845f;
    int kend = q0 + 16;
    int kr = tid >> 2, klane = tid & 3;

    for (int n0 = 0; n0 < kend; n0 += 32) {
        __syncthreads();
        {
            const float* ksrc = Kb + (size_t)(n0 + kr) * HDIM;
            const float* vsrc = Vb + (size_t)(n0 + kr) * HDIM;
            #pragma unroll
            for (int t = 0; t < 8; t++) {
                int f4 = klane + 4 * t;
                *(float4*)&Ks[kr][f4 * 4] = *(const float4*)(ksrc + f4 * 4);
                *(float4*)&Vs[kr][f4 * 4] = *(const float4*)(vsrc + f4 * 4);
            }
        }
        __syncthreads();

        float s[4] = {0, 0, 0, 0};
        const float4* qrow = (const float4*)&Qs[m][0];
        #pragma unroll 8
        for (int d4 = 0; d4 < 32; d4++) {
            float4 q4 = qrow[d4];
            #pragma unroll
            for (int j = 0; j < 4; j++) {
                float4 k4 = *(const float4*)&Ks[j*8 + g][d4 * 4];
                s[j] = fmaf(q4.x, k4.x, s[j]);
                s[j] = fmaf(q4.y, k4.y, s[j]);
                s[j] = fmaf(q4.z, k4.z, s[j]);
                s[j] = fmaf(q4.w, k4.w, s[j]);
            }
        }
        float tmax = -INFINITY;
        #pragma unroll
        for (int j = 0; j < 4; j++) {
            int n = n0 + j*8 + g;
            s[j] = (n <= qg) ? s[j] * scale : -INFINITY;
            tmax = fmaxf(tmax, s[j]);
        }
        #pragma unroll
        for (int off = 4; off > 0; off >>= 1)
            tmax = fmaxf(tmax, __shfl_xor_sync(0xffffffffu, tmax, off));
        float mnew = fmaxf(mrow, tmax);
        float corr = expf(mrow - mnew);
        float p[4], psum = 0.0f;
        #pragma unroll
        for (int j = 0; j < 4; j++) { p[j] = expf(s[j] - mnew); psum += p[j]; }
        #pragma unroll
        for (int off = 4; off > 0; off >>= 1)
            psum += __shfl_xor_sync(0xffffffffu, psum, off);
        lrow = lrow * corr + psum;
        mrow = mnew;
        o0.x *= corr; o0.y *= corr; o0.z *= corr; o0.w *= corr;
        o1.x *= corr; o1.y *= corr; o1.z *= corr; o1.w *= corr;
        o2.x *= corr; o2.y *= corr; o2.z *= corr; o2.w *= corr;
        o3.x *= corr; o3.y *= corr; o3.z *= corr; o3.w *= corr;
        #pragma unroll
        for (int j = 0; j < 4; j++) Ps[m][j*8 + g] = p[j];
        __syncwarp();
        #pragma unroll 4
        for (int n = 0; n < 32; n++) {
            float pv = Ps[m][n];
            float4 v;
            v = *(const float4*)&Vs[n][(g +  0) * 4];
            o0.x = fmaf(pv, v.x, o0.x); o0.y = fmaf(pv, v.y, o0.y);
            o0.z = fmaf(pv, v.z, o0.z); o0.w = fmaf(pv, v.w, o0.w);
            v = *(const float4*)&Vs[n][(g +  8) * 4];
            o1.x = fmaf(pv, v.x, o1.x); o1.y = fmaf(pv, v.y, o1.y);
            o1.z = fmaf(pv, v.z, o1.z); o1.w = fmaf(pv, v.w, o1.w);
            v = *(const float4*)&Vs[n][(g + 16) * 4];
            o2.x = fmaf(pv, v.x, o2.x); o2.y = fmaf(pv, v.y, o2.y);
            o2.z = fmaf(pv, v.z, o2.z); o2.w = fmaf(pv, v.w, o2.w);
            v = *(const float4*)&Vs[n][(g + 24) * 4];
            o3.x = fmaf(pv, v.x, o3.x); o3.y = fmaf(pv, v.y, o3.y);
            o3.z = fmaf(pv, v.z, o3.z); o3.w = fmaf(pv, v.w, o3.w);
        }
    }

    float inv = 1.0f / lrow;
    o0 = make_float4(tf32r(o0.x*inv), tf32r(o0.y*inv), tf32r(o0.z*inv), tf32r(o0.w*inv));
    o1 = make_float4(tf32r(o1.x*inv), tf32r(o1.y*inv), tf32r(o1.z*inv), tf32r(o1.w*inv));
    o2 = make_float4(tf32r(o2.x*inv), tf32r(o2.y*inv), tf32r(o2.z*inv), tf32r(o2.w*inv));
    o3 = make_float4(tf32r(o3.x*inv), tf32r(o3.y*inv), tf32r(o3.z*inv), tf32r(o3.w*inv));

    int b = bh >> 4, h = bh & 15;
    float* dst = O + ((size_t)(b * SEQ + qg)) * DM + h * HDIM;
    *(float4*)(dst + (g +  0) * 4) = o0;
    *(float4*)(dst + (g +  8) * 4) = o1;
    *(float4*)(dst + (g + 16) * 4) = o2;
    *(float4*)(dst + (g + 24) * 4) = o3;
}

// ---------------- SwiGLU (tf32-rounded output) -------------------------------
__global__ __launch_bounds__(256)
void swiglu_kernel()
{
    size_t idx = (size_t)blockIdx.x * 256 + threadIdx.x;
    size_t row = idx >> 11;
    int c4 = (int)(idx & 2047);
    const float4* Pr = (const float4*)(g_p + row * (size_t)(8 * DM));
    float4 gt = Pr[c4];
    float4 vl = Pr[c4 + 2048];
    float4 r;
    r.x = tf32r(gt.x / (1.0f + expf(-gt.x)) * vl.x);
    r.y = tf32r(gt.y / (1.0f + expf(-gt.y)) * vl.y);
    r.z = tf32r(gt.z / (1.0f + expf(-gt.z)) * vl.z);
    r.w = tf32r(gt.w / (1.0f + expf(-gt.w)) * vl.w);
    ((float4*)g_ff)[idx] = r;
}

// ---------------- launch -----------------------------------------------------
extern "C" void kernel_launch(void* const* d_in, const int* in_sizes, int n_in,
                              void* d_out, int out_size)
{
    const float* x    = (const float*)d_in[0];
    const float* Wqkv = (const float*)d_in[1];
    const float* bqkv = (const float*)d_in[2];
    const float* Wo   = (const float*)d_in[3];
    const float* bo   = (const float*)d_in[4];
    const float* g1   = (const float*)d_in[5];
    const float* g2   = (const float*)d_in[6];
    const float* Wp   = (const float*)d_in[7];
    const float* bp   = (const float*)d_in[8];
    const float* Wff  = (const float*)d_in[9];
    const float* bff  = (const float*)d_in[10];
    float* out = (float*)d_out;

    float *pH, *pQKV, *pQ, *pK, *pV, *pO, *pX1, *pP, *pFF, *pW;
    cudaGetSymbolAddress((void**)&pH,   g_h);
    cudaGetSymbolAddress((void**)&pQKV, g_qkv);
    cudaGetSymbolAddress((void**)&pQ,   g_q);
    cudaGetSymbolAddress((void**)&pK,   g_k);
    cudaGetSymbolAddress((void**)&pV,   g_v);
    cudaGetSymbolAddress((void**)&pO,   g_o);
    cudaGetSymbolAddress((void**)&pX1,  g_x1);
    cudaGetSymbolAddress((void**)&pP,   g_p);
    cudaGetSymbolAddress((void**)&pFF,  g_ff);
    cudaGetSymbolAddress((void**)&pW,   g_w);

    float* wqkv = pW;                       // 12,582,912
    float* wo   = pW + 12582912;            //  4,194,304
    float* wp   = pW + 16777216;            // 33,554,432
    float* wff  = pW + 50331648;            // 16,777,216

    // 0. pre-round weights to tf32 values
    cvtw_kernel<<<12582912/1024, 256>>>((const float4*)Wqkv, (float4*)wqkv);
    cvtw_kernel<<< 4194304/1024, 256>>>((const float4*)Wo,   (float4*)wo);
    cvtw_kernel<<<33554432/1024, 256>>>((const float4*)Wp,   (float4*)wp);
    cvtw_kernel<<<16777216/1024, 256>>>((const float4*)Wff,  (float4*)wff);

    // 1. h = rms(x, g1)   (tf32-rounded)
    rmsnorm_kernel<<<NROWS, 256>>>(x, g1, pH);
    // 2. qkv = h @ Wqkv + bqkv            [4096, 6144]
    tgemm_kernel<<<dim3(6144/128, NROWS/128), 256>>>(pH, wqkv, bqkv, nullptr, pQKV,
                                                     NROWS, 3*DM, DM);
    // 3. rope + split into Q/K/V [B,H,L,HD]
    rope_split_kernel<<<(NROWS * NHEAD * 64) / 256, 256>>>(pQKV);
    // 4. causal attention -> O [B,L,D]  (tf32-rounded)
    attn_kernel<<<dim3(SEQ/16, 2*NHEAD), 128>>>(pQ, pK, pV, pO);
    // 5. x1 = O @ Wo + bo + x
    tgemm_kernel<<<dim3(DM/128, NROWS/128), 256>>>(pO, wo, bo, x, pX1,
                                                   NROWS, DM, DM);
    // 6. h2 = rms(x1, g2)  (tf32-rounded)
    rmsnorm_kernel<<<NROWS, 256>>>(pX1, g2, pH);
    // 7. p = h2 @ Wp + bp                 [4096, 16384]
    tgemm_kernel<<<dim3(16384/128, NROWS/128), 256>>>(pH, wp, bp, nullptr, pP,
                                                      NROWS, 8*DM, DM);
    // 8. ff = silu(gate) * value  (tf32-rounded)
    swiglu_kernel<<<(NROWS * 2048) / 256, 256>>>();
    // 9. out = ff @ Wff_out + bff + x1
    tgemm_kernel<<<dim3(DM/128, NROWS/128), 256>>>(pFF, wff, bff, pX1, out,
                                                   NROWS, DM, 4*DM);
}

// round 4
// speedup vs baseline: 2.9678x; 1.2544x over previous
#include <cuda_runtime.h>
#include <math.h>
#include <stdint.h>

static constexpr int SEQ   = 2048;
static constexpr int DM    = 2048;
static constexpr int NHEAD = 16;
static constexpr int HDIM  = 128;
static constexpr int NROWS = 4096;   // B * L

// ---------------- scratch (device globals; no allocation allowed) ----------
__device__ __align__(16) float g_h  [(size_t)NROWS * DM];
__device__ __align__(16) float g_qkv[(size_t)NROWS * 3 * DM];
__device__ __align__(16) float g_q  [(size_t)NROWS * DM];
__device__ __align__(16) float g_k  [(size_t)NROWS * DM];
__device__ __align__(16) float g_v  [(size_t)NROWS * DM];
__device__ __align__(16) float g_o  [(size_t)NROWS * DM];
__device__ __align__(16) float g_x1 [(size_t)NROWS * DM];
__device__ __align__(16) float g_p  [(size_t)NROWS * 8 * DM];
__device__ __align__(16) float g_ff [(size_t)NROWS * 4 * DM];
// tf32-rounded weight copies: Wqkv | Wo | Wp | Wff  (67,108,864 floats)
__device__ __align__(16) float g_w  [(size_t)67108864];

__device__ __forceinline__ uint32_t f2tf32(float f) {
    uint32_t u;
    asm("cvt.rna.tf32.f32 %0, %1;" : "=r"(u) : "f"(f));
    return u;
}
__device__ __forceinline__ float tf32r(float f) { return __uint_as_float(f2tf32(f)); }

__device__ __forceinline__ void cp_async16(uint32_t smem, const void* g) {
    asm volatile("cp.async.cg.shared.global [%0], [%1], 16;" :: "r"(smem), "l"(g));
}
__device__ __forceinline__ void cp_commit() {
    asm volatile("cp.async.commit_group;");
}
template<int N> __device__ __forceinline__ void cp_wait() {
    asm volatile("cp.async.wait_group %0;" :: "n"(N));
}

// ---------------- weight tf32 pre-rounding ----------------------------------
__global__ __launch_bounds__(256)
void cvtw_kernel(const float4* __restrict__ src, float4* __restrict__ dst)
{
    int i = blockIdx.x * 256 + threadIdx.x;
    float4 v = src[i];
    v.x = tf32r(v.x); v.y = tf32r(v.y); v.z = tf32r(v.z); v.w = tf32r(v.w);
    dst[i] = v;
}

// ---------------- RMSNorm (tf32-rounded output) ------------------------------
__global__ __launch_bounds__(256)
void rmsnorm_kernel(const float* __restrict__ x, const float* __restrict__ g,
                    float* __restrict__ out)
{
    int row = blockIdx.x;
    int tid = threadIdx.x;
    const float4* xr = (const float4*)(x + (size_t)row * DM);
    const float4* gr = (const float4*)g;
    float4* orow = (float4*)(out + (size_t)row * DM);
    float4 v0 = xr[tid];
    float4 v1 = xr[tid + 256];
    float ss = v0.x*v0.x + v0.y*v0.y + v0.z*v0.z + v0.w*v0.w
             + v1.x*v1.x + v1.y*v1.y + v1.z*v1.z + v1.w*v1.w;
    #pragma unroll
    for (int off = 16; off > 0; off >>= 1)
        ss += __shfl_xor_sync(0xffffffffu, ss, off);
    __shared__ float wsum[8];
    if ((tid & 31) == 0) wsum[tid >> 5] = ss;
    __syncthreads();
    float tot = wsum[0]+wsum[1]+wsum[2]+wsum[3]+wsum[4]+wsum[5]+wsum[6]+wsum[7];
    float sc = rsqrtf(tot * (1.0f / (float)DM) + 1e-8f);
    float4 ga = gr[tid], gb = gr[tid + 256];
    float4 o0 = make_float4(tf32r(v0.x*sc*ga.x), tf32r(v0.y*sc*ga.y),
                            tf32r(v0.z*sc*ga.z), tf32r(v0.w*sc*ga.w));
    float4 o1 = make_float4(tf32r(v1.x*sc*gb.x), tf32r(v1.y*sc*gb.y),
                            tf32r(v1.z*sc*gb.z), tf32r(v1.w*sc*gb.w));
    orow[tid]       = o0;
    orow[tid + 256] = o1;
}

// ---------------- TF32 tensor-core GEMM, cp.async double-buffered ------------
// C[M,N] = A[M,K] @ B[K,N] + bias (+ residual)
// 256x128 CTA tile, BK=32, 2-stage pipeline, 256 threads = 8 warps (4x2),
// warp tile 64x64.  A/B pre-rounded to tf32 values (raw bits fed to MMA).
// Dynamic smem: As[2][256][36] + Bs[2][32][136]  = 108,544 bytes.
#define AS(s,r,c) As[(s)*9216 + (r)*36 + (c)]
#define BS(s,r,c) Bs[(s)*4352 + (r)*136 + (c)]
__global__ __launch_bounds__(256, 1)
void tgemm_kernel(const float* __restrict__ A, const float* __restrict__ B,
                  const float* __restrict__ bias, const float* __restrict__ res,
                  float* __restrict__ C, int M, int N, int K)
{
    extern __shared__ float smem_dyn[];
    float* As = smem_dyn;                 // 2*256*36 = 18432 floats
    float* Bs = smem_dyn + 18432;         // 2*32*136 =  8704 floats

    int tid  = threadIdx.x;
    int wid  = tid >> 5, lane = tid & 31;
    int wm   = wid >> 1;         // 0..3  -> 64 rows each
    int wn   = wid & 1;          // 0..1  -> 64 cols each
    int g    = lane >> 2;        // 0..7
    int tig  = lane & 3;         // 0..3

    const float* Ab = A + (size_t)blockIdx.y * 256 * K;
    const float* Bb = B + (size_t)blockIdx.x * 128;

    uint32_t as_base = (uint32_t)__cvta_generic_to_shared(As);
    uint32_t bs_base = (uint32_t)__cvta_generic_to_shared(Bs);

    int arow[8], acol[8], brow[4], bcol[4];
    #pragma unroll
    for (int i = 0; i < 8; i++) {
        int c = tid + 256 * i;
        arow[i] = c >> 3;  acol[i] = (c & 7) * 4;
    }
    #pragma unroll
    for (int i = 0; i < 4; i++) {
        int c = tid + 256 * i;
        brow[i] = c >> 5;  bcol[i] = (c & 31) * 4;
    }

    float acc[4][8][4];
    #pragma unroll
    for (int i = 0; i < 4; i++)
        #pragma unroll
        for (int j = 0; j < 8; j++) {
            acc[i][j][0] = 0.f; acc[i][j][1] = 0.f;
            acc[i][j][2] = 0.f; acc[i][j][3] = 0.f;
        }

    const int NT = K >> 5;

    // prologue: stage 0
    #pragma unroll
    for (int i = 0; i < 8; i++)
        cp_async16(as_base + (uint32_t)((arow[i] * 36 + acol[i]) * 4),
                   Ab + (size_t)arow[i] * K + acol[i]);
    #pragma unroll
    for (int i = 0; i < 4; i++)
        cp_async16(bs_base + (uint32_t)((brow[i] * 136 + bcol[i]) * 4),
                   Bb + (size_t)brow[i] * N + bcol[i]);
    cp_commit();

    for (int t = 0; t < NT; t++) {
        int buf = t & 1;
        if (t + 1 < NT) {
            int nbuf = (t + 1) & 1;
            int k0   = (t + 1) * 32;
            uint32_t aoff = as_base + (uint32_t)(nbuf * 9216 * 4);
            uint32_t boff = bs_base + (uint32_t)(nbuf * 4352 * 4);
            #pragma unroll
            for (int i = 0; i < 8; i++)
                cp_async16(aoff + (uint32_t)((arow[i] * 36 + acol[i]) * 4),
                           Ab + (size_t)arow[i] * K + k0 + acol[i]);
            #pragma unroll
            for (int i = 0; i < 4; i++)
                cp_async16(boff + (uint32_t)((brow[i] * 136 + bcol[i]) * 4),
                           Bb + (size_t)(k0 + brow[i]) * N + bcol[i]);
            cp_commit();
            cp_wait<1>();
        } else {
            cp_wait<0>();
        }
        __syncthreads();

        #pragma unroll
        for (int ks = 0; ks < 4; ks++) {
            int kb = ks * 8;
            uint32_t af[4][4], bf[8][2];
            #pragma unroll
            for (int mi = 0; mi < 4; mi++) {
                int row = wm * 64 + mi * 16 + g;
                af[mi][0] = __float_as_uint(AS(buf, row    , kb + tig));
                af[mi][1] = __float_as_uint(AS(buf, row + 8, kb + tig));
                af[mi][2] = __float_as_uint(AS(buf, row    , kb + tig + 4));
                af[mi][3] = __float_as_uint(AS(buf, row + 8, kb + tig + 4));
            }
            #pragma unroll
            for (int ni = 0; ni < 8; ni++) {
                int col = wn * 64 + ni * 8 + g;
                bf[ni][0] = __float_as_uint(BS(buf, kb + tig    , col));
                bf[ni][1] = __float_as_uint(BS(buf, kb + tig + 4, col));
            }
            #pragma unroll
            for (int mi = 0; mi < 4; mi++)
                #pragma unroll
                for (int ni = 0; ni < 8; ni++) {
                    asm volatile(
                        "mma.sync.aligned.m16n8k8.row.col.f32.tf32.tf32.f32 "
                        "{%0,%1,%2,%3}, {%4,%5,%6,%7}, {%8,%9}, {%0,%1,%2,%3};"
                        : "+f"(acc[mi][ni][0]), "+f"(acc[mi][ni][1]),
                          "+f"(acc[mi][ni][2]), "+f"(acc[mi][ni][3])
                        : "r"(af[mi][0]), "r"(af[mi][1]),
                          "r"(af[mi][2]), "r"(af[mi][3]),
                          "r"(bf[ni][0]), "r"(bf[ni][1]));
                }
        }
        __syncthreads();
    }

    // epilogue
    #pragma unroll
    for (int mi = 0; mi < 4; mi++) {
        #pragma unroll
        for (int ni = 0; ni < 8; ni++) {
            int row = blockIdx.y * 256 + wm * 64 + mi * 16 + g;
            int col = blockIdx.x * 128 + wn * 64 + ni * 8 + 2 * tig;
            float bx = bias[col], by = bias[col + 1];
            size_t off0 = (size_t)row * N + col;
            size_t off1 = (size_t)(row + 8) * N + col;
            float2 r0 = make_float2(acc[mi][ni][0] + bx, acc[mi][ni][1] + by);
            float2 r1 = make_float2(acc[mi][ni][2] + bx, acc[mi][ni][3] + by);
            if (res) {
                float2 q0 = *(const float2*)(res + off0);
                float2 q1 = *(const float2*)(res + off1);
                r0.x += q0.x; r0.y += q0.y;
                r1.x += q1.x; r1.y += q1.y;
            }
            *(float2*)(C + off0) = r0;
            *(float2*)(C + off1) = r1;
        }
    }
}

// ---------------- RoPE + head split: qkv[B,L,3D] -> Q/K/V [B,H,L,HD] --------
__global__ __launch_bounds__(256)
void rope_split_kernel(const float* __restrict__ qkv)
{
    int idx = blockIdx.x * 256 + threadIdx.x;
    int i   = idx & 63;
    int h   = (idx >> 6) & 15;
    int row = idx >> 10;          // b*SEQ + l
    int l   = row & (SEQ - 1);
    int b   = row >> 11;
    const float* base = qkv + (size_t)row * (3 * DM) + h * HDIM;
    float q0 = base[i],          q1 = base[i + 64];
    float k0 = base[DM + i],     k1 = base[DM + i + 64];
    float v0 = base[2*DM + i],   v1 = base[2*DM + i + 64];
    float invf = powf(10000.0f, -(float)(2 * i) * (1.0f / 128.0f));
    float ang = (float)l * invf;
    float sn, cs;
    sincosf(ang, &sn, &cs);
    size_t ob = ((size_t)((b * NHEAD + h) * SEQ + l)) * HDIM;
    g_q[ob + i]      = q0 * cs - q1 * sn;
    g_q[ob + i + 64] = q1 * cs + q0 * sn;
    g_k[ob + i]      = k0 * cs - k1 * sn;
    g_k[ob + i + 64] = k1 * cs + k0 * sn;
    g_v[ob + i]      = v0;
    g_v[ob + i + 64] = v1;
}

// ---------------- causal flash attention ------------------------------------
// CTA: 128 threads, 32 queries (2 per thread: rows m and m+16), key tiles of 32.
// Dynamic smem: Qs/Ks/Vs [32][132] + Ps[32][33] = 54,912 bytes.
#define QS_(r,c) Qs[(r)*132 + (c)]
#define KS_(r,c) Ks[(r)*132 + (c)]
#define VS_(r,c) Vs[(r)*132 + (c)]
__global__ __launch_bounds__(128)
void attn_kernel(const float* __restrict__ Q, const float* __restrict__ K,
                 const float* __restrict__ V, float* __restrict__ O)
{
    extern __shared__ float smem_dyn[];
    float* Qs = smem_dyn;            // 32*132
    float* Ks = Qs + 32 * 132;
    float* Vs = Ks + 32 * 132;
    float* Ps = Vs + 32 * 132;       // 32*33

    int tid = threadIdx.x;
    int bh  = blockIdx.y;
    int q0  = blockIdx.x * 32;
    const float* Qb = Q + (size_t)bh * SEQ * HDIM;
    const float* Kb = K + (size_t)bh * SEQ * HDIM;
    const float* Vb = V + (size_t)bh * SEQ * HDIM;

    int kr = tid >> 2, klane = tid & 3;
    {   // load Q tile: 32 rows, 4 threads/row, 8 float4 each
        const float* src = Qb + (size_t)(q0 + kr) * HDIM;
        #pragma unroll
        for (int t = 0; t < 8; t++) {
            int f4 = klane + 4 * t;
            *(float4*)&QS_(kr, f4 * 4) = *(const float4*)(src + f4 * 4);
        }
    }

    int m = tid >> 3;        // 0..15 -> queries m, m+16
    int g = tid & 7;
    float mr[2] = {-INFINITY, -INFINITY};
    float lr[2] = {0.f, 0.f};
    float4 o[2][4];
    #pragma unroll
    for (int qi = 0; qi < 2; qi++)
        #pragma unroll
        for (int w = 0; w < 4; w++) o[qi][w] = make_float4(0,0,0,0);
    const float scale = 0.08838834764831845f;
    int kend = q0 + 32;

    for (int n0 = 0; n0 < kend; n0 += 32) {
        __syncthreads();
        {
            const float* ksrc = Kb + (size_t)(n0 + kr) * HDIM;
            const float* vsrc = Vb + (size_t)(n0 + kr) * HDIM;
            #pragma unroll
            for (int t = 0; t < 8; t++) {
                int f4 = klane + 4 * t;
                *(float4*)&KS_(kr, f4 * 4) = *(const float4*)(ksrc + f4 * 4);
                *(float4*)&VS_(kr, f4 * 4) = *(const float4*)(vsrc + f4 * 4);
            }
        }
        __syncthreads();

        float s[2][4] = {{0,0,0,0},{0,0,0,0}};
        #pragma unroll 4
        for (int d4 = 0; d4 < 32; d4++) {
            float4 qa = *(const float4*)&QS_(m,      d4 * 4);
            float4 qb = *(const float4*)&QS_(m + 16, d4 * 4);
            #pragma unroll
            for (int j = 0; j < 4; j++) {
                float4 k4 = *(const float4*)&KS_(j*8 + g, d4 * 4);
                s[0][j] = fmaf(qa.x, k4.x, s[0][j]); s[0][j] = fmaf(qa.y, k4.y, s[0][j]);
                s[0][j] = fmaf(qa.z, k4.z, s[0][j]); s[0][j] = fmaf(qa.w, k4.w, s[0][j]);
                s[1][j] = fmaf(qb.x, k4.x, s[1][j]); s[1][j] = fmaf(qb.y, k4.y, s[1][j]);
                s[1][j] = fmaf(qb.z, k4.z, s[1][j]); s[1][j] = fmaf(qb.w, k4.w, s[1][j]);
            }
        }

        #pragma unroll
        for (int qi = 0; qi < 2; qi++) {
            int qg = q0 + m + qi * 16;
            float tmax = -INFINITY;
            #pragma unroll
            for (int j = 0; j < 4; j++) {
                int n = n0 + j*8 + g;
                s[qi][j] = (n <= qg) ? s[qi][j] * scale : -INFINITY;
                tmax = fmaxf(tmax, s[qi][j]);
            }
            #pragma unroll
            for (int off = 4; off > 0; off >>= 1)
                tmax = fmaxf(tmax, __shfl_xor_sync(0xffffffffu, tmax, off));
            float mnew = fmaxf(mr[qi], tmax);
            float corr = expf(mr[qi] - mnew);
            float p[4], psum = 0.0f;
            #pragma unroll
            for (int j = 0; j < 4; j++) { p[j] = expf(s[qi][j] - mnew); psum += p[j]; }
            #pragma unroll
            for (int off = 4; off > 0; off >>= 1)
                psum += __shfl_xor_sync(0xffffffffu, psum, off);
            lr[qi] = lr[qi] * corr + psum;
            mr[qi] = mnew;
            #pragma unroll
            for (int w = 0; w < 4; w++) {
                o[qi][w].x *= corr; o[qi][w].y *= corr;
                o[qi][w].z *= corr; o[qi][w].w *= corr;
            }
            #pragma unroll
            for (int j = 0; j < 4; j++) Ps[(m + qi*16)*33 + j*8 + g] = p[j];
        }
        __syncwarp();

        #pragma unroll 4
        for (int n = 0; n < 32; n++) {
            float pv0 = Ps[m*33 + n];
            float pv1 = Ps[(m+16)*33 + n];
            #pragma unroll
            for (int w = 0; w < 4; w++) {
                float4 v = *(const float4*)&VS_(n, (g + 8*w) * 4);
                o[0][w].x = fmaf(pv0, v.x, o[0][w].x);
                o[0][w].y = fmaf(pv0, v.y, o[0][w].y);
                o[0][w].z = fmaf(pv0, v.z, o[0][w].z);
                o[0][w].w = fmaf(pv0, v.w, o[0][w].w);
                o[1][w].x = fmaf(pv1, v.x, o[1][w].x);
                o[1][w].y = fmaf(pv1, v.y, o[1][w].y);
                o[1][w].z = fmaf(pv1, v.z, o[1][w].z);
                o[1][w].w = fmaf(pv1, v.w, o[1][w].w);
            }
        }
        __syncwarp();
    }

    int b = bh >> 4, h = bh & 15;
    #pragma unroll
    for (int qi = 0; qi < 2; qi++) {
        float inv = 1.0f / lr[qi];
        int qg = q0 + m + qi * 16;
        float* dst = O + ((size_t)(b * SEQ + qg)) * DM + h * HDIM;
        #pragma unroll
        for (int w = 0; w < 4; w++) {
            float4 r = make_float4(tf32r(o[qi][w].x*inv), tf32r(o[qi][w].y*inv),
                                   tf32r(o[qi][w].z*inv), tf32r(o[qi][w].w*inv));
            *(float4*)(dst + (g + 8*w) * 4) = r;
        }
    }
}

// ---------------- SwiGLU (tf32-rounded output) -------------------------------
__global__ __launch_bounds__(256)
void swiglu_kernel()
{
    size_t idx = (size_t)blockIdx.x * 256 + threadIdx.x;
    size_t row = idx >> 11;
    int c4 = (int)(idx & 2047);
    const float4* Pr = (const float4*)(g_p + row * (size_t)(8 * DM));
    float4 gt = Pr[c4];
    float4 vl = Pr[c4 + 2048];
    float4 r;
    r.x = tf32r(gt.x / (1.0f + expf(-gt.x)) * vl.x);
    r.y = tf32r(gt.y / (1.0f + expf(-gt.y)) * vl.y);
    r.z = tf32r(gt.z / (1.0f + expf(-gt.z)) * vl.z);
    r.w = tf32r(gt.w / (1.0f + expf(-gt.w)) * vl.w);
    ((float4*)g_ff)[idx] = r;
}

// ---------------- launch -----------------------------------------------------
extern "C" void kernel_launch(void* const* d_in, const int* in_sizes, int n_in,
                              void* d_out, int out_size)
{
    const float* x    = (const float*)d_in[0];
    const float* Wqkv = (const float*)d_in[1];
    const float* bqkv = (const float*)d_in[2];
    const float* Wo   = (const float*)d_in[3];
    const float* bo   = (const float*)d_in[4];
    const float* g1   = (const float*)d_in[5];
    const float* g2   = (const float*)d_in[6];
    const float* Wp   = (const float*)d_in[7];
    const float* bp   = (const float*)d_in[8];
    const float* Wff  = (const float*)d_in[9];
    const float* bff  = (const float*)d_in[10];
    float* out = (float*)d_out;

    float *pH, *pQKV, *pQ, *pK, *pV, *pO, *pX1, *pP, *pFF, *pW;
    cudaGetSymbolAddress((void**)&pH,   g_h);
    cudaGetSymbolAddress((void**)&pQKV, g_qkv);
    cudaGetSymbolAddress((void**)&pQ,   g_q);
    cudaGetSymbolAddress((void**)&pK,   g_k);
    cudaGetSymbolAddress((void**)&pV,   g_v);
    cudaGetSymbolAddress((void**)&pO,   g_o);
    cudaGetSymbolAddress((void**)&pX1,  g_x1);
    cudaGetSymbolAddress((void**)&pP,   g_p);
    cudaGetSymbolAddress((void**)&pFF,  g_ff);
    cudaGetSymbolAddress((void**)&pW,   g_w);

    float* wqkv = pW;                       // 12,582,912
    float* wo   = pW + 12582912;            //  4,194,304
    float* wp   = pW + 16777216;            // 33,554,432
    float* wff  = pW + 50331648;            // 16,777,216

    static constexpr int GEMM_SMEM = 108544;
    static constexpr int ATTN_SMEM = 54912;
    cudaFuncSetAttribute(tgemm_kernel, cudaFuncAttributeMaxDynamicSharedMemorySize, GEMM_SMEM);
    cudaFuncSetAttribute(attn_kernel,  cudaFuncAttributeMaxDynamicSharedMemorySize, ATTN_SMEM);

    // 0. pre-round weights to tf32 values
    cvtw_kernel<<<12582912/1024, 256>>>((const float4*)Wqkv, (float4*)wqkv);
    cvtw_kernel<<< 4194304/1024, 256>>>((const float4*)Wo,   (float4*)wo);
    cvtw_kernel<<<33554432/1024, 256>>>((const float4*)Wp,   (float4*)wp);
    cvtw_kernel<<<16777216/1024, 256>>>((const float4*)Wff,  (float4*)wff);

    // 1. h = rms(x, g1)   (tf32-rounded)
    rmsnorm_kernel<<<NROWS, 256>>>(x, g1, pH);
    // 2. qkv = h @ Wqkv + bqkv            [4096, 6144]
    tgemm_kernel<<<dim3(6144/128, NROWS/256), 256, GEMM_SMEM>>>(pH, wqkv, bqkv, nullptr, pQKV,
                                                                NROWS, 3*DM, DM);
    // 3. rope + split into Q/K/V [B,H,L,HD]
    rope_split_kernel<<<(NROWS * NHEAD * 64) / 256, 256>>>(pQKV);
    // 4. causal attention -> O [B,L,D]  (tf32-rounded)
    attn_kernel<<<dim3(SEQ/32, 2*NHEAD), 128, ATTN_SMEM>>>(pQ, pK, pV, pO);
    // 5. x1 = O @ Wo + bo + x
    tgemm_kernel<<<dim3(DM/128, NROWS/256), 256, GEMM_SMEM>>>(pO, wo, bo, x, pX1,
                                                              NROWS, DM, DM);
    // 6. h2 = rms(x1, g2)  (tf32-rounded)
    rmsnorm_kernel<<<NROWS, 256>>>(pX1, g2, pH);
    // 7. p = h2 @ Wp + bp                 [4096, 16384]
    tgemm_kernel<<<dim3(16384/128, NROWS/256), 256, GEMM_SMEM>>>(pH, wp, bp, nullptr, pP,
                                                                 NROWS, 8*DM, DM);
    // 8. ff = silu(gate) * value  (tf32-rounded)
    swiglu_kernel<<<(NROWS * 2048) / 256, 256>>>();
    // 9. out = ff @ Wff_out + bff + x1
    tgemm_kernel<<<dim3(DM/128, NROWS/256), 256, GEMM_SMEM>>>(pFF, wff, bff, pX1, out,
                                                              NROWS, DM, 4*DM);
}

// round 6
// speedup vs baseline: 3.8342x; 1.2919x over previous
#include <cuda_runtime.h>
#include <math.h>
#include <stdint.h>

static constexpr int SEQ   = 2048;
static constexpr int DM    = 2048;
static constexpr int NHEAD = 16;
static constexpr int HDIM  = 128;
static constexpr int NROWS = 4096;   // B * L

// ---------------- scratch (device globals; no allocation allowed) ----------
__device__ __align__(16) float g_h  [(size_t)NROWS * DM];
__device__ __align__(16) float g_qkv[(size_t)NROWS * 3 * DM];
__device__ __align__(16) float g_q  [(size_t)NROWS * DM];
__device__ __align__(16) float g_k  [(size_t)NROWS * DM];
__device__ __align__(16) float g_v  [(size_t)NROWS * DM];
__device__ __align__(16) float g_o  [(size_t)NROWS * DM];
__device__ __align__(16) float g_x1 [(size_t)NROWS * DM];
__device__ __align__(16) float g_p  [(size_t)NROWS * 8 * DM];
__device__ __align__(16) float g_ff [(size_t)NROWS * 4 * DM];
// tf32-rounded weight copies: Wqkv | Wo | Wp | Wff  (67,108,864 floats)
__device__ __align__(16) float g_w  [(size_t)67108864];

__device__ __forceinline__ uint32_t f2tf32(float f) {
    uint32_t u;
    asm("cvt.rna.tf32.f32 %0, %1;" : "=r"(u) : "f"(f));
    return u;
}
__device__ __forceinline__ float tf32r(float f) { return __uint_as_float(f2tf32(f)); }

__device__ __forceinline__ void cp_async16(uint32_t smem, const void* g) {
    asm volatile("cp.async.cg.shared.global [%0], [%1], 16;" :: "r"(smem), "l"(g));
}
__device__ __forceinline__ void cp_commit() {
    asm volatile("cp.async.commit_group;");
}
template<int N> __device__ __forceinline__ void cp_wait() {
    asm volatile("cp.async.wait_group %0;" :: "n"(N));
}

#define MMA_TF32(acc, a0, a1, a2, a3, b0, b1)                                  \
    asm volatile(                                                              \
        "mma.sync.aligned.m16n8k8.row.col.f32.tf32.tf32.f32 "                  \
        "{%0,%1,%2,%3}, {%4,%5,%6,%7}, {%8,%9}, {%0,%1,%2,%3};"                \
        : "+f"(acc[0]), "+f"(acc[1]), "+f"(acc[2]), "+f"(acc[3])               \
        : "r"(a0), "r"(a1), "r"(a2), "r"(a3), "r"(b0), "r"(b1))

// ---------------- weight tf32 pre-rounding ----------------------------------
__global__ __launch_bounds__(256)
void cvtw_kernel(const float4* __restrict__ src, float4* __restrict__ dst)
{
    int i = blockIdx.x * 256 + threadIdx.x;
    float4 v = src[i];
    v.x = tf32r(v.x); v.y = tf32r(v.y); v.z = tf32r(v.z); v.w = tf32r(v.w);
    dst[i] = v;
}

// ---------------- RMSNorm (tf32-rounded output) ------------------------------
__global__ __launch_bounds__(256)
void rmsnorm_kernel(const float* __restrict__ x, const float* __restrict__ g,
                    float* __restrict__ out)
{
    int row = blockIdx.x;
    int tid = threadIdx.x;
    const float4* xr = (const float4*)(x + (size_t)row * DM);
    const float4* gr = (const float4*)g;
    float4* orow = (float4*)(out + (size_t)row * DM);
    float4 v0 = xr[tid];
    float4 v1 = xr[tid + 256];
    float ss = v0.x*v0.x + v0.y*v0.y + v0.z*v0.z + v0.w*v0.w
             + v1.x*v1.x + v1.y*v1.y + v1.z*v1.z + v1.w*v1.w;
    #pragma unroll
    for (int off = 16; off > 0; off >>= 1)
        ss += __shfl_xor_sync(0xffffffffu, ss, off);
    __shared__ float wsum[8];
    if ((tid & 31) == 0) wsum[tid >> 5] = ss;
    __syncthreads();
    float tot = wsum[0]+wsum[1]+wsum[2]+wsum[3]+wsum[4]+wsum[5]+wsum[6]+wsum[7];
    float sc = rsqrtf(tot * (1.0f / (float)DM) + 1e-8f);
    float4 ga = gr[tid], gb = gr[tid + 256];
    float4 o0 = make_float4(tf32r(v0.x*sc*ga.x), tf32r(v0.y*sc*ga.y),
                            tf32r(v0.z*sc*ga.z), tf32r(v0.w*sc*ga.w));
    float4 o1 = make_float4(tf32r(v1.x*sc*gb.x), tf32r(v1.y*sc*gb.y),
                            tf32r(v1.z*sc*gb.z), tf32r(v1.w*sc*gb.w));
    orow[tid]       = o0;
    orow[tid + 256] = o1;
}

// ---------------- TF32 tensor-core GEMM, cp.async double-buffered ------------
// 256x128 CTA tile, BK=32, 2-stage, 8 warps (4x2), warp tile 64x64.
#define AS(s,r,c) As[(s)*9216 + (r)*36 + (c)]
#define BS(s,r,c) Bs[(s)*4352 + (r)*136 + (c)]
__global__ __launch_bounds__(256, 1)
void tgemm_kernel(const float* __restrict__ A, const float* __restrict__ B,
                  const float* __restrict__ bias, const float* __restrict__ res,
                  float* __restrict__ C, int M, int N, int K)
{
    extern __shared__ float smem_dyn[];
    float* As = smem_dyn;                 // 2*256*36 = 18432 floats
    float* Bs = smem_dyn + 18432;         // 2*32*136 =  8704 floats

    int tid  = threadIdx.x;
    int wid  = tid >> 5, lane = tid & 31;
    int wm   = wid >> 1;         // 0..3  -> 64 rows each
    int wn   = wid & 1;          // 0..1  -> 64 cols each
    int g    = lane >> 2;        // 0..7
    int tig  = lane & 3;         // 0..3

    const float* Ab = A + (size_t)blockIdx.y * 256 * K;
    const float* Bb = B + (size_t)blockIdx.x * 128;

    uint32_t as_base = (uint32_t)__cvta_generic_to_shared(As);
    uint32_t bs_base = (uint32_t)__cvta_generic_to_shared(Bs);

    int arow[8], acol[8], brow[4], bcol[4];
    #pragma unroll
    for (int i = 0; i < 8; i++) {
        int c = tid + 256 * i;
        arow[i] = c >> 3;  acol[i] = (c & 7) * 4;
    }
    #pragma unroll
    for (int i = 0; i < 4; i++) {
        int c = tid + 256 * i;
        brow[i] = c >> 5;  bcol[i] = (c & 31) * 4;
    }

    float acc[4][8][4];
    #pragma unroll
    for (int i = 0; i < 4; i++)
        #pragma unroll
        for (int j = 0; j < 8; j++) {
            acc[i][j][0] = 0.f; acc[i][j][1] = 0.f;
            acc[i][j][2] = 0.f; acc[i][j][3] = 0.f;
        }

    const int NT = K >> 5;

    #pragma unroll
    for (int i = 0; i < 8; i++)
        cp_async16(as_base + (uint32_t)((arow[i] * 36 + acol[i]) * 4),
                   Ab + (size_t)arow[i] * K + acol[i]);
    #pragma unroll
    for (int i = 0; i < 4; i++)
        cp_async16(bs_base + (uint32_t)((brow[i] * 136 + bcol[i]) * 4),
                   Bb + (size_t)brow[i] * N + bcol[i]);
    cp_commit();

    for (int t = 0; t < NT; t++) {
        int buf = t & 1;
        if (t + 1 < NT) {
            int nbuf = (t + 1) & 1;
            int k0   = (t + 1) * 32;
            uint32_t aoff = as_base + (uint32_t)(nbuf * 9216 * 4);
            uint32_t boff = bs_base + (uint32_t)(nbuf * 4352 * 4);
            #pragma unroll
            for (int i = 0; i < 8; i++)
                cp_async16(aoff + (uint32_t)((arow[i] * 36 + acol[i]) * 4),
                           Ab + (size_t)arow[i] * K + k0 + acol[i]);
            #pragma unroll
            for (int i = 0; i < 4; i++)
                cp_async16(boff + (uint32_t)((brow[i] * 136 + bcol[i]) * 4),
                           Bb + (size_t)(k0 + brow[i]) * N + bcol[i]);
            cp_commit();
            cp_wait<1>();
        } else {
            cp_wait<0>();
        }
        __syncthreads();

        #pragma unroll
        for (int ks = 0; ks < 4; ks++) {
            int kb = ks * 8;
            uint32_t af[4][4], bf[8][2];
            #pragma unroll
            for (int mi = 0; mi < 4; mi++) {
                int row = wm * 64 + mi * 16 + g;
                af[mi][0] = __float_as_uint(AS(buf, row    , kb + tig));
                af[mi][1] = __float_as_uint(AS(buf, row + 8, kb + tig));
                af[mi][2] = __float_as_uint(AS(buf, row    , kb + tig + 4));
                af[mi][3] = __float_as_uint(AS(buf, row + 8, kb + tig + 4));
            }
            #pragma unroll
            for (int ni = 0; ni < 8; ni++) {
                int col = wn * 64 + ni * 8 + g;
                bf[ni][0] = __float_as_uint(BS(buf, kb + tig    , col));
                bf[ni][1] = __float_as_uint(BS(buf, kb + tig + 4, col));
            }
            #pragma unroll
            for (int mi = 0; mi < 4; mi++)
                #pragma unroll
                for (int ni = 0; ni < 8; ni++)
                    MMA_TF32(acc[mi][ni], af[mi][0], af[mi][1], af[mi][2], af[mi][3],
                             bf[ni][0], bf[ni][1]);
        }
        __syncthreads();
    }

    #pragma unroll
    for (int mi = 0; mi < 4; mi++) {
        #pragma unroll
        for (int ni = 0; ni < 8; ni++) {
            int row = blockIdx.y * 256 + wm * 64 + mi * 16 + g;
            int col = blockIdx.x * 128 + wn * 64 + ni * 8 + 2 * tig;
            float bx = bias[col], by = bias[col + 1];
            size_t off0 = (size_t)row * N + col;
            size_t off1 = (size_t)(row + 8) * N + col;
            float2 r0 = make_float2(acc[mi][ni][0] + bx, acc[mi][ni][1] + by);
            float2 r1 = make_float2(acc[mi][ni][2] + bx, acc[mi][ni][3] + by);
            if (res) {
                float2 q0 = *(const float2*)(res + off0);
                float2 q1 = *(const float2*)(res + off1);
                r0.x += q0.x; r0.y += q0.y;
                r1.x += q1.x; r1.y += q1.y;
            }
            *(float2*)(C + off0) = r0;
            *(float2*)(C + off1) = r1;
        }
    }
}

// ---------------- RoPE + head split (tf32-rounded q/k/v) ---------------------
__global__ __launch_bounds__(256)
void rope_split_kernel(const float* __restrict__ qkv)
{
    int idx = blockIdx.x * 256 + threadIdx.x;
    int i   = idx & 63;
    int h   = (idx >> 6) & 15;
    int row = idx >> 10;          // b*SEQ + l
    int l   = row & (SEQ - 1);
    int b   = row >> 11;
    const float* base = qkv + (size_t)row * (3 * DM) + h * HDIM;
    float q0 = base[i],          q1 = base[i + 64];
    float k0 = base[DM + i],     k1 = base[DM + i + 64];
    float v0 = base[2*DM + i],   v1 = base[2*DM + i + 64];
    float invf = powf(10000.0f, -(float)(2 * i) * (1.0f / 128.0f));
    float ang = (float)l * invf;
    float sn, cs;
    sincosf(ang, &sn, &cs);
    size_t ob = ((size_t)((b * NHEAD + h) * SEQ + l)) * HDIM;
    g_q[ob + i]      = tf32r(q0 * cs - q1 * sn);
    g_q[ob + i + 64] = tf32r(q1 * cs + q0 * sn);
    g_k[ob + i]      = tf32r(k0 * cs - k1 * sn);
    g_k[ob + i + 64] = tf32r(k1 * cs + k0 * sn);
    g_v[ob + i]      = tf32r(v0);
    g_v[ob + i + 64] = tf32r(v1);
}

// ---------------- TF32 MMA causal flash attention ----------------------------
// CTA: 128 threads = 4 warps; 64 queries per CTA (16 per warp); key tiles of 64.
// Dynamic smem: Qs/Ks/Vs [64][132] + Ps [64][68] = 118,784 bytes.
__global__ __launch_bounds__(128)
void attn_kernel(const float* __restrict__ Q, const float* __restrict__ K,
                 const float* __restrict__ V, float* __restrict__ O)
{
    extern __shared__ float sm_[];
    float* Qs = sm_;                 // 64*132
    float* Ks = Qs + 64 * 132;
    float* Vs = Ks + 64 * 132;
    float* Ps = Vs + 64 * 132;       // 64*68

    int tid = threadIdx.x;
    int wid = tid >> 5, lane = tid & 31;
    int g = lane >> 2, tig = lane & 3;
    int bh = blockIdx.y;
    int q0 = blockIdx.x * 64;
    const float* Qb = Q + (size_t)bh * SEQ * HDIM;
    const float* Kb = K + (size_t)bh * SEQ * HDIM;
    const float* Vb = V + (size_t)bh * SEQ * HDIM;

    // load Q tile (fully coalesced)
    #pragma unroll
    for (int it = 0; it < 16; it++) {
        int idx = it * 128 + tid;
        int r = idx >> 5, c4 = idx & 31;
        *(float4*)&Qs[r * 132 + c4 * 4] =
            *(const float4*)(Qb + (size_t)(q0 + r) * HDIM + c4 * 4);
    }

    const float scale = 0.08838834764831845f;   // 1/sqrt(128)
    float mrow[2] = {-INFINITY, -INFINITY};
    float lrow[2] = {0.f, 0.f};
    float oacc[16][4];
    #pragma unroll
    for (int d = 0; d < 16; d++) {
        oacc[d][0] = 0.f; oacc[d][1] = 0.f; oacc[d][2] = 0.f; oacc[d][3] = 0.f;
    }

    int arow0 = (wid * 16 + g) * 132;
    int arow1 = (wid * 16 + g + 8) * 132;
    int prow0 = (wid * 16 + g) * 68;
    int prow1 = (wid * 16 + g + 8) * 68;
    int qrow0 = q0 + wid * 16 + g;       // global query index, row 0
    int qrow1 = qrow0 + 8;

    for (int n0 = 0; n0 <= q0; n0 += 64) {
        __syncthreads();   // all warps done with Ks/Vs from previous tile
        #pragma unroll
        for (int it = 0; it < 16; it++) {
            int idx = it * 128 + tid;
            int r = idx >> 5, c4 = idx & 31;
            *(float4*)&Ks[r * 132 + c4 * 4] =
                *(const float4*)(Kb + (size_t)(n0 + r) * HDIM + c4 * 4);
            *(float4*)&Vs[r * 132 + c4 * 4] =
                *(const float4*)(Vb + (size_t)(n0 + r) * HDIM + c4 * 4);
        }
        __syncthreads();

        // ---- S = Q K^T  (16 x 64 per warp) ----
        float sacc[8][4];
        #pragma unroll
        for (int ni = 0; ni < 8; ni++) {
            sacc[ni][0] = 0.f; sacc[ni][1] = 0.f;
            sacc[ni][2] = 0.f; sacc[ni][3] = 0.f;
        }
        #pragma unroll
        for (int ks = 0; ks < 16; ks++) {
            int kb = ks * 8;
            uint32_t a0 = __float_as_uint(Qs[arow0 + kb + tig]);
            uint32_t a1 = __float_as_uint(Qs[arow1 + kb + tig]);
            uint32_t a2 = __float_as_uint(Qs[arow0 + kb + tig + 4]);
            uint32_t a3 = __float_as_uint(Qs[arow1 + kb + tig + 4]);
            #pragma unroll
            for (int ni = 0; ni < 8; ni++) {
                uint32_t b0 = __float_as_uint(Ks[(ni*8 + g) * 132 + kb + tig]);
                uint32_t b1 = __float_as_uint(Ks[(ni*8 + g) * 132 + kb + tig + 4]);
                MMA_TF32(sacc[ni], a0, a1, a2, a3, b0, b1);
            }
        }

        // ---- online softmax ----
        bool diag = (n0 == q0);
        float tm0 = -INFINITY, tm1 = -INFINITY;
        #pragma unroll
        for (int ni = 0; ni < 8; ni++) {
            int n = n0 + ni * 8 + 2 * tig;
            float s0 = sacc[ni][0] * scale;
            float s1 = sacc[ni][1] * scale;
            float s2 = sacc[ni][2] * scale;
            float s3 = sacc[ni][3] * scale;
            if (diag) {
                if (n     > qrow0) s0 = -INFINITY;
                if (n + 1 > qrow0) s1 = -INFINITY;
                if (n     > qrow1) s2 = -INFINITY;
                if (n + 1 > qrow1) s3 = -INFINITY;
            }
            sacc[ni][0] = s0; sacc[ni][1] = s1;
            sacc[ni][2] = s2; sacc[ni][3] = s3;
            tm0 = fmaxf(tm0, fmaxf(s0, s1));
            tm1 = fmaxf(tm1, fmaxf(s2, s3));
        }
        tm0 = fmaxf(tm0, __shfl_xor_sync(0xffffffffu, tm0, 1));
        tm0 = fmaxf(tm0, __shfl_xor_sync(0xffffffffu, tm0, 2));
        tm1 = fmaxf(tm1, __shfl_xor_sync(0xffffffffu, tm1, 1));
        tm1 = fmaxf(tm1, __shfl_xor_sync(0xffffffffu, tm1, 2));

        float mn0 = fmaxf(mrow[0], tm0), mn1 = fmaxf(mrow[1], tm1);
        float corr0 = expf(mrow[0] - mn0), corr1 = expf(mrow[1] - mn1);
        float ps0 = 0.f, ps1 = 0.f;
        #pragma unroll
        for (int ni = 0; ni < 8; ni++) {
            float p0 = expf(sacc[ni][0] - mn0);
            float p1 = expf(sacc[ni][1] - mn0);
            float p2 = expf(sacc[ni][2] - mn1);
            float p3 = expf(sacc[ni][3] - mn1);
            ps0 += p0 + p1; ps1 += p2 + p3;
            Ps[prow0 + ni*8 + 2*tig    ] = tf32r(p0);
            Ps[prow0 + ni*8 + 2*tig + 1] = tf32r(p1);
            Ps[prow1 + ni*8 + 2*tig    ] = tf32r(p2);
            Ps[prow1 + ni*8 + 2*tig + 1] = tf32r(p3);
        }
        ps0 += __shfl_xor_sync(0xffffffffu, ps0, 1);
        ps0 += __shfl_xor_sync(0xffffffffu, ps0, 2);
        ps1 += __shfl_xor_sync(0xffffffffu, ps1, 1);
        ps1 += __shfl_xor_sync(0xffffffffu, ps1, 2);
        lrow[0] = lrow[0] * corr0 + ps0;
        lrow[1] = lrow[1] * corr1 + ps1;
        mrow[0] = mn0; mrow[1] = mn1;
        #pragma unroll
        for (int d = 0; d < 16; d++) {
            oacc[d][0] *= corr0; oacc[d][1] *= corr0;
            oacc[d][2] *= corr1; oacc[d][3] *= corr1;
        }
        __syncwarp();   // Ps visible warp-wide

        // ---- O += P V  (16 x 128 per warp) ----
        #pragma unroll
        for (int ks = 0; ks < 8; ks++) {
            int kb = ks * 8;
            uint32_t a0 = __float_as_uint(Ps[prow0 + kb + tig]);
            uint32_t a1 = __float_as_uint(Ps[prow1 + kb + tig]);
            uint32_t a2 = __float_as_uint(Ps[prow0 + kb + tig + 4]);
            uint32_t a3 = __float_as_uint(Ps[prow1 + kb + tig + 4]);
            #pragma unroll
            for (int dt = 0; dt < 16; dt++) {
                uint32_t b0 = __float_as_uint(Vs[(kb + tig    ) * 132 + dt*8 + g]);
                uint32_t b1 = __float_as_uint(Vs[(kb + tig + 4) * 132 + dt*8 + g]);
                MMA_TF32(oacc[dt], a0, a1, a2, a3, b0, b1);
            }
        }
        __syncwarp();   // done reading Ps before next overwrite
    }

    float inv0 = 1.0f / lrow[0], inv1 = 1.0f / lrow[1];
    int b = bh >> 4, h = bh & 15;
    float* d0 = O + ((size_t)(b * SEQ + qrow0)) * DM + h * HDIM;
    float* d1 = O + ((size_t)(b * SEQ + qrow1)) * DM + h * HDIM;
    #pragma unroll
    for (int dt = 0; dt < 16; dt++) {
        int col = dt * 8 + 2 * tig;
        float2 r0 = make_float2(tf32r(oacc[dt][0] * inv0), tf32r(oacc[dt][1] * inv0));
        float2 r1 = make_float2(tf32r(oacc[dt][2] * inv1), tf32r(oacc[dt][3] * inv1));
        *(float2*)(d0 + col) = r0;
        *(float2*)(d1 + col) = r1;
    }
}

// ---------------- SwiGLU (tf32-rounded output) -------------------------------
__global__ __launch_bounds__(256)
void swiglu_kernel()
{
    size_t idx = (size_t)blockIdx.x * 256 + threadIdx.x;
    size_t row = idx >> 11;
    int c4 = (int)(idx & 2047);
    const float4* Pr = (const float4*)(g_p + row * (size_t)(8 * DM));
    float4 gt = Pr[c4];
    float4 vl = Pr[c4 + 2048];
    float4 r;
    r.x = tf32r(gt.x / (1.0f + expf(-gt.x)) * vl.x);
    r.y = tf32r(gt.y / (1.0f + expf(-gt.y)) * vl.y);
    r.z = tf32r(gt.z / (1.0f + expf(-gt.z)) * vl.z);
    r.w = tf32r(gt.w / (1.0f + expf(-gt.w)) * vl.w);
    ((float4*)g_ff)[idx] = r;
}

// ---------------- launch -----------------------------------------------------
extern "C" void kernel_launch(void* const* d_in, const int* in_sizes, int n_in,
                              void* d_out, int out_size)
{
    const float* x    = (const float*)d_in[0];
    const float* Wqkv = (const float*)d_in[1];
    const float* bqkv = (const float*)d_in[2];
    const float* Wo   = (const float*)d_in[3];
    const float* bo   = (const float*)d_in[4];
    const float* g1   = (const float*)d_in[5];
    const float* g2   = (const float*)d_in[6];
    const float* Wp   = (const float*)d_in[7];
    const float* bp   = (const float*)d_in[8];
    const float* Wff  = (const float*)d_in[9];
    const float* bff  = (const float*)d_in[10];
    float* out = (float*)d_out;

    float *pH, *pQKV, *pQ, *pK, *pV, *pO, *pX1, *pP, *pFF, *pW;
    cudaGetSymbolAddress((void**)&pH,   g_h);
    cudaGetSymbolAddress((void**)&pQKV, g_qkv);
    cudaGetSymbolAddress((void**)&pQ,   g_q);
    cudaGetSymbolAddress((void**)&pK,   g_k);
    cudaGetSymbolAddress((void**)&pV,   g_v);
    cudaGetSymbolAddress((void**)&pO,   g_o);
    cudaGetSymbolAddress((void**)&pX1,  g_x1);
    cudaGetSymbolAddress((void**)&pP,   g_p);
    cudaGetSymbolAddress((void**)&pFF,  g_ff);
    cudaGetSymbolAddress((void**)&pW,   g_w);

    float* wqkv = pW;                       // 12,582,912
    float* wo   = pW + 12582912;            //  4,194,304
    float* wp   = pW + 16777216;            // 33,554,432
    float* wff  = pW + 50331648;            // 16,777,216

    static constexpr int GEMM_SMEM = 108544;
    static constexpr int ATTN_SMEM = 118784;
    cudaFuncSetAttribute(tgemm_kernel, cudaFuncAttributeMaxDynamicSharedMemorySize, GEMM_SMEM);
    cudaFuncSetAttribute(attn_kernel,  cudaFuncAttributeMaxDynamicSharedMemorySize, ATTN_SMEM);

    // 0. pre-round weights to tf32 values
    cvtw_kernel<<<12582912/1024, 256>>>((const float4*)Wqkv, (float4*)wqkv);
    cvtw_kernel<<< 4194304/1024, 256>>>((const float4*)Wo,   (float4*)wo);
    cvtw_kernel<<<33554432/1024, 256>>>((const float4*)Wp,   (float4*)wp);
    cvtw_kernel<<<16777216/1024, 256>>>((const float4*)Wff,  (float4*)wff);

    // 1. h = rms(x, g1)   (tf32-rounded)
    rmsnorm_kernel<<<NROWS, 256>>>(x, g1, pH);
    // 2. qkv = h @ Wqkv + bqkv            [4096, 6144]
    tgemm_kernel<<<dim3(6144/128, NROWS/256), 256, GEMM_SMEM>>>(pH, wqkv, bqkv, nullptr, pQKV,
                                                                NROWS, 3*DM, DM);
    // 3. rope + split into Q/K/V [B,H,L,HD]  (tf32-rounded)
    rope_split_kernel<<<(NROWS * NHEAD * 64) / 256, 256>>>(pQKV);
    // 4. causal attention -> O [B,L,D]  (tensor-core, tf32)
    attn_kernel<<<dim3(SEQ/64, 2*NHEAD), 128, ATTN_SMEM>>>(pQ, pK, pV, pO);
    // 5. x1 = O @ Wo + bo + x
    tgemm_kernel<<<dim3(DM/128, NROWS/256), 256, GEMM_SMEM>>>(pO, wo, bo, x, pX1,
                                                              NROWS, DM, DM);
    // 6. h2 = rms(x1, g2)  (tf32-rounded)
    rmsnorm_kernel<<<NROWS, 256>>>(pX1, g2, pH);
    // 7. p = h2 @ Wp + bp                 [4096, 16384]
    tgemm_kernel<<<dim3(16384/128, NROWS/256), 256, GEMM_SMEM>>>(pH, wp, bp, nullptr, pP,
                                                                 NROWS, 8*DM, DM);
    // 8. ff = silu(gate) * value  (tf32-rounded)
    swiglu_kernel<<<(NROWS * 2048) / 256, 256>>>();
    // 9. out = ff @ Wff_out + bff + x1
    tgemm_kernel<<<dim3(DM/128, NROWS/256), 256, GEMM_SMEM>>>(pFF, wff, bff, pX1, out,
                                                              NROWS, DM, 4*DM);
}

// round 8
// speedup vs baseline: 6.3968x; 1.6684x over previous
#include <cuda_runtime.h>
#include <cuda_fp16.h>
#include <math.h>
#include <stdint.h>

static constexpr int SEQ   = 2048;
static constexpr int DM    = 2048;
static constexpr int NHEAD = 16;
static constexpr int HDIM  = 128;
static constexpr int NROWS = 4096;   // B * L

// ---------------- scratch (device globals; no allocation allowed) ----------
__device__ __align__(16) __half g_h  [(size_t)NROWS * DM];          // rms out (half)
__device__ __align__(16) __half g_qkv[(size_t)NROWS * 3 * DM];      // qkv (half)
__device__ __align__(16) float  g_q  [(size_t)NROWS * DM];          // rope'd fp32 (tf32)
__device__ __align__(16) float  g_k  [(size_t)NROWS * DM];
__device__ __align__(16) float  g_v  [(size_t)NROWS * DM];
__device__ __align__(16) __half g_o  [(size_t)NROWS * DM];          // attn out (half)
__device__ __align__(16) float  g_x1 [(size_t)NROWS * DM];          // residual fp32
__device__ __align__(16) __half g_p  [(size_t)NROWS * 8 * DM];      // ffn proj (half)
__device__ __align__(16) __half g_ff [(size_t)NROWS * 4 * DM];      // swiglu out (half)
// half TRANSPOSED weights: Wqkv^T | Wo^T | Wp^T | Wff^T (67,108,864 halves)
__device__ __align__(16) __half g_w  [(size_t)67108864];

__device__ __forceinline__ uint32_t f2tf32(float f) {
    uint32_t u;
    asm("cvt.rna.tf32.f32 %0, %1;" : "=r"(u) : "f"(f));
    return u;
}
__device__ __forceinline__ float tf32r(float f) { return __uint_as_float(f2tf32(f)); }

__device__ __forceinline__ void cp_async16(uint32_t smem, const void* g) {
    asm volatile("cp.async.cg.shared.global [%0], [%1], 16;" :: "r"(smem), "l"(g));
}
__device__ __forceinline__ void cp_commit() {
    asm volatile("cp.async.commit_group;");
}
template<int N> __device__ __forceinline__ void cp_wait() {
    asm volatile("cp.async.wait_group %0;" :: "n"(N));
}

#define MMA_TF32(acc, a0, a1, a2, a3, b0, b1)                                  \
    asm volatile(                                                              \
        "mma.sync.aligned.m16n8k8.row.col.f32.tf32.tf32.f32 "                  \
        "{%0,%1,%2,%3}, {%4,%5,%6,%7}, {%8,%9}, {%0,%1,%2,%3};"                \
        : "+f"(acc[0]), "+f"(acc[1]), "+f"(acc[2]), "+f"(acc[3])               \
        : "r"(a0), "r"(a1), "r"(a2), "r"(a3), "r"(b0), "r"(b1))

#define MMA_F16(acc, a0, a1, a2, a3, b0, b1)                                   \
    asm volatile(                                                              \
        "mma.sync.aligned.m16n8k16.row.col.f32.f16.f16.f32 "                   \
        "{%0,%1,%2,%3}, {%4,%5,%6,%7}, {%8,%9}, {%0,%1,%2,%3};"                \
        : "+f"(acc[0]), "+f"(acc[1]), "+f"(acc[2]), "+f"(acc[3])               \
        : "r"(a0), "r"(a1), "r"(a2), "r"(a3), "r"(b0), "r"(b1))

// ---------------- weight half pre-convert + transpose: Wt[n][k] = W[k][n] ----
__global__ __launch_bounds__(256)
void cvtw_t_kernel(const float* __restrict__ W, __half* __restrict__ Wt,
                   int K, int N)
{
    __shared__ float tile[32][33];
    int tx = threadIdx.x & 31, ty = threadIdx.x >> 5;   // 32 x 8
    int n0 = blockIdx.x * 32, k0 = blockIdx.y * 32;
    #pragma unroll
    for (int j = 0; j < 4; j++)
        tile[ty + 8*j][tx] = W[(size_t)(k0 + ty + 8*j) * N + n0 + tx];
    __syncthreads();
    #pragma unroll
    for (int j = 0; j < 4; j++)
        Wt[(size_t)(n0 + ty + 8*j) * K + k0 + tx] = __float2half(tile[tx][ty + 8*j]);
}

// ---------------- RMSNorm (half output) --------------------------------------
__global__ __launch_bounds__(256)
void rmsnorm_kernel(const float* __restrict__ x, const float* __restrict__ g,
                    __half* __restrict__ out)
{
    int row = blockIdx.x;
    int tid = threadIdx.x;
    const float4* xr = (const float4*)(x + (size_t)row * DM);
    const float4* gr = (const float4*)g;
    float4 v0 = xr[2*tid], v1 = xr[2*tid + 1];
    float ss = v0.x*v0.x + v0.y*v0.y + v0.z*v0.z + v0.w*v0.w
             + v1.x*v1.x + v1.y*v1.y + v1.z*v1.z + v1.w*v1.w;
    #pragma unroll
    for (int off = 16; off > 0; off >>= 1)
        ss += __shfl_xor_sync(0xffffffffu, ss, off);
    __shared__ float wsum[8];
    if ((tid & 31) == 0) wsum[tid >> 5] = ss;
    __syncthreads();
    float tot = wsum[0]+wsum[1]+wsum[2]+wsum[3]+wsum[4]+wsum[5]+wsum[6]+wsum[7];
    float sc = rsqrtf(tot * (1.0f / (float)DM) + 1e-8f);
    float4 ga = gr[2*tid], gb = gr[2*tid + 1];
    __half2 h0 = __floats2half2_rn(v0.x*sc*ga.x, v0.y*sc*ga.y);
    __half2 h1 = __floats2half2_rn(v0.z*sc*ga.z, v0.w*sc*ga.w);
    __half2 h2 = __floats2half2_rn(v1.x*sc*gb.x, v1.y*sc*gb.y);
    __half2 h3 = __floats2half2_rn(v1.z*sc*gb.z, v1.w*sc*gb.w);
    uint4 pk;
    pk.x = *(uint32_t*)&h0; pk.y = *(uint32_t*)&h1;
    pk.z = *(uint32_t*)&h2; pk.w = *(uint32_t*)&h3;
    ((uint4*)(out + (size_t)row * DM))[tid] = pk;
}

// ---------------- FP16 tensor-core GEMM, cp.async double-buffered ------------
// C[M,N] = A[M,K] @ Bt[N,K]^T + bias (+ residual, float-out only)
// 256x128 CTA tile, BK=64, 2-stage, 8 warps (4x2), warp tile 64x64.
// Smem: As 2*256*72 + Bs 2*128*72 halves = 110,592 bytes (stride 72 -> no conflicts).
template<bool HALF_OUT>
__global__ __launch_bounds__(256, 1)
void hgemm_kernel(const __half* __restrict__ A, const __half* __restrict__ Bt,
                  const float* __restrict__ bias, const float* __restrict__ res,
                  void* __restrict__ Cv, int M, int N, int K)
{
    extern __shared__ __half hsm[];
    __half* As = hsm;                  // 2 stages x 256 x 72
    __half* Bs = hsm + 36864;          // 2 stages x 128 x 72

    int tid = threadIdx.x;
    int wid = tid >> 5, lane = tid & 31;
    int wm  = wid >> 1;        // 0..3 -> 64 rows
    int wn  = wid & 1;         // 0..1 -> 64 cols
    int g   = lane >> 2;       // 0..7
    int tig = lane & 3;        // 0..3

    const __half* Ab = A  + (size_t)blockIdx.y * 256 * K;
    const __half* Bb = Bt + (size_t)blockIdx.x * 128 * K;

    uint32_t as_base = (uint32_t)__cvta_generic_to_shared(As);
    uint32_t bs_base = (uint32_t)__cvta_generic_to_shared(Bs);

    int arow[8], acol8[8], brow[4], bcol8[4];
    #pragma unroll
    for (int i = 0; i < 8; i++) {
        int c = tid + 256 * i;
        arow[i] = c >> 3; acol8[i] = (c & 7) * 8;
    }
    #pragma unroll
    for (int i = 0; i < 4; i++) {
        int c = tid + 256 * i;
        brow[i] = c >> 3; bcol8[i] = (c & 7) * 8;
    }

    float acc[4][8][4];
    #pragma unroll
    for (int i = 0; i < 4; i++)
        #pragma unroll
        for (int j = 0; j < 8; j++) {
            acc[i][j][0] = 0.f; acc[i][j][1] = 0.f;
            acc[i][j][2] = 0.f; acc[i][j][3] = 0.f;
        }

    const int NT = K >> 6;

    #pragma unroll
    for (int i = 0; i < 8; i++)
        cp_async16(as_base + (uint32_t)((arow[i] * 72 + acol8[i]) * 2),
                   Ab + (size_t)arow[i] * K + acol8[i]);
    #pragma unroll
    for (int i = 0; i < 4; i++)
        cp_async16(bs_base + (uint32_t)((brow[i] * 72 + bcol8[i]) * 2),
                   Bb + (size_t)brow[i] * K + bcol8[i]);
    cp_commit();

    for (int t = 0; t < NT; t++) {
        int buf = t & 1;
        if (t + 1 < NT) {
            int nb = (t + 1) & 1;
            int k0 = (t + 1) * 64;
            uint32_t aoff = as_base + (uint32_t)(nb * 18432 * 2);
            uint32_t boff = bs_base + (uint32_t)(nb * 9216 * 2);
            #pragma unroll
            for (int i = 0; i < 8; i++)
                cp_async16(aoff + (uint32_t)((arow[i] * 72 + acol8[i]) * 2),
                           Ab + (size_t)arow[i] * K + k0 + acol8[i]);
            #pragma unroll
            for (int i = 0; i < 4; i++)
                cp_async16(boff + (uint32_t)((brow[i] * 72 + bcol8[i]) * 2),
                           Bb + (size_t)brow[i] * K + k0 + bcol8[i]);
            cp_commit();
            cp_wait<1>();
        } else {
            cp_wait<0>();
        }
        __syncthreads();

        int abuf = buf * 18432, bbuf = buf * 9216;
        #pragma unroll
        for (int ks = 0; ks < 4; ks++) {
            int kb = ks * 16;
            uint32_t af[4][4], bf[8][2];
            #pragma unroll
            for (int mi = 0; mi < 4; mi++) {
                int row = wm * 64 + mi * 16 + g;
                const __half* r0 = &As[abuf + row * 72 + kb + 2 * tig];
                const __half* r1 = &As[abuf + (row + 8) * 72 + kb + 2 * tig];
                af[mi][0] = *(const uint32_t*)r0;
                af[mi][1] = *(const uint32_t*)r1;
                af[mi][2] = *(const uint32_t*)(r0 + 8);
                af[mi][3] = *(const uint32_t*)(r1 + 8);
            }
            #pragma unroll
            for (int ni = 0; ni < 8; ni++) {
                int col = wn * 64 + ni * 8 + g;
                const __half* b0 = &Bs[bbuf + col * 72 + kb + 2 * tig];
                bf[ni][0] = *(const uint32_t*)b0;
                bf[ni][1] = *(const uint32_t*)(b0 + 8);
            }
            #pragma unroll
            for (int mi = 0; mi < 4; mi++)
                #pragma unroll
                for (int ni = 0; ni < 8; ni++)
                    MMA_F16(acc[mi][ni], af[mi][0], af[mi][1], af[mi][2], af[mi][3],
                            bf[ni][0], bf[ni][1]);
        }
        __syncthreads();
    }

    #pragma unroll
    for (int mi = 0; mi < 4; mi++) {
        #pragma unroll
        for (int ni = 0; ni < 8; ni++) {
            int row = blockIdx.y * 256 + wm * 64 + mi * 16 + g;
            int col = blockIdx.x * 128 + wn * 64 + ni * 8 + 2 * tig;
            float bx = bias[col], by = bias[col + 1];
            size_t off0 = (size_t)row * N + col;
            size_t off1 = (size_t)(row + 8) * N + col;
            float r0x = acc[mi][ni][0] + bx, r0y = acc[mi][ni][1] + by;
            float r1x = acc[mi][ni][2] + bx, r1y = acc[mi][ni][3] + by;
            if (HALF_OUT) {
                __half* C = (__half*)Cv;
                __half2 h0 = __floats2half2_rn(r0x, r0y);
                __half2 h1 = __floats2half2_rn(r1x, r1y);
                *(__half2*)(C + off0) = h0;
                *(__half2*)(C + off1) = h1;
            } else {
                float* C = (float*)Cv;
                if (res) {
                    float2 q0 = *(const float2*)(res + off0);
                    float2 q1 = *(const float2*)(res + off1);
                    r0x += q0.x; r0y += q0.y;
                    r1x += q1.x; r1y += q1.y;
                }
                *(float2*)(C + off0) = make_float2(r0x, r0y);
                *(float2*)(C + off1) = make_float2(r1x, r1y);
            }
        }
    }
}

// ---------------- RoPE + head split: qkv(half) -> Q/K/V fp32 (tf32-rounded) --
__global__ __launch_bounds__(256)
void rope_split_kernel(const __half* __restrict__ qkv)
{
    int idx = blockIdx.x * 256 + threadIdx.x;
    int i   = idx & 63;
    int h   = (idx >> 6) & 15;
    int row = idx >> 10;          // b*SEQ + l
    int l   = row & (SEQ - 1);
    int b   = row >> 11;
    const __half* base = qkv + (size_t)row * (3 * DM) + h * HDIM;
    float q0 = __half2float(base[i]),        q1 = __half2float(base[i + 64]);
    float k0 = __half2float(base[DM + i]),   k1 = __half2float(base[DM + i + 64]);
    float v0 = __half2float(base[2*DM + i]), v1 = __half2float(base[2*DM + i + 64]);
    float invf = powf(10000.0f, -(float)(2 * i) * (1.0f / 128.0f));
    float ang = (float)l * invf;
    float sn, cs;
    sincosf(ang, &sn, &cs);
    size_t ob = ((size_t)((b * NHEAD + h) * SEQ + l)) * HDIM;
    g_q[ob + i]      = tf32r(q0 * cs - q1 * sn);
    g_q[ob + i + 64] = tf32r(q1 * cs + q0 * sn);
    g_k[ob + i]      = tf32r(k0 * cs - k1 * sn);
    g_k[ob + i + 64] = tf32r(k1 * cs + k0 * sn);
    g_v[ob + i]      = tf32r(v0);
    g_v[ob + i + 64] = tf32r(v1);
}

// ---------------- TF32 MMA causal flash attention (O stored half) ------------
__global__ __launch_bounds__(128)
void attn_kernel(const float* __restrict__ Q, const float* __restrict__ K,
                 const float* __restrict__ V, __half* __restrict__ O)
{
    extern __shared__ float sm_[];
    float* Qs = sm_;                 // 64*132
    float* Ks = Qs + 64 * 132;
    float* Vs = Ks + 64 * 132;
    float* Ps = Vs + 64 * 132;       // 64*68

    int tid = threadIdx.x;
    int wid = tid >> 5, lane = tid & 31;
    int g = lane >> 2, tig = lane & 3;
    int bh = blockIdx.y;
    int q0 = blockIdx.x * 64;
    const float* Qb = Q + (size_t)bh * SEQ * HDIM;
    const float* Kb = K + (size_t)bh * SEQ * HDIM;
    const float* Vb = V + (size_t)bh * SEQ * HDIM;

    #pragma unroll
    for (int it = 0; it < 16; it++) {
        int idx = it * 128 + tid;
        int r = idx >> 5, c4 = idx & 31;
        *(float4*)&Qs[r * 132 + c4 * 4] =
            *(const float4*)(Qb + (size_t)(q0 + r) * HDIM + c4 * 4);
    }

    const float scale = 0.08838834764831845f;   // 1/sqrt(128)
    float mrow[2] = {-INFINITY, -INFINITY};
    float lrow[2] = {0.f, 0.f};
    float oacc[16][4];
    #pragma unroll
    for (int d = 0; d < 16; d++) {
        oacc[d][0] = 0.f; oacc[d][1] = 0.f; oacc[d][2] = 0.f; oacc[d][3] = 0.f;
    }

    int arow0 = (wid * 16 + g) * 132;
    int arow1 = (wid * 16 + g + 8) * 132;
    int prow0 = (wid * 16 + g) * 68;
    int prow1 = (wid * 16 + g + 8) * 68;
    int qrow0 = q0 + wid * 16 + g;
    int qrow1 = qrow0 + 8;

    for (int n0 = 0; n0 <= q0; n0 += 64) {
        __syncthreads();
        #pragma unroll
        for (int it = 0; it < 16; it++) {
            int idx = it * 128 + tid;
            int r = idx >> 5, c4 = idx & 31;
            *(float4*)&Ks[r * 132 + c4 * 4] =
                *(const float4*)(Kb + (size_t)(n0 + r) * HDIM + c4 * 4);
            *(float4*)&Vs[r * 132 + c4 * 4] =
                *(const float4*)(Vb + (size_t)(n0 + r) * HDIM + c4 * 4);
        }
        __syncthreads();

        float sacc[8][4];
        #pragma unroll
        for (int ni = 0; ni < 8; ni++) {
            sacc[ni][0] = 0.f; sacc[ni][1] = 0.f;
            sacc[ni][2] = 0.f; sacc[ni][3] = 0.f;
        }
        #pragma unroll
        for (int ks = 0; ks < 16; ks++) {
            int kb = ks * 8;
            uint32_t a0 = __float_as_uint(Qs[arow0 + kb + tig]);
            uint32_t a1 = __float_as_uint(Qs[arow1 + kb + tig]);
            uint32_t a2 = __float_as_uint(Qs[arow0 + kb + tig + 4]);
            uint32_t a3 = __float_as_uint(Qs[arow1 + kb + tig + 4]);
            #pragma unroll
            for (int ni = 0; ni < 8; ni++) {
                uint32_t b0 = __float_as_uint(Ks[(ni*8 + g) * 132 + kb + tig]);
                uint32_t b1 = __float_as_uint(Ks[(ni*8 + g) * 132 + kb + tig + 4]);
                MMA_TF32(sacc[ni], a0, a1, a2, a3, b0, b1);
            }
        }

        bool diag = (n0 == q0);
        float tm0 = -INFINITY, tm1 = -INFINITY;
        #pragma unroll
        for (int ni = 0; ni < 8; ni++) {
            int n = n0 + ni * 8 + 2 * tig;
            float s0 = sacc[ni][0] * scale;
            float s1 = sacc[ni][1] * scale;
            float s2 = sacc[ni][2] * scale;
            float s3 = sacc[ni][3] * scale;
            if (diag) {
                if (n     > qrow0) s0 = -INFINITY;
                if (n + 1 > qrow0) s1 = -INFINITY;
                if (n     > qrow1) s2 = -INFINITY;
                if (n + 1 > qrow1) s3 = -INFINITY;
            }
            sacc[ni][0] = s0; sacc[ni][1] = s1;
            sacc[ni][2] = s2; sacc[ni][3] = s3;
            tm0 = fmaxf(tm0, fmaxf(s0, s1));
            tm1 = fmaxf(tm1, fmaxf(s2, s3));
        }
        tm0 = fmaxf(tm0, __shfl_xor_sync(0xffffffffu, tm0, 1));
        tm0 = fmaxf(tm0, __shfl_xor_sync(0xffffffffu, tm0, 2));
        tm1 = fmaxf(tm1, __shfl_xor_sync(0xffffffffu, tm1, 1));
        tm1 = fmaxf(tm1, __shfl_xor_sync(0xffffffffu, tm1, 2));

        float mn0 = fmaxf(mrow[0], tm0), mn1 = fmaxf(mrow[1], tm1);
        float corr0 = expf(mrow[0] - mn0), corr1 = expf(mrow[1] - mn1);
        float ps0 = 0.f, ps1 = 0.f;
        #pragma unroll
        for (int ni = 0; ni < 8; ni++) {
            float p0 = expf(sacc[ni][0] - mn0);
            float p1 = expf(sacc[ni][1] - mn0);
            float p2 = expf(sacc[ni][2] - mn1);
            float p3 = expf(sacc[ni][3] - mn1);
            ps0 += p0 + p1; ps1 += p2 + p3;
            Ps[prow0 + ni*8 + 2*tig    ] = tf32r(p0);
            Ps[prow0 + ni*8 + 2*tig + 1] = tf32r(p1);
            Ps[prow1 + ni*8 + 2*tig    ] = tf32r(p2);
            Ps[prow1 + ni*8 + 2*tig + 1] = tf32r(p3);
        }
        ps0 += __shfl_xor_sync(0xffffffffu, ps0, 1);
        ps0 += __shfl_xor_sync(0xffffffffu, ps0, 2);
        ps1 += __shfl_xor_sync(0xffffffffu, ps1, 1);
        ps1 += __shfl_xor_sync(0xffffffffu, ps1, 2);
        lrow[0] = lrow[0] * corr0 + ps0;
        lrow[1] = lrow[1] * corr1 + ps1;
        mrow[0] = mn0; mrow[1] = mn1;
        #pragma unroll
        for (int d = 0; d < 16; d++) {
            oacc[d][0] *= corr0; oacc[d][1] *= corr0;
            oacc[d][2] *= corr1; oacc[d][3] *= corr1;
        }
        __syncwarp();

        #pragma unroll
        for (int ks = 0; ks < 8; ks++) {
            int kb = ks * 8;
            uint32_t a0 = __float_as_uint(Ps[prow0 + kb + tig]);
            uint32_t a1 = __float_as_uint(Ps[prow1 + kb + tig]);
            uint32_t a2 = __float_as_uint(Ps[prow0 + kb + tig + 4]);
            uint32_t a3 = __float_as_uint(Ps[prow1 + kb + tig + 4]);
            #pragma unroll
            for (int dt = 0; dt < 16; dt++) {
                uint32_t b0 = __float_as_uint(Vs[(kb + tig    ) * 132 + dt*8 + g]);
                uint32_t b1 = __float_as_uint(Vs[(kb + tig + 4) * 132 + dt*8 + g]);
                MMA_TF32(oacc[dt], a0, a1, a2, a3, b0, b1);
            }
        }
        __syncwarp();
    }

    float inv0 = 1.0f / lrow[0], inv1 = 1.0f / lrow[1];
    int b = bh >> 4, h = bh & 15;
    __half* d0 = O + ((size_t)(b * SEQ + qrow0)) * DM + h * HDIM;
    __half* d1 = O + ((size_t)(b * SEQ + qrow1)) * DM + h * HDIM;
    #pragma unroll
    for (int dt = 0; dt < 16; dt++) {
        int col = dt * 8 + 2 * tig;
        __half2 r0 = __floats2half2_rn(oacc[dt][0] * inv0, oacc[dt][1] * inv0);
        __half2 r1 = __floats2half2_rn(oacc[dt][2] * inv1, oacc[dt][3] * inv1);
        *(__half2*)(d0 + col) = r0;
        *(__half2*)(d1 + col) = r1;
    }
}

// ---------------- SwiGLU: half in, half out ----------------------------------
__global__ __launch_bounds__(256)
void swiglu_kernel()
{
    size_t idx = (size_t)blockIdx.x * 256 + threadIdx.x;  // 8 halves per thread
    size_t row = idx >> 10;
    int c = (int)(idx & 1023);
    const uint4* gp = (const uint4*)(g_p + row * (size_t)(8 * DM));
    uint4 gt4 = gp[c];
    uint4 vl4 = gp[c + 1024];
    uint4 o;
    const uint32_t* gw = &gt4.x;
    const uint32_t* vw = &vl4.x;
    uint32_t* ow = &o.x;
    #pragma unroll
    for (int j = 0; j < 4; j++) {
        float2 gf = __half22float2(*(const __half2*)&gw[j]);
        float2 vf = __half22float2(*(const __half2*)&vw[j]);
        float rx = gf.x / (1.0f + expf(-gf.x)) * vf.x;
        float ry = gf.y / (1.0f + expf(-gf.y)) * vf.y;
        __half2 h = __floats2half2_rn(rx, ry);
        ow[j] = *(uint32_t*)&h;
    }
    ((uint4*)(g_ff + row * (size_t)(4 * DM)))[c] = o;
}

// ---------------- launch -----------------------------------------------------
extern "C" void kernel_launch(void* const* d_in, const int* in_sizes, int n_in,
                              void* d_out, int out_size)
{
    const float* x    = (const float*)d_in[0];
    const float* Wqkv = (const float*)d_in[1];
    const float* bqkv = (const float*)d_in[2];
    const float* Wo   = (const float*)d_in[3];
    const float* bo   = (const float*)d_in[4];
    const float* g1   = (const float*)d_in[5];
    const float* g2   = (const float*)d_in[6];
    const float* Wp   = (const float*)d_in[7];
    const float* bp   = (const float*)d_in[8];
    const float* Wff  = (const float*)d_in[9];
    const float* bff  = (const float*)d_in[10];
    float* out = (float*)d_out;

    __half *pH, *pQKV, *pO, *pP, *pFF, *pW;
    float *pQ, *pK, *pV, *pX1;
    cudaGetSymbolAddress((void**)&pH,   g_h);
    cudaGetSymbolAddress((void**)&pQKV, g_qkv);
    cudaGetSymbolAddress((void**)&pQ,   g_q);
    cudaGetSymbolAddress((void**)&pK,   g_k);
    cudaGetSymbolAddress((void**)&pV,   g_v);
    cudaGetSymbolAddress((void**)&pO,   g_o);
    cudaGetSymbolAddress((void**)&pX1,  g_x1);
    cudaGetSymbolAddress((void**)&pP,   g_p);
    cudaGetSymbolAddress((void**)&pFF,  g_ff);
    cudaGetSymbolAddress((void**)&pW,   g_w);

    __half* wqkv = pW;                       // [6144 x 2048]
    __half* wo   = pW + 12582912;            // [2048 x 2048]
    __half* wp   = pW + 16777216;            // [16384 x 2048]
    __half* wff  = pW + 50331648;            // [2048 x 8192]

    static constexpr int GEMM_SMEM = 110592;
    static constexpr int ATTN_SMEM = 118784;
    cudaFuncSetAttribute(hgemm_kernel<true>,  cudaFuncAttributeMaxDynamicSharedMemorySize, GEMM_SMEM);
    cudaFuncSetAttribute(hgemm_kernel<false>, cudaFuncAttributeMaxDynamicSharedMemorySize, GEMM_SMEM);
    cudaFuncSetAttribute(attn_kernel,  cudaFuncAttributeMaxDynamicSharedMemorySize, ATTN_SMEM);

    // 0. pre-convert + transpose weights to half:  wT[n][k] = (half)W[k][n]
    cvtw_t_kernel<<<dim3(6144/32,  2048/32), 256>>>(Wqkv, wqkv, 2048, 6144);
    cvtw_t_kernel<<<dim3(2048/32,  2048/32), 256>>>(Wo,   wo,   2048, 2048);
    cvtw_t_kernel<<<dim3(16384/32, 2048/32), 256>>>(Wp,   wp,   2048, 16384);
    cvtw_t_kernel<<<dim3(2048/32,  8192/32), 256>>>(Wff,  wff,  8192, 2048);

    // 1. h = rms(x, g1)  (half)
    rmsnorm_kernel<<<NROWS, 256>>>(x, g1, pH);
    // 2. qkv = h @ Wqkv + bqkv            [4096, 6144]  (half out)
    hgemm_kernel<true><<<dim3(6144/128, NROWS/256), 256, GEMM_SMEM>>>(
        pH, wqkv, bqkv, nullptr, pQKV, NROWS, 3*DM, DM);
    // 3. rope + split into Q/K/V [B,H,L,HD]  (fp32, tf32-rounded)
    rope_split_kernel<<<(NROWS * NHEAD * 64) / 256, 256>>>(pQKV);
    // 4. causal attention -> O (half)
    attn_kernel<<<dim3(SEQ/64, 2*NHEAD), 128, ATTN_SMEM>>>(pQ, pK, pV, pO);
    // 5. x1 = O @ Wo + bo + x  (fp32 out, residual)
    hgemm_kernel<false><<<dim3(DM/128, NROWS/256), 256, GEMM_SMEM>>>(
        pO, wo, bo, x, pX1, NROWS, DM, DM);
    // 6. h2 = rms(x1, g2)  (half)
    rmsnorm_kernel<<<NROWS, 256>>>(pX1, g2, pH);
    // 7. p = h2 @ Wp + bp                 [4096, 16384]  (half out)
    hgemm_kernel<true><<<dim3(16384/128, NROWS/256), 256, GEMM_SMEM>>>(
        pH, wp, bp, nullptr, pP, NROWS, 8*DM, DM);
    // 8. ff = silu(gate) * value  (half)
    swiglu_kernel<<<(NROWS * 1024) / 256, 256>>>();
    // 9. out = ff @ Wff_out + bff + x1  (fp32 out, residual)
    hgemm_kernel<false><<<dim3(DM/128, NROWS/256), 256, GEMM_SMEM>>>(
        pFF, wff, bff, pX1, out, NROWS, DM, 4*DM);
}

// round 11
// speedup vs baseline: 6.4043x; 1.0012x over previous
#include <cuda_runtime.h>
#include <cuda_fp16.h>
#include <math.h>
#include <stdint.h>

static constexpr int SEQ   = 2048;
static constexpr int DM    = 2048;
static constexpr int NHEAD = 16;
static constexpr int HDIM  = 128;
static constexpr int NROWS = 4096;   // B * L

// ---------------- scratch (device globals; no allocation allowed) ----------
__device__ __align__(16) __half g_h  [(size_t)NROWS * DM];          // rms out (half)
__device__ __align__(16) __half g_qkv[(size_t)NROWS * 3 * DM];      // qkv (half)
__device__ __align__(16) float  g_q  [(size_t)NROWS * DM];          // rope'd fp32 (tf32)
__device__ __align__(16) float  g_k  [(size_t)NROWS * DM];
__device__ __align__(16) float  g_v  [(size_t)NROWS * DM];
__device__ __align__(16) __half g_o  [(size_t)NROWS * DM];          // attn out (half)
__device__ __align__(16) float  g_x1 [(size_t)NROWS * DM];          // residual fp32
__device__ __align__(16) __half g_ff [(size_t)NROWS * 4 * DM];      // swiglu out (half)
// half TRANSPOSED weights: Wqkv^T | Wo^T | Wp^T(permuted) | Wff^T
__device__ __align__(16) __half g_w  [(size_t)67108864];

__device__ __forceinline__ uint32_t f2tf32(float f) {
    uint32_t u;
    asm("cvt.rna.tf32.f32 %0, %1;" : "=r"(u) : "f"(f));
    return u;
}
__device__ __forceinline__ float tf32r(float f) { return __uint_as_float(f2tf32(f)); }

__device__ __forceinline__ void cp_async16(uint32_t smem, const void* g) {
    asm volatile("cp.async.cg.shared.global [%0], [%1], 16;" :: "r"(smem), "l"(g));
}
__device__ __forceinline__ void cp_commit() {
    asm volatile("cp.async.commit_group;");
}
template<int N> __device__ __forceinline__ void cp_wait() {
    asm volatile("cp.async.wait_group %0;" :: "n"(N));
}

#define MMA_TF32(acc, a0, a1, a2, a3, b0, b1)                                  \
    asm volatile(                                                              \
        "mma.sync.aligned.m16n8k8.row.col.f32.tf32.tf32.f32 "                  \
        "{%0,%1,%2,%3}, {%4,%5,%6,%7}, {%8,%9}, {%0,%1,%2,%3};"                \
        : "+f"(acc[0]), "+f"(acc[1]), "+f"(acc[2]), "+f"(acc[3])               \
        : "r"(a0), "r"(a1), "r"(a2), "r"(a3), "r"(b0), "r"(b1))

#define MMA_F16(acc, a0, a1, a2, a3, b0, b1)                                   \
    asm volatile(                                                              \
        "mma.sync.aligned.m16n8k16.row.col.f32.f16.f16.f32 "                   \
        "{%0,%1,%2,%3}, {%4,%5,%6,%7}, {%8,%9}, {%0,%1,%2,%3};"                \
        : "+f"(acc[0]), "+f"(acc[1]), "+f"(acc[2]), "+f"(acc[3])               \
        : "r"(a0), "r"(a1), "r"(a2), "r"(a3), "r"(b0), "r"(b1))

// ---------------- weight half convert + transpose: Wt[n][k] = W[k][n] --------
// PERM: swiglu row permutation for Wp (gate/value interleaved per 64-row block)
template<bool PERM>
__global__ __launch_bounds__(256)
void cvtw_t_kernel(const float* __restrict__ W, __half* __restrict__ Wt,
                   int K, int N)
{
    __shared__ float tile[32][33];
    int tx = threadIdx.x & 31, ty = threadIdx.x >> 5;   // 32 x 8
    int n0 = blockIdx.x * 32, k0 = blockIdx.y * 32;
    #pragma unroll
    for (int j = 0; j < 4; j++)
        tile[ty + 8*j][tx] = W[(size_t)(k0 + ty + 8*j) * N + n0 + tx];
    __syncthreads();
    #pragma unroll
    for (int j = 0; j < 4; j++) {
        int n = n0 + ty + 8*j;
        int r = n;
        if (PERM) {
            int half_n = N >> 1;                 // 8192
            if (n < half_n) r = (n >> 5) * 64 + (n & 31);
            else { int f = n - half_n; r = (f >> 5) * 64 + 32 + (f & 31); }
        }
        Wt[(size_t)r * K + k0 + tx] = __float2half(tile[tx][ty + 8*j]);
    }
}

// ---------------- RMSNorm (half output) --------------------------------------
__global__ __launch_bounds__(256)
void rmsnorm_kernel(const float* __restrict__ x, const float* __restrict__ g,
                    __half* __restrict__ out)
{
    int row = blockIdx.x;
    int tid = threadIdx.x;
    const float4* xr = (const float4*)(x + (size_t)row * DM);
    const float4* gr = (const float4*)g;
    float4 v0 = xr[2*tid], v1 = xr[2*tid + 1];
    float ss = v0.x*v0.x + v0.y*v0.y + v0.z*v0.z + v0.w*v0.w
             + v1.x*v1.x + v1.y*v1.y + v1.z*v1.z + v1.w*v1.w;
    #pragma unroll
    for (int off = 16; off > 0; off >>= 1)
        ss += __shfl_xor_sync(0xffffffffu, ss, off);
    __shared__ float wsum[8];
    if ((tid & 31) == 0) wsum[tid >> 5] = ss;
    __syncthreads();
    float tot = wsum[0]+wsum[1]+wsum[2]+wsum[3]+wsum[4]+wsum[5]+wsum[6]+wsum[7];
    float sc = rsqrtf(tot * (1.0f / (float)DM) + 1e-8f);
    float4 ga = gr[2*tid], gb = gr[2*tid + 1];
    __half2 h0 = __floats2half2_rn(v0.x*sc*ga.x, v0.y*sc*ga.y);
    __half2 h1 = __floats2half2_rn(v0.z*sc*ga.z, v0.w*sc*ga.w);
    __half2 h2 = __floats2half2_rn(v1.x*sc*gb.x, v1.y*sc*gb.y);
    __half2 h3 = __floats2half2_rn(v1.z*sc*gb.z, v1.w*sc*gb.w);
    uint4 pk;
    pk.x = *(uint32_t*)&h0; pk.y = *(uint32_t*)&h1;
    pk.z = *(uint32_t*)&h2; pk.w = *(uint32_t*)&h3;
    ((uint4*)(out + (size_t)row * DM))[tid] = pk;
}

// ---------------- FP16 tensor-core GEMM, cp.async double-buffered ------------
// MODE 0: float out + optional residual; MODE 1: half out; MODE 2: swiglu->half
// 256x128 CTA tile, BK=64, 2-stage, 8 warps (4x2), warp tile 64x64.
template<int MODE>
__global__ __launch_bounds__(256, 1)
void hgemm_kernel(const __half* __restrict__ A, const __half* __restrict__ Bt,
                  const float* __restrict__ bias, const float* __restrict__ res,
                  void* __restrict__ Cv, int M, int N, int K)
{
    extern __shared__ __half hsm[];
    __half* As = hsm;                  // 2 stages x 256 x 72
    __half* Bs = hsm + 36864;          // 2 stages x 128 x 72

    int tid = threadIdx.x;
    int wid = tid >> 5, lane = tid & 31;
    int wm  = wid >> 1;        // 0..3 -> 64 rows
    int wn  = wid & 1;         // 0..1 -> 64 cols
    int g   = lane >> 2;       // 0..7
    int tig = lane & 3;        // 0..3

    const __half* Ab = A  + (size_t)blockIdx.y * 256 * K;
    const __half* Bb = Bt + (size_t)blockIdx.x * 128 * K;

    uint32_t as_base = (uint32_t)__cvta_generic_to_shared(As);
    uint32_t bs_base = (uint32_t)__cvta_generic_to_shared(Bs);

    int arow[8], acol8[8], brow[4], bcol8[4];
    #pragma unroll
    for (int i = 0; i < 8; i++) {
        int c = tid + 256 * i;
        arow[i] = c >> 3; acol8[i] = (c & 7) * 8;
    }
    #pragma unroll
    for (int i = 0; i < 4; i++) {
        int c = tid + 256 * i;
        brow[i] = c >> 3; bcol8[i] = (c & 7) * 8;
    }

    float acc[4][8][4];
    #pragma unroll
    for (int i = 0; i < 4; i++)
        #pragma unroll
        for (int j = 0; j < 8; j++) {
            acc[i][j][0] = 0.f; acc[i][j][1] = 0.f;
            acc[i][j][2] = 0.f; acc[i][j][3] = 0.f;
        }

    const int NT = K >> 6;

    #pragma unroll
    for (int i = 0; i < 8; i++)
        cp_async16(as_base + (uint32_t)((arow[i] * 72 + acol8[i]) * 2),
                   Ab + (size_t)arow[i] * K + acol8[i]);
    #pragma unroll
    for (int i = 0; i < 4; i++)
        cp_async16(bs_base + (uint32_t)((brow[i] * 72 + bcol8[i]) * 2),
                   Bb + (size_t)brow[i] * K + bcol8[i]);
    cp_commit();

    for (int t = 0; t < NT; t++) {
        int buf = t & 1;
        if (t + 1 < NT) {
            int nb = (t + 1) & 1;
            int k0 = (t + 1) * 64;
            uint32_t aoff = as_base + (uint32_t)(nb * 18432 * 2);
            uint32_t boff = bs_base + (uint32_t)(nb * 9216 * 2);
            #pragma unroll
            for (int i = 0; i < 8; i++)
                cp_async16(aoff + (uint32_t)((arow[i] * 72 + acol8[i]) * 2),
                           Ab + (size_t)arow[i] * K + k0 + acol8[i]);
            #pragma unroll
            for (int i = 0; i < 4; i++)
                cp_async16(boff + (uint32_t)((brow[i] * 72 + bcol8[i]) * 2),
                           Bb + (size_t)brow[i] * K + k0 + bcol8[i]);
            cp_commit();
            cp_wait<1>();
        } else {
            cp_wait<0>();
        }
        __syncthreads();

        int abuf = buf * 18432, bbuf = buf * 9216;
        #pragma unroll
        for (int ks = 0; ks < 4; ks++) {
            int kb = ks * 16;
            uint32_t af[4][4], bf[8][2];
            #pragma unroll
            for (int mi = 0; mi < 4; mi++) {
                int row = wm * 64 + mi * 16 + g;
                const __half* r0 = &As[abuf + row * 72 + kb + 2 * tig];
                const __half* r1 = &As[abuf + (row + 8) * 72 + kb + 2 * tig];
                af[mi][0] = *(const uint32_t*)r0;
                af[mi][1] = *(const uint32_t*)r1;
                af[mi][2] = *(const uint32_t*)(r0 + 8);
                af[mi][3] = *(const uint32_t*)(r1 + 8);
            }
            #pragma unroll
            for (int ni = 0; ni < 8; ni++) {
                int col = wn * 64 + ni * 8 + g;
                const __half* b0 = &Bs[bbuf + col * 72 + kb + 2 * tig];
                bf[ni][0] = *(const uint32_t*)b0;
                bf[ni][1] = *(const uint32_t*)(b0 + 8);
            }
            #pragma unroll
            for (int mi = 0; mi < 4; mi++)
                #pragma unroll
                for (int ni = 0; ni < 8; ni++)
                    MMA_F16(acc[mi][ni], af[mi][0], af[mi][1], af[mi][2], af[mi][3],
                            bf[ni][0], bf[ni][1]);
        }
        __syncthreads();
    }

    if (MODE == 2) {
        // swiglu fused: warp block holds [gate f..f+31 | value f..f+31]
        __half* FF = (__half*)Cv;
        int b = blockIdx.x * 2 + wn;
        #pragma unroll
        for (int mi = 0; mi < 4; mi++) {
            int row = blockIdx.y * 256 + wm * 64 + mi * 16 + g;
            #pragma unroll
            for (int ni = 0; ni < 4; ni++) {
                int off = ni * 8 + 2 * tig;
                int f   = b * 32 + off;              // ff column
                float bg0 = bias[f],        bg1 = bias[f + 1];
                float bv0 = bias[8192 + f], bv1 = bias[8192 + f + 1];
                #pragma unroll
                for (int rr = 0; rr < 2; rr++) {
                    float gt0 = acc[mi][ni][2*rr]   + bg0;
                    float gt1 = acc[mi][ni][2*rr+1] + bg1;
                    float vl0 = acc[mi][ni+4][2*rr]   + bv0;
                    float vl1 = acc[mi][ni+4][2*rr+1] + bv1;
                    float r0 = gt0 / (1.0f + expf(-gt0)) * vl0;
                    float r1 = gt1 / (1.0f + expf(-gt1)) * vl1;
                    __half2 h = __floats2half2_rn(r0, r1);
                    *(__half2*)(FF + (size_t)(row + 8*rr) * (4*DM) + f) = h;
                }
            }
        }
    } else {
        #pragma unroll
        for (int mi = 0; mi < 4; mi++) {
            #pragma unroll
            for (int ni = 0; ni < 8; ni++) {
                int row = blockIdx.y * 256 + wm * 64 + mi * 16 + g;
                int col = blockIdx.x * 128 + wn * 64 + ni * 8 + 2 * tig;
                float bx = bias[col], by = bias[col + 1];
                size_t off0 = (size_t)row * N + col;
                size_t off1 = (size_t)(row + 8) * N + col;
                float r0x = acc[mi][ni][0] + bx, r0y = acc[mi][ni][1] + by;
                float r1x = acc[mi][ni][2] + bx, r1y = acc[mi][ni][3] + by;
                if (MODE == 1) {
                    __half* C = (__half*)Cv;
                    *(__half2*)(C + off0) = __floats2half2_rn(r0x, r0y);
                    *(__half2*)(C + off1) = __floats2half2_rn(r1x, r1y);
                } else {
                    float* C = (float*)Cv;
                    if (res) {
                        float2 q0 = *(const float2*)(res + off0);
                        float2 q1 = *(const float2*)(res + off1);
                        r0x += q0.x; r0y += q0.y;
                        r1x += q1.x; r1y += q1.y;
                    }
                    *(float2*)(C + off0) = make_float2(r0x, r0y);
                    *(float2*)(C + off1) = make_float2(r1x, r1y);
                }
            }
        }
    }
}

// ---------------- RoPE + head split: qkv(half) -> Q/K/V fp32 (tf32-rounded) --
__global__ __launch_bounds__(256)
void rope_split_kernel(const __half* __restrict__ qkv)
{
    int idx = blockIdx.x * 256 + threadIdx.x;
    int i   = idx & 63;
    int h   = (idx >> 6) & 15;
    int row = idx >> 10;          // b*SEQ + l
    int l   = row & (SEQ - 1);
    int b   = row >> 11;
    const __half* base = qkv + (size_t)row * (3 * DM) + h * HDIM;
    float q0 = __half2float(base[i]),        q1 = __half2float(base[i + 64]);
    float k0 = __half2float(base[DM + i]),   k1 = __half2float(base[DM + i + 64]);
    float v0 = __half2float(base[2*DM + i]), v1 = __half2float(base[2*DM + i + 64]);
    float invf = powf(10000.0f, -(float)(2 * i) * (1.0f / 128.0f));
    float ang = (float)l * invf;
    float sn, cs;
    sincosf(ang, &sn, &cs);
    size_t ob = ((size_t)((b * NHEAD + h) * SEQ + l)) * HDIM;
    g_q[ob + i]      = tf32r(q0 * cs - q1 * sn);
    g_q[ob + i + 64] = tf32r(q1 * cs + q0 * sn);
    g_k[ob + i]      = tf32r(k0 * cs - k1 * sn);
    g_k[ob + i + 64] = tf32r(k1 * cs + k0 * sn);
    g_v[ob + i]      = tf32r(v0);
    g_v[ob + i + 64] = tf32r(v1);
}

// ---------------- TF32 MMA causal flash attention (O stored half) ------------
// R8-proven version, unchanged.
__global__ __launch_bounds__(128)
void attn_kernel(const float* __restrict__ Q, const float* __restrict__ K,
                 const float* __restrict__ V, __half* __restrict__ O)
{
    extern __shared__ float sm_[];
    float* Qs = sm_;                 // 64*132
    float* Ks = Qs + 64 * 132;
    float* Vs = Ks + 64 * 132;
    float* Ps = Vs + 64 * 132;       // 64*68

    int tid = threadIdx.x;
    int wid = tid >> 5, lane = tid & 31;
    int g = lane >> 2, tig = lane & 3;
    int bh = blockIdx.y;
    int q0 = blockIdx.x * 64;
    const float* Qb = Q + (size_t)bh * SEQ * HDIM;
    const float* Kb = K + (size_t)bh * SEQ * HDIM;
    const float* Vb = V + (size_t)bh * SEQ * HDIM;

    #pragma unroll
    for (int it = 0; it < 16; it++) {
        int idx = it * 128 + tid;
        int r = idx >> 5, c4 = idx & 31;
        *(float4*)&Qs[r * 132 + c4 * 4] =
            *(const float4*)(Qb + (size_t)(q0 + r) * HDIM + c4 * 4);
    }

    const float scale = 0.08838834764831845f;   // 1/sqrt(128)
    float mrow[2] = {-INFINITY, -INFINITY};
    float lrow[2] = {0.f, 0.f};
    float oacc[16][4];
    #pragma unroll
    for (int d = 0; d < 16; d++) {
        oacc[d][0] = 0.f; oacc[d][1] = 0.f; oacc[d][2] = 0.f; oacc[d][3] = 0.f;
    }

    int arow0 = (wid * 16 + g) * 132;
    int arow1 = (wid * 16 + g + 8) * 132;
    int prow0 = (wid * 16 + g) * 68;
    int prow1 = (wid * 16 + g + 8) * 68;
    int qrow0 = q0 + wid * 16 + g;
    int qrow1 = qrow0 + 8;

    for (int n0 = 0; n0 <= q0; n0 += 64) {
        __syncthreads();
        #pragma unroll
        for (int it = 0; it < 16; it++) {
            int idx = it * 128 + tid;
            int r = idx >> 5, c4 = idx & 31;
            *(float4*)&Ks[r * 132 + c4 * 4] =
                *(const float4*)(Kb + (size_t)(n0 + r) * HDIM + c4 * 4);
            *(float4*)&Vs[r * 132 + c4 * 4] =
                *(const float4*)(Vb + (size_t)(n0 + r) * HDIM + c4 * 4);
        }
        __syncthreads();

        float sacc[8][4];
        #pragma unroll
        for (int ni = 0; ni < 8; ni++) {
            sacc[ni][0] = 0.f; sacc[ni][1] = 0.f;
            sacc[ni][2] = 0.f; sacc[ni][3] = 0.f;
        }
        #pragma unroll
        for (int ks = 0; ks < 16; ks++) {
            int kb = ks * 8;
            uint32_t a0 = __float_as_uint(Qs[arow0 + kb + tig]);
            uint32_t a1 = __float_as_uint(Qs[arow1 + kb + tig]);
            uint32_t a2 = __float_as_uint(Qs[arow0 + kb + tig + 4]);
            uint32_t a3 = __float_as_uint(Qs[arow1 + kb + tig + 4]);
            #pragma unroll
            for (int ni = 0; ni < 8; ni++) {
                uint32_t b0 = __float_as_uint(Ks[(ni*8 + g) * 132 + kb + tig]);
                uint32_t b1 = __float_as_uint(Ks[(ni*8 + g) * 132 + kb + tig + 4]);
                MMA_TF32(sacc[ni], a0, a1, a2, a3, b0, b1);
            }
        }

        bool diag = (n0 == q0);
        float tm0 = -INFINITY, tm1 = -INFINITY;
        #pragma unroll
        for (int ni = 0; ni < 8; ni++) {
            int n = n0 + ni * 8 + 2 * tig;
            float s0 = sacc[ni][0] * scale;
            float s1 = sacc[ni][1] * scale;
            float s2 = sacc[ni][2] * scale;
            float s3 = sacc[ni][3] * scale;
            if (diag) {
                if (n     > qrow0) s0 = -INFINITY;
                if (n + 1 > qrow0) s1 = -INFINITY;
                if (n     > qrow1) s2 = -INFINITY;
                if (n + 1 > qrow1) s3 = -INFINITY;
            }
            sacc[ni][0] = s0; sacc[ni][1] = s1;
            sacc[ni][2] = s2; sacc[ni][3] = s3;
            tm0 = fmaxf(tm0, fmaxf(s0, s1));
            tm1 = fmaxf(tm1, fmaxf(s2, s3));
        }
        tm0 = fmaxf(tm0, __shfl_xor_sync(0xffffffffu, tm0, 1));
        tm0 = fmaxf(tm0, __shfl_xor_sync(0xffffffffu, tm0, 2));
        tm1 = fmaxf(tm1, __shfl_xor_sync(0xffffffffu, tm1, 1));
        tm1 = fmaxf(tm1, __shfl_xor_sync(0xffffffffu, tm1, 2));

        float mn0 = fmaxf(mrow[0], tm0), mn1 = fmaxf(mrow[1], tm1);
        float corr0 = expf(mrow[0] - mn0), corr1 = expf(mrow[1] - mn1);
        float ps0 = 0.f, ps1 = 0.f;
        #pragma unroll
        for (int ni = 0; ni < 8; ni++) {
            float p0 = expf(sacc[ni][0] - mn0);
            float p1 = expf(sacc[ni][1] - mn0);
            float p2 = expf(sacc[ni][2] - mn1);
            float p3 = expf(sacc[ni][3] - mn1);
            ps0 += p0 + p1; ps1 += p2 + p3;
            Ps[prow0 + ni*8 + 2*tig    ] = tf32r(p0);
            Ps[prow0 + ni*8 + 2*tig + 1] = tf32r(p1);
            Ps[prow1 + ni*8 + 2*tig    ] = tf32r(p2);
            Ps[prow1 + ni*8 + 2*tig + 1] = tf32r(p3);
        }
        ps0 += __shfl_xor_sync(0xffffffffu, ps0, 1);
        ps0 += __shfl_xor_sync(0xffffffffu, ps0, 2);
        ps1 += __shfl_xor_sync(0xffffffffu, ps1, 1);
        ps1 += __shfl_xor_sync(0xffffffffu, ps1, 2);
        lrow[0] = lrow[0] * corr0 + ps0;
        lrow[1] = lrow[1] * corr1 + ps1;
        mrow[0] = mn0; mrow[1] = mn1;
        #pragma unroll
        for (int d = 0; d < 16; d++) {
            oacc[d][0] *= corr0; oacc[d][1] *= corr0;
            oacc[d][2] *= corr1; oacc[d][3] *= corr1;
        }
        __syncwarp();

        #pragma unroll
        for (int ks = 0; ks < 8; ks++) {
            int kb = ks * 8;
            uint32_t a0 = __float_as_uint(Ps[prow0 + kb + tig]);
            uint32_t a1 = __float_as_uint(Ps[prow1 + kb + tig]);
            uint32_t a2 = __float_as_uint(Ps[prow0 + kb + tig + 4]);
            uint32_t a3 = __float_as_uint(Ps[prow1 + kb + tig + 4]);
            #pragma unroll
            for (int dt = 0; dt < 16; dt++) {
                uint32_t b0 = __float_as_uint(Vs[(kb + tig    ) * 132 + dt*8 + g]);
                uint32_t b1 = __float_as_uint(Vs[(kb + tig + 4) * 132 + dt*8 + g]);
                MMA_TF32(oacc[dt], a0, a1, a2, a3, b0, b1);
            }
        }
        __syncwarp();
    }

    float inv0 = 1.0f / lrow[0], inv1 = 1.0f / lrow[1];
    int b = bh >> 4, h = bh & 15;
    __half* d0 = O + ((size_t)(b * SEQ + qrow0)) * DM + h * HDIM;
    __half* d1 = O + ((size_t)(b * SEQ + qrow1)) * DM + h * HDIM;
    #pragma unroll
    for (int dt = 0; dt < 16; dt++) {
        int col = dt * 8 + 2 * tig;
        __half2 r0 = __floats2half2_rn(oacc[dt][0] * inv0, oacc[dt][1] * inv0);
        __half2 r1 = __floats2half2_rn(oacc[dt][2] * inv1, oacc[dt][3] * inv1);
        *(__half2*)(d0 + col) = r0;
        *(__half2*)(d1 + col) = r1;
    }
}

// ---------------- launch -----------------------------------------------------
extern "C" void kernel_launch(void* const* d_in, const int* in_sizes, int n_in,
                              void* d_out, int out_size)
{
    const float* x    = (const float*)d_in[0];
    const float* Wqkv = (const float*)d_in[1];
    const float* bqkv = (const float*)d_in[2];
    const float* Wo   = (const float*)d_in[3];
    const float* bo   = (const float*)d_in[4];
    const float* g1   = (const float*)d_in[5];
    const float* g2   = (const float*)d_in[6];
    const float* Wp   = (const float*)d_in[7];
    const float* bp   = (const float*)d_in[8];
    const float* Wff  = (const float*)d_in[9];
    const float* bff  = (const float*)d_in[10];
    float* out = (float*)d_out;

    __half *pH, *pQKV, *pO, *pFF, *pW;
    float *pQ, *pK, *pV, *pX1;
    cudaGetSymbolAddress((void**)&pH,   g_h);
    cudaGetSymbolAddress((void**)&pQKV, g_qkv);
    cudaGetSymbolAddress((void**)&pQ,   g_q);
    cudaGetSymbolAddress((void**)&pK,   g_k);
    cudaGetSymbolAddress((void**)&pV,   g_v);
    cudaGetSymbolAddress((void**)&pO,   g_o);
    cudaGetSymbolAddress((void**)&pX1,  g_x1);
    cudaGetSymbolAddress((void**)&pFF,  g_ff);
    cudaGetSymbolAddress((void**)&pW,   g_w);

    __half* wqkv = pW;                       // [6144 x 2048]
    __half* wo   = pW + 12582912;            // [2048 x 2048]
    __half* wp   = pW + 16777216;            // [16384 x 2048] (permuted rows)
    __half* wff  = pW + 50331648;            // [2048 x 8192]

    static constexpr int GEMM_SMEM = 110592;
    static constexpr int ATTN_SMEM = 118784;
    cudaFuncSetAttribute(hgemm_kernel<0>, cudaFuncAttributeMaxDynamicSharedMemorySize, GEMM_SMEM);
    cudaFuncSetAttribute(hgemm_kernel<1>, cudaFuncAttributeMaxDynamicSharedMemorySize, GEMM_SMEM);
    cudaFuncSetAttribute(hgemm_kernel<2>, cudaFuncAttributeMaxDynamicSharedMemorySize, GEMM_SMEM);
    cudaFuncSetAttribute(attn_kernel, cudaFuncAttributeMaxDynamicSharedMemorySize, ATTN_SMEM);

    // 0. convert + transpose weights to half (Wp with swiglu row permutation)
    cvtw_t_kernel<false><<<dim3(6144/32,  2048/32), 256>>>(Wqkv, wqkv, 2048, 6144);
    cvtw_t_kernel<false><<<dim3(2048/32,  2048/32), 256>>>(Wo,   wo,   2048, 2048);
    cvtw_t_kernel<true ><<<dim3(16384/32, 2048/32), 256>>>(Wp,   wp,   2048, 16384);
    cvtw_t_kernel<false><<<dim3(2048/32,  8192/32), 256>>>(Wff,  wff,  8192, 2048);

    // 1. h = rms(x, g1)  (half)
    rmsnorm_kernel<<<NROWS, 256>>>(x, g1, pH);
    // 2. qkv = h @ Wqkv + bqkv  (half out)
    hgemm_kernel<1><<<dim3(6144/128, NROWS/256), 256, GEMM_SMEM>>>(
        pH, wqkv, bqkv, nullptr, pQKV, NROWS, 3*DM, DM);
    // 3. rope + split into Q/K/V (fp32, tf32-rounded)
    rope_split_kernel<<<(NROWS * NHEAD * 64) / 256, 256>>>(pQKV);
    // 4. causal attention -> O (half, tf32 MMA — R8-proven)
    attn_kernel<<<dim3(SEQ/64, 2*NHEAD), 128, ATTN_SMEM>>>(pQ, pK, pV, pO);
    // 5. x1 = O @ Wo + bo + x  (fp32 out, residual)
    hgemm_kernel<0><<<dim3(DM/128, NROWS/256), 256, GEMM_SMEM>>>(
        pO, wo, bo, x, pX1, NROWS, DM, DM);
    // 6. h2 = rms(x1, g2)  (half)
    rmsnorm_kernel<<<NROWS, 256>>>(pX1, g2, pH);
    // 7+8. ff = swiglu(h2 @ Wp + bp)  fused  (half out)
    hgemm_kernel<2><<<dim3(16384/128, NROWS/256), 256, GEMM_SMEM>>>(
        pH, wp, bp, nullptr, pFF, NROWS, 8*DM, DM);
    // 9. out = ff @ Wff_out + bff + x1  (fp32 out, residual)
    hgemm_kernel<0><<<dim3(DM/128, NROWS/256), 256, GEMM_SMEM>>>(
        pFF, wff, bff, pX1, out, NROWS, DM, 4*DM);
}

// round 12
// speedup vs baseline: 6.5627x; 1.0247x over previous
#include <cuda_runtime.h>
#include <cuda_fp16.h>
#include <math.h>
#include <stdint.h>

static constexpr int SEQ   = 2048;
static constexpr int DM    = 2048;
static constexpr int NHEAD = 16;
static constexpr int HDIM  = 128;
static constexpr int NROWS = 4096;   // B * L

// ---------------- scratch (device globals; no allocation allowed) ----------
__device__ __align__(16) __half g_h  [(size_t)NROWS * DM];          // rms out (half)
__device__ __align__(16) __half g_qkv[(size_t)NROWS * 3 * DM];      // qkv (half)
__device__ __align__(16) float  g_q  [(size_t)NROWS * DM];          // rope'd fp32 (tf32)
__device__ __align__(16) float  g_k  [(size_t)NROWS * DM];
__device__ __align__(16) float  g_v  [(size_t)NROWS * DM];
__device__ __align__(16) __half g_o  [(size_t)NROWS * DM];          // attn out (half)
__device__ __align__(16) float  g_x1 [(size_t)NROWS * DM];          // residual fp32
__device__ __align__(16) __half g_ff [(size_t)NROWS * 4 * DM];      // swiglu out (half)
// half TRANSPOSED weights: Wqkv^T | Wo^T | Wp^T(permuted) | Wff^T
__device__ __align__(16) __half g_w  [(size_t)67108864];

__device__ __forceinline__ uint32_t f2tf32(float f) {
    uint32_t u;
    asm("cvt.rna.tf32.f32 %0, %1;" : "=r"(u) : "f"(f));
    return u;
}
__device__ __forceinline__ float tf32r(float f) { return __uint_as_float(f2tf32(f)); }

__device__ __forceinline__ void cp_async16(uint32_t smem, const void* g) {
    asm volatile("cp.async.cg.shared.global [%0], [%1], 16;" :: "r"(smem), "l"(g));
}
__device__ __forceinline__ void cp_commit() {
    asm volatile("cp.async.commit_group;");
}
template<int N> __device__ __forceinline__ void cp_wait() {
    asm volatile("cp.async.wait_group %0;" :: "n"(N));
}

#define MMA_TF32(acc, a0, a1, a2, a3, b0, b1)                                  \
    asm volatile(                                                              \
        "mma.sync.aligned.m16n8k8.row.col.f32.tf32.tf32.f32 "                  \
        "{%0,%1,%2,%3}, {%4,%5,%6,%7}, {%8,%9}, {%0,%1,%2,%3};"                \
        : "+f"(acc[0]), "+f"(acc[1]), "+f"(acc[2]), "+f"(acc[3])               \
        : "r"(a0), "r"(a1), "r"(a2), "r"(a3), "r"(b0), "r"(b1))

#define MMA_F16(acc, a0, a1, a2, a3, b0, b1)                                   \
    asm volatile(                                                              \
        "mma.sync.aligned.m16n8k16.row.col.f32.f16.f16.f32 "                   \
        "{%0,%1,%2,%3}, {%4,%5,%6,%7}, {%8,%9}, {%0,%1,%2,%3};"                \
        : "+f"(acc[0]), "+f"(acc[1]), "+f"(acc[2]), "+f"(acc[3])               \
        : "r"(a0), "r"(a1), "r"(a2), "r"(a3), "r"(b0), "r"(b1))

// ---------------- weight half convert + transpose: Wt[n][k] = W[k][n] --------
// 64(k) x 32(n) tiles: 128B-coalesced loads AND stores, conflict-free smem.
// PERM: swiglu row permutation for Wp (gate/value interleaved per 64-row block)
template<bool PERM>
__global__ __launch_bounds__(256)
void cvtw_t_kernel(const float* __restrict__ W, __half* __restrict__ Wt,
                   int K, int N)
{
    __shared__ float tile[32][65];    // [n][k]
    int tid = threadIdx.x;
    int n0 = blockIdx.x * 32, k0 = blockIdx.y * 64;
    // load 64 x 32 elements: idx = r*32 + c, coalesced along n
    #pragma unroll
    for (int it = 0; it < 8; it++) {
        int idx = it * 256 + tid;
        int r = idx >> 5, c = idx & 31;
        tile[c][r] = W[(size_t)(k0 + r) * N + n0 + c];
    }
    __syncthreads();
    // store: 8 warps x 4 rows each, lane writes half2 at k = 2*lane (128B/row)
    int wid = tid >> 5, lane = tid & 31;
    #pragma unroll
    for (int j = 0; j < 4; j++) {
        int nrow = wid + 8 * j;
        int n = n0 + nrow;
        int r = n;
        if (PERM) {
            int half_n = N >> 1;                 // 8192
            if (n < half_n) r = (n >> 5) * 64 + (n & 31);
            else { int f = n - half_n; r = (f >> 5) * 64 + 32 + (f & 31); }
        }
        float v0 = tile[nrow][2 * lane];
        float v1 = tile[nrow][2 * lane + 1];
        *(__half2*)(Wt + (size_t)r * K + k0 + 2 * lane) = __floats2half2_rn(v0, v1);
    }
}

// ---------------- RMSNorm (half output) --------------------------------------
__global__ __launch_bounds__(256)
void rmsnorm_kernel(const float* __restrict__ x, const float* __restrict__ g,
                    __half* __restrict__ out)
{
    int row = blockIdx.x;
    int tid = threadIdx.x;
    const float4* xr = (const float4*)(x + (size_t)row * DM);
    const float4* gr = (const float4*)g;
    float4 v0 = xr[2*tid], v1 = xr[2*tid + 1];
    float ss = v0.x*v0.x + v0.y*v0.y + v0.z*v0.z + v0.w*v0.w
             + v1.x*v1.x + v1.y*v1.y + v1.z*v1.z + v1.w*v1.w;
    #pragma unroll
    for (int off = 16; off > 0; off >>= 1)
        ss += __shfl_xor_sync(0xffffffffu, ss, off);
    __shared__ float wsum[8];
    if ((tid & 31) == 0) wsum[tid >> 5] = ss;
    __syncthreads();
    float tot = wsum[0]+wsum[1]+wsum[2]+wsum[3]+wsum[4]+wsum[5]+wsum[6]+wsum[7];
    float sc = rsqrtf(tot * (1.0f / (float)DM) + 1e-8f);
    float4 ga = gr[2*tid], gb = gr[2*tid + 1];
    __half2 h0 = __floats2half2_rn(v0.x*sc*ga.x, v0.y*sc*ga.y);
    __half2 h1 = __floats2half2_rn(v0.z*sc*ga.z, v0.w*sc*ga.w);
    __half2 h2 = __floats2half2_rn(v1.x*sc*gb.x, v1.y*sc*gb.y);
    __half2 h3 = __floats2half2_rn(v1.z*sc*gb.z, v1.w*sc*gb.w);
    uint4 pk;
    pk.x = *(uint32_t*)&h0; pk.y = *(uint32_t*)&h1;
    pk.z = *(uint32_t*)&h2; pk.w = *(uint32_t*)&h3;
    ((uint4*)(out + (size_t)row * DM))[tid] = pk;
}

// ---------------- FP16 tensor-core GEMM, cp.async double-buffered ------------
// MODE 0: float out + optional residual; MODE 1: half out; MODE 2: swiglu->half
// 256x128 CTA tile, BK=64, 2-stage, 8 warps (4x2), warp tile 64x64.
template<int MODE>
__global__ __launch_bounds__(256, 1)
void hgemm_kernel(const __half* __restrict__ A, const __half* __restrict__ Bt,
                  const float* __restrict__ bias, const float* __restrict__ res,
                  void* __restrict__ Cv, int M, int N, int K)
{
    extern __shared__ __half hsm[];
    __half* As = hsm;                  // 2 stages x 256 x 72
    __half* Bs = hsm + 36864;          // 2 stages x 128 x 72

    int tid = threadIdx.x;
    int wid = tid >> 5, lane = tid & 31;
    int wm  = wid >> 1;        // 0..3 -> 64 rows
    int wn  = wid & 1;         // 0..1 -> 64 cols
    int g   = lane >> 2;       // 0..7
    int tig = lane & 3;        // 0..3

    const __half* Ab = A  + (size_t)blockIdx.y * 256 * K;
    const __half* Bb = Bt + (size_t)blockIdx.x * 128 * K;

    uint32_t as_base = (uint32_t)__cvta_generic_to_shared(As);
    uint32_t bs_base = (uint32_t)__cvta_generic_to_shared(Bs);

    int arow[8], acol8[8], brow[4], bcol8[4];
    #pragma unroll
    for (int i = 0; i < 8; i++) {
        int c = tid + 256 * i;
        arow[i] = c >> 3; acol8[i] = (c & 7) * 8;
    }
    #pragma unroll
    for (int i = 0; i < 4; i++) {
        int c = tid + 256 * i;
        brow[i] = c >> 3; bcol8[i] = (c & 7) * 8;
    }

    float acc[4][8][4];
    #pragma unroll
    for (int i = 0; i < 4; i++)
        #pragma unroll
        for (int j = 0; j < 8; j++) {
            acc[i][j][0] = 0.f; acc[i][j][1] = 0.f;
            acc[i][j][2] = 0.f; acc[i][j][3] = 0.f;
        }

    const int NT = K >> 6;

    #pragma unroll
    for (int i = 0; i < 8; i++)
        cp_async16(as_base + (uint32_t)((arow[i] * 72 + acol8[i]) * 2),
                   Ab + (size_t)arow[i] * K + acol8[i]);
    #pragma unroll
    for (int i = 0; i < 4; i++)
        cp_async16(bs_base + (uint32_t)((brow[i] * 72 + bcol8[i]) * 2),
                   Bb + (size_t)brow[i] * K + bcol8[i]);
    cp_commit();

    for (int t = 0; t < NT; t++) {
        int buf = t & 1;
        if (t + 1 < NT) {
            int nb = (t + 1) & 1;
            int k0 = (t + 1) * 64;
            uint32_t aoff = as_base + (uint32_t)(nb * 18432 * 2);
            uint32_t boff = bs_base + (uint32_t)(nb * 9216 * 2);
            #pragma unroll
            for (int i = 0; i < 8; i++)
                cp_async16(aoff + (uint32_t)((arow[i] * 72 + acol8[i]) * 2),
                           Ab + (size_t)arow[i] * K + k0 + acol8[i]);
            #pragma unroll
            for (int i = 0; i < 4; i++)
                cp_async16(boff + (uint32_t)((brow[i] * 72 + bcol8[i]) * 2),
                           Bb + (size_t)brow[i] * K + k0 + bcol8[i]);
            cp_commit();
            cp_wait<1>();
        } else {
            cp_wait<0>();
        }
        __syncthreads();

        int abuf = buf * 18432, bbuf = buf * 9216;
        #pragma unroll
        for (int ks = 0; ks < 4; ks++) {
            int kb = ks * 16;
            uint32_t af[4][4], bf[8][2];
            #pragma unroll
            for (int mi = 0; mi < 4; mi++) {
                int row = wm * 64 + mi * 16 + g;
                const __half* r0 = &As[abuf + row * 72 + kb + 2 * tig];
                const __half* r1 = &As[abuf + (row + 8) * 72 + kb + 2 * tig];
                af[mi][0] = *(const uint32_t*)r0;
                af[mi][1] = *(const uint32_t*)r1;
                af[mi][2] = *(const uint32_t*)(r0 + 8);
                af[mi][3] = *(const uint32_t*)(r1 + 8);
            }
            #pragma unroll
            for (int ni = 0; ni < 8; ni++) {
                int col = wn * 64 + ni * 8 + g;
                const __half* b0 = &Bs[bbuf + col * 72 + kb + 2 * tig];
                bf[ni][0] = *(const uint32_t*)b0;
                bf[ni][1] = *(const uint32_t*)(b0 + 8);
            }
            #pragma unroll
            for (int mi = 0; mi < 4; mi++)
                #pragma unroll
                for (int ni = 0; ni < 8; ni++)
                    MMA_F16(acc[mi][ni], af[mi][0], af[mi][1], af[mi][2], af[mi][3],
                            bf[ni][0], bf[ni][1]);
        }
        __syncthreads();
    }

    if (MODE == 2) {
        // swiglu fused: warp block holds [gate f..f+31 | value f..f+31]
        __half* FF = (__half*)Cv;
        int b = blockIdx.x * 2 + wn;
        #pragma unroll
        for (int mi = 0; mi < 4; mi++) {
            int row = blockIdx.y * 256 + wm * 64 + mi * 16 + g;
            #pragma unroll
            for (int ni = 0; ni < 4; ni++) {
                int off = ni * 8 + 2 * tig;
                int f   = b * 32 + off;              // ff column
                float bg0 = bias[f],        bg1 = bias[f + 1];
                float bv0 = bias[8192 + f], bv1 = bias[8192 + f + 1];
                #pragma unroll
                for (int rr = 0; rr < 2; rr++) {
                    float gt0 = acc[mi][ni][2*rr]   + bg0;
                    float gt1 = acc[mi][ni][2*rr+1] + bg1;
                    float vl0 = acc[mi][ni+4][2*rr]   + bv0;
                    float vl1 = acc[mi][ni+4][2*rr+1] + bv1;
                    float r0 = gt0 / (1.0f + expf(-gt0)) * vl0;
                    float r1 = gt1 / (1.0f + expf(-gt1)) * vl1;
                    __half2 h = __floats2half2_rn(r0, r1);
                    *(__half2*)(FF + (size_t)(row + 8*rr) * (4*DM) + f) = h;
                }
            }
        }
    } else {
        #pragma unroll
        for (int mi = 0; mi < 4; mi++) {
            #pragma unroll
            for (int ni = 0; ni < 8; ni++) {
                int row = blockIdx.y * 256 + wm * 64 + mi * 16 + g;
                int col = blockIdx.x * 128 + wn * 64 + ni * 8 + 2 * tig;
                float bx = bias[col], by = bias[col + 1];
                size_t off0 = (size_t)row * N + col;
                size_t off1 = (size_t)(row + 8) * N + col;
                float r0x = acc[mi][ni][0] + bx, r0y = acc[mi][ni][1] + by;
                float r1x = acc[mi][ni][2] + bx, r1y = acc[mi][ni][3] + by;
                if (MODE == 1) {
                    __half* C = (__half*)Cv;
                    *(__half2*)(C + off0) = __floats2half2_rn(r0x, r0y);
                    *(__half2*)(C + off1) = __floats2half2_rn(r1x, r1y);
                } else {
                    float* C = (float*)Cv;
                    if (res) {
                        float2 q0 = *(const float2*)(res + off0);
                        float2 q1 = *(const float2*)(res + off1);
                        r0x += q0.x; r0y += q0.y;
                        r1x += q1.x; r1y += q1.y;
                    }
                    *(float2*)(C + off0) = make_float2(r0x, r0y);
                    *(float2*)(C + off1) = make_float2(r1x, r1y);
                }
            }
        }
    }
}

// ---------------- RoPE + head split: qkv(half) -> Q/K/V fp32 (tf32-rounded) --
__global__ __launch_bounds__(256)
void rope_split_kernel(const __half* __restrict__ qkv)
{
    int idx = blockIdx.x * 256 + threadIdx.x;
    int i   = idx & 63;
    int h   = (idx >> 6) & 15;
    int row = idx >> 10;          // b*SEQ + l
    int l   = row & (SEQ - 1);
    int b   = row >> 11;
    const __half* base = qkv + (size_t)row * (3 * DM) + h * HDIM;
    float q0 = __half2float(base[i]),        q1 = __half2float(base[i + 64]);
    float k0 = __half2float(base[DM + i]),   k1 = __half2float(base[DM + i + 64]);
    float v0 = __half2float(base[2*DM + i]), v1 = __half2float(base[2*DM + i + 64]);
    float invf = powf(10000.0f, -(float)(2 * i) * (1.0f / 128.0f));
    float ang = (float)l * invf;
    float sn, cs;
    sincosf(ang, &sn, &cs);
    size_t ob = ((size_t)((b * NHEAD + h) * SEQ + l)) * HDIM;
    g_q[ob + i]      = tf32r(q0 * cs - q1 * sn);
    g_q[ob + i + 64] = tf32r(q1 * cs + q0 * sn);
    g_k[ob + i]      = tf32r(k0 * cs - k1 * sn);
    g_k[ob + i + 64] = tf32r(k1 * cs + k0 * sn);
    g_v[ob + i]      = tf32r(v0);
    g_v[ob + i + 64] = tf32r(v1);
}

// ---------------- TF32 MMA causal flash attention (O stored half) ------------
// LPT scheduling: blockIdx.x = head, blockIdx.y = REVERSED q-tile (longest first)
__global__ __launch_bounds__(128)
void attn_kernel(const float* __restrict__ Q, const float* __restrict__ K,
                 const float* __restrict__ V, __half* __restrict__ O)
{
    extern __shared__ float sm_[];
    float* Qs = sm_;                 // 64*132
    float* Ks = Qs + 64 * 132;
    float* Vs = Ks + 64 * 132;
    float* Ps = Vs + 64 * 132;       // 64*68

    int tid = threadIdx.x;
    int wid = tid >> 5, lane = tid & 31;
    int g = lane >> 2, tig = lane & 3;
    int bh = blockIdx.x;
    int q0 = (gridDim.y - 1 - blockIdx.y) * 64;    // longest CTAs scheduled first
    const float* Qb = Q + (size_t)bh * SEQ * HDIM;
    const float* Kb = K + (size_t)bh * SEQ * HDIM;
    const float* Vb = V + (size_t)bh * SEQ * HDIM;

    #pragma unroll
    for (int it = 0; it < 16; it++) {
        int idx = it * 128 + tid;
        int r = idx >> 5, c4 = idx & 31;
        *(float4*)&Qs[r * 132 + c4 * 4] =
            *(const float4*)(Qb + (size_t)(q0 + r) * HDIM + c4 * 4);
    }

    const float scale = 0.08838834764831845f;   // 1/sqrt(128)
    float mrow[2] = {-INFINITY, -INFINITY};
    float lrow[2] = {0.f, 0.f};
    float oacc[16][4];
    #pragma unroll
    for (int d = 0; d < 16; d++) {
        oacc[d][0] = 0.f; oacc[d][1] = 0.f; oacc[d][2] = 0.f; oacc[d][3] = 0.f;
    }

    int arow0 = (wid * 16 + g) * 132;
    int arow1 = (wid * 16 + g + 8) * 132;
    int prow0 = (wid * 16 + g) * 68;
    int prow1 = (wid * 16 + g + 8) * 68;
    int qrow0 = q0 + wid * 16 + g;
    int qrow1 = qrow0 + 8;

    for (int n0 = 0; n0 <= q0; n0 += 64) {
        __syncthreads();
        #pragma unroll
        for (int it = 0; it < 16; it++) {
            int idx = it * 128 + tid;
            int r = idx >> 5, c4 = idx & 31;
            *(float4*)&Ks[r * 132 + c4 * 4] =
                *(const float4*)(Kb + (size_t)(n0 + r) * HDIM + c4 * 4);
            *(float4*)&Vs[r * 132 + c4 * 4] =
                *(const float4*)(Vb + (size_t)(n0 + r) * HDIM + c4 * 4);
        }
        __syncthreads();

        float sacc[8][4];
        #pragma unroll
        for (int ni = 0; ni < 8; ni++) {
            sacc[ni][0] = 0.f; sacc[ni][1] = 0.f;
            sacc[ni][2] = 0.f; sacc[ni][3] = 0.f;
        }
        #pragma unroll
        for (int ks = 0; ks < 16; ks++) {
            int kb = ks * 8;
            uint32_t a0 = __float_as_uint(Qs[arow0 + kb + tig]);
            uint32_t a1 = __float_as_uint(Qs[arow1 + kb + tig]);
            uint32_t a2 = __float_as_uint(Qs[arow0 + kb + tig + 4]);
            uint32_t a3 = __float_as_uint(Qs[arow1 + kb + tig + 4]);
            #pragma unroll
            for (int ni = 0; ni < 8; ni++) {
                uint32_t b0 = __float_as_uint(Ks[(ni*8 + g) * 132 + kb + tig]);
                uint32_t b1 = __float_as_uint(Ks[(ni*8 + g) * 132 + kb + tig + 4]);
                MMA_TF32(sacc[ni], a0, a1, a2, a3, b0, b1);
            }
        }

        bool diag = (n0 == q0);
        float tm0 = -INFINITY, tm1 = -INFINITY;
        #pragma unroll
        for (int ni = 0; ni < 8; ni++) {
            int n = n0 + ni * 8 + 2 * tig;
            float s0 = sacc[ni][0] * scale;
            float s1 = sacc[ni][1] * scale;
            float s2 = sacc[ni][2] * scale;
            float s3 = sacc[ni][3] * scale;
            if (diag) {
                if (n     > qrow0) s0 = -INFINITY;
                if (n + 1 > qrow0) s1 = -INFINITY;
                if (n     > qrow1) s2 = -INFINITY;
                if (n + 1 > qrow1) s3 = -INFINITY;
            }
            sacc[ni][0] = s0; sacc[ni][1] = s1;
            sacc[ni][2] = s2; sacc[ni][3] = s3;
            tm0 = fmaxf(tm0, fmaxf(s0, s1));
            tm1 = fmaxf(tm1, fmaxf(s2, s3));
        }
        tm0 = fmaxf(tm0, __shfl_xor_sync(0xffffffffu, tm0, 1));
        tm0 = fmaxf(tm0, __shfl_xor_sync(0xffffffffu, tm0, 2));
        tm1 = fmaxf(tm1, __shfl_xor_sync(0xffffffffu, tm1, 1));
        tm1 = fmaxf(tm1, __shfl_xor_sync(0xffffffffu, tm1, 2));

        float mn0 = fmaxf(mrow[0], tm0), mn1 = fmaxf(mrow[1], tm1);
        float corr0 = expf(mrow[0] - mn0), corr1 = expf(mrow[1] - mn1);
        float ps0 = 0.f, ps1 = 0.f;
        #pragma unroll
        for (int ni = 0; ni < 8; ni++) {
            float p0 = expf(sacc[ni][0] - mn0);
            float p1 = expf(sacc[ni][1] - mn0);
            float p2 = expf(sacc[ni][2] - mn1);
            float p3 = expf(sacc[ni][3] - mn1);
            ps0 += p0 + p1; ps1 += p2 + p3;
            Ps[prow0 + ni*8 + 2*tig    ] = tf32r(p0);
            Ps[prow0 + ni*8 + 2*tig + 1] = tf32r(p1);
            Ps[prow1 + ni*8 + 2*tig    ] = tf32r(p2);
            Ps[prow1 + ni*8 + 2*tig + 1] = tf32r(p3);
        }
        ps0 += __shfl_xor_sync(0xffffffffu, ps0, 1);
        ps0 += __shfl_xor_sync(0xffffffffu, ps0, 2);
        ps1 += __shfl_xor_sync(0xffffffffu, ps1, 1);
        ps1 += __shfl_xor_sync(0xffffffffu, ps1, 2);
        lrow[0] = lrow[0] * corr0 + ps0;
        lrow[1] = lrow[1] * corr1 + ps1;
        mrow[0] = mn0; mrow[1] = mn1;
        #pragma unroll
        for (int d = 0; d < 16; d++) {
            oacc[d][0] *= corr0; oacc[d][1] *= corr0;
            oacc[d][2] *= corr1; oacc[d][3] *= corr1;
        }
        __syncwarp();

        #pragma unroll
        for (int ks = 0; ks < 8; ks++) {
            int kb = ks * 8;
            uint32_t a0 = __float_as_uint(Ps[prow0 + kb + tig]);
            uint32_t a1 = __float_as_uint(Ps[prow1 + kb + tig]);
            uint32_t a2 = __float_as_uint(Ps[prow0 + kb + tig + 4]);
            uint32_t a3 = __float_as_uint(Ps[prow1 + kb + tig + 4]);
            #pragma unroll
            for (int dt = 0; dt < 16; dt++) {
                uint32_t b0 = __float_as_uint(Vs[(kb + tig    ) * 132 + dt*8 + g]);
                uint32_t b1 = __float_as_uint(Vs[(kb + tig + 4) * 132 + dt*8 + g]);
                MMA_TF32(oacc[dt], a0, a1, a2, a3, b0, b1);
            }
        }
        __syncwarp();
    }

    float inv0 = 1.0f / lrow[0], inv1 = 1.0f / lrow[1];
    int b = bh >> 4, h = bh & 15;
    __half* d0 = O + ((size_t)(b * SEQ + qrow0)) * DM + h * HDIM;
    __half* d1 = O + ((size_t)(b * SEQ + qrow1)) * DM + h * HDIM;
    #pragma unroll
    for (int dt = 0; dt < 16; dt++) {
        int col = dt * 8 + 2 * tig;
        __half2 r0 = __floats2half2_rn(oacc[dt][0] * inv0, oacc[dt][1] * inv0);
        __half2 r1 = __floats2half2_rn(oacc[dt][2] * inv1, oacc[dt][3] * inv1);
        *(__half2*)(d0 + col) = r0;
        *(__half2*)(d1 + col) = r1;
    }
}

// ---------------- launch -----------------------------------------------------
extern "C" void kernel_launch(void* const* d_in, const int* in_sizes, int n_in,
                              void* d_out, int out_size)
{
    const float* x    = (const float*)d_in[0];
    const float* Wqkv = (const float*)d_in[1];
    const float* bqkv = (const float*)d_in[2];
    const float* Wo   = (const float*)d_in[3];
    const float* bo   = (const float*)d_in[4];
    const float* g1   = (const float*)d_in[5];
    const float* g2   = (const float*)d_in[6];
    const float* Wp   = (const float*)d_in[7];
    const float* bp   = (const float*)d_in[8];
    const float* Wff  = (const float*)d_in[9];
    const float* bff  = (const float*)d_in[10];
    float* out = (float*)d_out;

    __half *pH, *pQKV, *pO, *pFF, *pW;
    float *pQ, *pK, *pV, *pX1;
    cudaGetSymbolAddress((void**)&pH,   g_h);
    cudaGetSymbolAddress((void**)&pQKV, g_qkv);
    cudaGetSymbolAddress((void**)&pQ,   g_q);
    cudaGetSymbolAddress((void**)&pK,   g_k);
    cudaGetSymbolAddress((void**)&pV,   g_v);
    cudaGetSymbolAddress((void**)&pO,   g_o);
    cudaGetSymbolAddress((void**)&pX1,  g_x1);
    cudaGetSymbolAddress((void**)&pFF,  g_ff);
    cudaGetSymbolAddress((void**)&pW,   g_w);

    __half* wqkv = pW;                       // [6144 x 2048]
    __half* wo   = pW + 12582912;            // [2048 x 2048]
    __half* wp   = pW + 16777216;            // [16384 x 2048] (permuted rows)
    __half* wff  = pW + 50331648;            // [2048 x 8192]

    static constexpr int GEMM_SMEM = 110592;
    static constexpr int ATTN_SMEM = 118784;
    cudaFuncSetAttribute(hgemm_kernel<0>, cudaFuncAttributeMaxDynamicSharedMemorySize, GEMM_SMEM);
    cudaFuncSetAttribute(hgemm_kernel<1>, cudaFuncAttributeMaxDynamicSharedMemorySize, GEMM_SMEM);
    cudaFuncSetAttribute(hgemm_kernel<2>, cudaFuncAttributeMaxDynamicSharedMemorySize, GEMM_SMEM);
    cudaFuncSetAttribute(attn_kernel, cudaFuncAttributeMaxDynamicSharedMemorySize, ATTN_SMEM);

    // 0. convert + transpose weights to half (Wp with swiglu row permutation)
    cvtw_t_kernel<false><<<dim3(6144/32,  2048/64), 256>>>(Wqkv, wqkv, 2048, 6144);
    cvtw_t_kernel<false><<<dim3(2048/32,  2048/64), 256>>>(Wo,   wo,   2048, 2048);
    cvtw_t_kernel<true ><<<dim3(16384/32, 2048/64), 256>>>(Wp,   wp,   2048, 16384);
    cvtw_t_kernel<false><<<dim3(2048/32,  8192/64), 256>>>(Wff,  wff,  8192, 2048);

    // 1. h = rms(x, g1)  (half)
    rmsnorm_kernel<<<NROWS, 256>>>(x, g1, pH);
    // 2. qkv = h @ Wqkv + bqkv  (half out)
    hgemm_kernel<1><<<dim3(6144/128, NROWS/256), 256, GEMM_SMEM>>>(
        pH, wqkv, bqkv, nullptr, pQKV, NROWS, 3*DM, DM);
    // 3. rope + split into Q/K/V (fp32, tf32-rounded)
    rope_split_kernel<<<(NROWS * NHEAD * 64) / 256, 256>>>(pQKV);
    // 4. causal attention -> O (half, tf32 MMA, LPT order)
    attn_kernel<<<dim3(2*NHEAD, SEQ/64), 128, ATTN_SMEM>>>(pQ, pK, pV, pO);
    // 5. x1 = O @ Wo + bo + x  (fp32 out, residual)
    hgemm_kernel<0><<<dim3(DM/128, NROWS/256), 256, GEMM_SMEM>>>(
        pO, wo, bo, x, pX1, NROWS, DM, DM);
    // 6. h2 = rms(x1, g2)  (half)
    rmsnorm_kernel<<<NROWS, 256>>>(pX1, g2, pH);
    // 7+8. ff = swiglu(h2 @ Wp + bp)  fused  (half out)
    hgemm_kernel<2><<<dim3(16384/128, NROWS/256), 256, GEMM_SMEM>>>(
        pH, wp, bp, nullptr, pFF, NROWS, 8*DM, DM);
    // 9. out = ff @ Wff_out + bff + x1  (fp32 out, residual)
    hgemm_kernel<0><<<dim3(DM/128, NROWS/256), 256, GEMM_SMEM>>>(
        pFF, wff, bff, pX1, out, NROWS, DM, 4*DM);
}

// round 13
// speedup vs baseline: 7.3350x; 1.1177x over previous
#include <cuda_runtime.h>
#include <cuda_fp16.h>
#include <math.h>
#include <stdint.h>

static constexpr int SEQ   = 2048;
static constexpr int DM    = 2048;
static constexpr int NHEAD = 16;
static constexpr int HDIM  = 128;
static constexpr int NROWS = 4096;   // B * L

// ---------------- scratch (device globals; no allocation allowed) ----------
__device__ __align__(16) __half g_h  [(size_t)NROWS * DM];          // rms out (half)
__device__ __align__(16) __half g_qkv[(size_t)NROWS * 3 * DM];      // qkv (half)
__device__ __align__(16) __half g_q  [(size_t)NROWS * DM];          // rope'd half
__device__ __align__(16) __half g_k  [(size_t)NROWS * DM];
__device__ __align__(16) __half g_v  [(size_t)NROWS * DM];
__device__ __align__(16) __half g_o  [(size_t)NROWS * DM];          // attn out (half)
__device__ __align__(16) float  g_x1 [(size_t)NROWS * DM];          // residual fp32
__device__ __align__(16) __half g_ff [(size_t)NROWS * 4 * DM];      // swiglu out (half)
// half TRANSPOSED weights: Wqkv^T | Wo^T | Wp^T(permuted) | Wff^T
__device__ __align__(16) __half g_w  [(size_t)67108864];

__device__ __forceinline__ void cp_async16(uint32_t smem, const void* g) {
    asm volatile("cp.async.cg.shared.global [%0], [%1], 16;" :: "r"(smem), "l"(g));
}
__device__ __forceinline__ void cp_commit() {
    asm volatile("cp.async.commit_group;");
}
template<int N> __device__ __forceinline__ void cp_wait() {
    asm volatile("cp.async.wait_group %0;" :: "n"(N));
}

#define MMA_F16(acc, a0, a1, a2, a3, b0, b1)                                   \
    asm volatile(                                                              \
        "mma.sync.aligned.m16n8k16.row.col.f32.f16.f16.f32 "                   \
        "{%0,%1,%2,%3}, {%4,%5,%6,%7}, {%8,%9}, {%0,%1,%2,%3};"                \
        : "+f"(acc[0]), "+f"(acc[1]), "+f"(acc[2]), "+f"(acc[3])               \
        : "r"(a0), "r"(a1), "r"(a2), "r"(a3), "r"(b0), "r"(b1))

// ---------------- weight half convert + transpose: Wt[n][k] = W[k][n] --------
// 64(k) x 32(n) tiles: 128B-coalesced loads AND stores, conflict-free smem.
// PERM: swiglu row permutation for Wp (gate/value interleaved per 64-row block)
template<bool PERM>
__global__ __launch_bounds__(256)
void cvtw_t_kernel(const float* __restrict__ W, __half* __restrict__ Wt,
                   int K, int N)
{
    __shared__ float tile[32][65];    // [n][k]
    int tid = threadIdx.x;
    int n0 = blockIdx.x * 32, k0 = blockIdx.y * 64;
    #pragma unroll
    for (int it = 0; it < 8; it++) {
        int idx = it * 256 + tid;
        int r = idx >> 5, c = idx & 31;
        tile[c][r] = W[(size_t)(k0 + r) * N + n0 + c];
    }
    __syncthreads();
    int wid = tid >> 5, lane = tid & 31;
    #pragma unroll
    for (int j = 0; j < 4; j++) {
        int nrow = wid + 8 * j;
        int n = n0 + nrow;
        int r = n;
        if (PERM) {
            int half_n = N >> 1;                 // 8192
            if (n < half_n) r = (n >> 5) * 64 + (n & 31);
            else { int f = n - half_n; r = (f >> 5) * 64 + 32 + (f & 31); }
        }
        float v0 = tile[nrow][2 * lane];
        float v1 = tile[nrow][2 * lane + 1];
        *(__half2*)(Wt + (size_t)r * K + k0 + 2 * lane) = __floats2half2_rn(v0, v1);
    }
}

// ---------------- RMSNorm (half output) --------------------------------------
__global__ __launch_bounds__(256)
void rmsnorm_kernel(const float* __restrict__ x, const float* __restrict__ g,
                    __half* __restrict__ out)
{
    int row = blockIdx.x;
    int tid = threadIdx.x;
    const float4* xr = (const float4*)(x + (size_t)row * DM);
    const float4* gr = (const float4*)g;
    float4 v0 = xr[2*tid], v1 = xr[2*tid + 1];
    float ss = v0.x*v0.x + v0.y*v0.y + v0.z*v0.z + v0.w*v0.w
             + v1.x*v1.x + v1.y*v1.y + v1.z*v1.z + v1.w*v1.w;
    #pragma unroll
    for (int off = 16; off > 0; off >>= 1)
        ss += __shfl_xor_sync(0xffffffffu, ss, off);
    __shared__ float wsum[8];
    if ((tid & 31) == 0) wsum[tid >> 5] = ss;
    __syncthreads();
    float tot = wsum[0]+wsum[1]+wsum[2]+wsum[3]+wsum[4]+wsum[5]+wsum[6]+wsum[7];
    float sc = rsqrtf(tot * (1.0f / (float)DM) + 1e-8f);
    float4 ga = gr[2*tid], gb = gr[2*tid + 1];
    __half2 h0 = __floats2half2_rn(v0.x*sc*ga.x, v0.y*sc*ga.y);
    __half2 h1 = __floats2half2_rn(v0.z*sc*ga.z, v0.w*sc*ga.w);
    __half2 h2 = __floats2half2_rn(v1.x*sc*gb.x, v1.y*sc*gb.y);
    __half2 h3 = __floats2half2_rn(v1.z*sc*gb.z, v1.w*sc*gb.w);
    uint4 pk;
    pk.x = *(uint32_t*)&h0; pk.y = *(uint32_t*)&h1;
    pk.z = *(uint32_t*)&h2; pk.w = *(uint32_t*)&h3;
    ((uint4*)(out + (size_t)row * DM))[tid] = pk;
}

// ---------------- FP16 tensor-core GEMM, cp.async double-buffered ------------
// MODE 0: float out + optional residual; MODE 1: half out; MODE 2: swiglu->half
// 256x128 CTA tile, BK=64, 2-stage, 8 warps (4x2), warp tile 64x64.
template<int MODE>
__global__ __launch_bounds__(256, 1)
void hgemm_kernel(const __half* __restrict__ A, const __half* __restrict__ Bt,
                  const float* __restrict__ bias, const float* __restrict__ res,
                  void* __restrict__ Cv, int M, int N, int K)
{
    extern __shared__ __half hsm[];
    __half* As = hsm;                  // 2 stages x 256 x 72
    __half* Bs = hsm + 36864;          // 2 stages x 128 x 72

    int tid = threadIdx.x;
    int wid = tid >> 5, lane = tid & 31;
    int wm  = wid >> 1;        // 0..3 -> 64 rows
    int wn  = wid & 1;         // 0..1 -> 64 cols
    int g   = lane >> 2;       // 0..7
    int tig = lane & 3;        // 0..3

    const __half* Ab = A  + (size_t)blockIdx.y * 256 * K;
    const __half* Bb = Bt + (size_t)blockIdx.x * 128 * K;

    uint32_t as_base = (uint32_t)__cvta_generic_to_shared(As);
    uint32_t bs_base = (uint32_t)__cvta_generic_to_shared(Bs);

    int arow[8], acol8[8], brow[4], bcol8[4];
    #pragma unroll
    for (int i = 0; i < 8; i++) {
        int c = tid + 256 * i;
        arow[i] = c >> 3; acol8[i] = (c & 7) * 8;
    }
    #pragma unroll
    for (int i = 0; i < 4; i++) {
        int c = tid + 256 * i;
        brow[i] = c >> 3; bcol8[i] = (c & 7) * 8;
    }

    float acc[4][8][4];
    #pragma unroll
    for (int i = 0; i < 4; i++)
        #pragma unroll
        for (int j = 0; j < 8; j++) {
            acc[i][j][0] = 0.f; acc[i][j][1] = 0.f;
            acc[i][j][2] = 0.f; acc[i][j][3] = 0.f;
        }

    const int NT = K >> 6;

    #pragma unroll
    for (int i = 0; i < 8; i++)
        cp_async16(as_base + (uint32_t)((arow[i] * 72 + acol8[i]) * 2),
                   Ab + (size_t)arow[i] * K + acol8[i]);
    #pragma unroll
    for (int i = 0; i < 4; i++)
        cp_async16(bs_base + (uint32_t)((brow[i] * 72 + bcol8[i]) * 2),
                   Bb + (size_t)brow[i] * K + bcol8[i]);
    cp_commit();

    for (int t = 0; t < NT; t++) {
        int buf = t & 1;
        if (t + 1 < NT) {
            int nb = (t + 1) & 1;
            int k0 = (t + 1) * 64;
            uint32_t aoff = as_base + (uint32_t)(nb * 18432 * 2);
            uint32_t boff = bs_base + (uint32_t)(nb * 9216 * 2);
            #pragma unroll
            for (int i = 0; i < 8; i++)
                cp_async16(aoff + (uint32_t)((arow[i] * 72 + acol8[i]) * 2),
                           Ab + (size_t)arow[i] * K + k0 + acol8[i]);
            #pragma unroll
            for (int i = 0; i < 4; i++)
                cp_async16(boff + (uint32_t)((brow[i] * 72 + bcol8[i]) * 2),
                           Bb + (size_t)brow[i] * K + k0 + bcol8[i]);
            cp_commit();
            cp_wait<1>();
        } else {
            cp_wait<0>();
        }
        __syncthreads();

        int abuf = buf * 18432, bbuf = buf * 9216;
        #pragma unroll
        for (int ks = 0; ks < 4; ks++) {
            int kb = ks * 16;
            uint32_t af[4][4], bf[8][2];
            #pragma unroll
            for (int mi = 0; mi < 4; mi++) {
                int row = wm * 64 + mi * 16 + g;
                const __half* r0 = &As[abuf + row * 72 + kb + 2 * tig];
                const __half* r1 = &As[abuf + (row + 8) * 72 + kb + 2 * tig];
                af[mi][0] = *(const uint32_t*)r0;
                af[mi][1] = *(const uint32_t*)r1;
                af[mi][2] = *(const uint32_t*)(r0 + 8);
                af[mi][3] = *(const uint32_t*)(r1 + 8);
            }
            #pragma unroll
            for (int ni = 0; ni < 8; ni++) {
                int col = wn * 64 + ni * 8 + g;
                const __half* b0 = &Bs[bbuf + col * 72 + kb + 2 * tig];
                bf[ni][0] = *(const uint32_t*)b0;
                bf[ni][1] = *(const uint32_t*)(b0 + 8);
            }
            #pragma unroll
            for (int mi = 0; mi < 4; mi++)
                #pragma unroll
                for (int ni = 0; ni < 8; ni++)
                    MMA_F16(acc[mi][ni], af[mi][0], af[mi][1], af[mi][2], af[mi][3],
                            bf[ni][0], bf[ni][1]);
        }
        __syncthreads();
    }

    if (MODE == 2) {
        // swiglu fused: warp block holds [gate f..f+31 | value f..f+31]
        __half* FF = (__half*)Cv;
        int b = blockIdx.x * 2 + wn;
        #pragma unroll
        for (int mi = 0; mi < 4; mi++) {
            int row = blockIdx.y * 256 + wm * 64 + mi * 16 + g;
            #pragma unroll
            for (int ni = 0; ni < 4; ni++) {
                int off = ni * 8 + 2 * tig;
                int f   = b * 32 + off;              // ff column
                float bg0 = bias[f],        bg1 = bias[f + 1];
                float bv0 = bias[8192 + f], bv1 = bias[8192 + f + 1];
                #pragma unroll
                for (int rr = 0; rr < 2; rr++) {
                    float gt0 = acc[mi][ni][2*rr]   + bg0;
                    float gt1 = acc[mi][ni][2*rr+1] + bg1;
                    float vl0 = acc[mi][ni+4][2*rr]   + bv0;
                    float vl1 = acc[mi][ni+4][2*rr+1] + bv1;
                    float r0 = gt0 / (1.0f + expf(-gt0)) * vl0;
                    float r1 = gt1 / (1.0f + expf(-gt1)) * vl1;
                    __half2 h = __floats2half2_rn(r0, r1);
                    *(__half2*)(FF + (size_t)(row + 8*rr) * (4*DM) + f) = h;
                }
            }
        }
    } else {
        #pragma unroll
        for (int mi = 0; mi < 4; mi++) {
            #pragma unroll
            for (int ni = 0; ni < 8; ni++) {
                int row = blockIdx.y * 256 + wm * 64 + mi * 16 + g;
                int col = blockIdx.x * 128 + wn * 64 + ni * 8 + 2 * tig;
                float bx = bias[col], by = bias[col + 1];
                size_t off0 = (size_t)row * N + col;
                size_t off1 = (size_t)(row + 8) * N + col;
                float r0x = acc[mi][ni][0] + bx, r0y = acc[mi][ni][1] + by;
                float r1x = acc[mi][ni][2] + bx, r1y = acc[mi][ni][3] + by;
                if (MODE == 1) {
                    __half* C = (__half*)Cv;
                    *(__half2*)(C + off0) = __floats2half2_rn(r0x, r0y);
                    *(__half2*)(C + off1) = __floats2half2_rn(r1x, r1y);
                } else {
                    float* C = (float*)Cv;
                    if (res) {
                        float2 q0 = *(const float2*)(res + off0);
                        float2 q1 = *(const float2*)(res + off1);
                        r0x += q0.x; r0y += q0.y;
                        r1x += q1.x; r1y += q1.y;
                    }
                    *(float2*)(C + off0) = make_float2(r0x, r0y);
                    *(float2*)(C + off1) = make_float2(r1x, r1y);
                }
            }
        }
    }
}

// ---------------- RoPE + head split: qkv(half) -> Q/K/V half -----------------
__global__ __launch_bounds__(256)
void rope_split_kernel(const __half* __restrict__ qkv)
{
    int idx = blockIdx.x * 256 + threadIdx.x;
    int i   = idx & 63;
    int h   = (idx >> 6) & 15;
    int row = idx >> 10;          // b*SEQ + l
    int l   = row & (SEQ - 1);
    int b   = row >> 11;
    const __half* base = qkv + (size_t)row * (3 * DM) + h * HDIM;
    float q0 = __half2float(base[i]),        q1 = __half2float(base[i + 64]);
    float k0 = __half2float(base[DM + i]),   k1 = __half2float(base[DM + i + 64]);
    float invf = powf(10000.0f, -(float)(2 * i) * (1.0f / 128.0f));
    float ang = (float)l * invf;
    float sn, cs;
    sincosf(ang, &sn, &cs);
    size_t ob = ((size_t)((b * NHEAD + h) * SEQ + l)) * HDIM;
    g_q[ob + i]      = __float2half(q0 * cs - q1 * sn);
    g_q[ob + i + 64] = __float2half(q1 * cs + q0 * sn);
    g_k[ob + i]      = __float2half(k0 * cs - k1 * sn);
    g_k[ob + i + 64] = __float2half(k1 * cs + k0 * sn);
    g_v[ob + i]      = base[2*DM + i];
    g_v[ob + i + 64] = base[2*DM + i + 64];
}

// ---------------- FP16 MMA causal flash attention (no ldmatrix) --------------
// 4 warps, 64 queries/CTA, key tiles of 64. V transposed into smem at load time
// (Vt[d][key], stride 72, key-XOR swizzle) so PV B-frags are plain LDS.32.
// Smem (half): Qs[64][136] + Ks[64][136] + Vt[128][72] + Ps[64][72] = 62,464 B.
// LPT: blockIdx.x = head, blockIdx.y = reversed q-tile.
__global__ __launch_bounds__(128)
void attn_kernel(const __half* __restrict__ Q, const __half* __restrict__ K,
                 const __half* __restrict__ V, __half* __restrict__ O)
{
    extern __shared__ __half hsm_[];
    __half* Qs = hsm_;               // 64*136
    __half* Ks = Qs + 64 * 136;
    __half* Vt = Ks + 64 * 136;      // 128*72 (transposed, swizzled)
    __half* Ps = Vt + 128 * 72;      // 64*72

    int tid = threadIdx.x;
    int wid = tid >> 5, lane = tid & 31;
    int g = lane >> 2, tig = lane & 3;
    int bh = blockIdx.x;
    int q0 = (gridDim.y - 1 - blockIdx.y) * 64;    // longest CTAs first
    const __half* Qb = Q + (size_t)bh * SEQ * HDIM;
    const __half* Kb = K + (size_t)bh * SEQ * HDIM;
    const __half* Vb = V + (size_t)bh * SEQ * HDIM;

    // load Q tile: 64 rows x 128 halves
    #pragma unroll
    for (int it = 0; it < 8; it++) {
        int idx = it * 128 + tid;
        int r = idx >> 4, c8 = idx & 15;
        *(uint4*)&Qs[r * 136 + c8 * 8] =
            *(const uint4*)(Qb + (size_t)(q0 + r) * HDIM + c8 * 8);
    }

    const float scale = 0.08838834764831845f;   // 1/sqrt(128)
    float mrow[2] = {-INFINITY, -INFINITY};
    float lrow[2] = {0.f, 0.f};
    float oacc[16][4];
    #pragma unroll
    for (int d = 0; d < 16; d++) {
        oacc[d][0] = 0.f; oacc[d][1] = 0.f; oacc[d][2] = 0.f; oacc[d][3] = 0.f;
    }

    int arow0 = (wid * 16 + g) * 136;
    int arow1 = (wid * 16 + g + 8) * 136;
    int prow0 = (wid * 16 + g) * 72;
    int prow1 = (wid * 16 + g + 8) * 72;
    int qrow0 = q0 + wid * 16 + g;
    int qrow1 = qrow0 + 8;

    for (int n0 = 0; n0 <= q0; n0 += 64) {
        __syncthreads();
        #pragma unroll
        for (int it = 0; it < 8; it++) {
            int idx = it * 128 + tid;
            int r = idx >> 4, c8 = idx & 15;
            *(uint4*)&Ks[r * 136 + c8 * 8] =
                *(const uint4*)(Kb + (size_t)(n0 + r) * HDIM + c8 * 8);
            // V: load row chunk, scatter transposed into Vt with key swizzle
            uint4 vv4 = *(const uint4*)(Vb + (size_t)(n0 + r) * HDIM + c8 * 8);
            const __half* vv = (const __half*)&vv4;
            int kcol = r ^ ((c8 & 7) * 8);
            #pragma unroll
            for (int j = 0; j < 8; j++)
                Vt[(c8 * 8 + j) * 72 + kcol] = vv[j];
        }
        __syncthreads();

        // ---- S = Q K^T (16 x 64 per warp), fp16 MMA k16 ----
        float sacc[8][4];
        #pragma unroll
        for (int ni = 0; ni < 8; ni++) {
            sacc[ni][0] = 0.f; sacc[ni][1] = 0.f;
            sacc[ni][2] = 0.f; sacc[ni][3] = 0.f;
        }
        #pragma unroll
        for (int kc = 0; kc < 8; kc++) {
            int kb = kc * 16;
            uint32_t a0 = *(const uint32_t*)&Qs[arow0 + kb + 2*tig];
            uint32_t a1 = *(const uint32_t*)&Qs[arow1 + kb + 2*tig];
            uint32_t a2 = *(const uint32_t*)&Qs[arow0 + kb + 8 + 2*tig];
            uint32_t a3 = *(const uint32_t*)&Qs[arow1 + kb + 8 + 2*tig];
            #pragma unroll
            for (int ni = 0; ni < 8; ni++) {
                const __half* bp = &Ks[(ni*8 + g) * 136 + kb + 2*tig];
                uint32_t b0 = *(const uint32_t*)bp;
                uint32_t b1 = *(const uint32_t*)(bp + 8);
                MMA_F16(sacc[ni], a0, a1, a2, a3, b0, b1);
            }
        }

        // ---- online softmax (fp32) ----
        bool diag = (n0 == q0);
        float tm0 = -INFINITY, tm1 = -INFINITY;
        #pragma unroll
        for (int ni = 0; ni < 8; ni++) {
            int n = n0 + ni * 8 + 2 * tig;
            float s0 = sacc[ni][0] * scale;
            float s1 = sacc[ni][1] * scale;
            float s2 = sacc[ni][2] * scale;
            float s3 = sacc[ni][3] * scale;
            if (diag) {
                if (n     > qrow0) s0 = -INFINITY;
                if (n + 1 > qrow0) s1 = -INFINITY;
                if (n     > qrow1) s2 = -INFINITY;
                if (n + 1 > qrow1) s3 = -INFINITY;
            }
            sacc[ni][0] = s0; sacc[ni][1] = s1;
            sacc[ni][2] = s2; sacc[ni][3] = s3;
            tm0 = fmaxf(tm0, fmaxf(s0, s1));
            tm1 = fmaxf(tm1, fmaxf(s2, s3));
        }
        tm0 = fmaxf(tm0, __shfl_xor_sync(0xffffffffu, tm0, 1));
        tm0 = fmaxf(tm0, __shfl_xor_sync(0xffffffffu, tm0, 2));
        tm1 = fmaxf(tm1, __shfl_xor_sync(0xffffffffu, tm1, 1));
        tm1 = fmaxf(tm1, __shfl_xor_sync(0xffffffffu, tm1, 2));

        float mn0 = fmaxf(mrow[0], tm0), mn1 = fmaxf(mrow[1], tm1);
        float corr0 = expf(mrow[0] - mn0), corr1 = expf(mrow[1] - mn1);
        float ps0 = 0.f, ps1 = 0.f;
        #pragma unroll
        for (int ni = 0; ni < 8; ni++) {
            float p0 = expf(sacc[ni][0] - mn0);
            float p1 = expf(sacc[ni][1] - mn0);
            float p2 = expf(sacc[ni][2] - mn1);
            float p3 = expf(sacc[ni][3] - mn1);
            ps0 += p0 + p1; ps1 += p2 + p3;
            *(__half2*)&Ps[prow0 + ni*8 + 2*tig] = __floats2half2_rn(p0, p1);
            *(__half2*)&Ps[prow1 + ni*8 + 2*tig] = __floats2half2_rn(p2, p3);
        }
        ps0 += __shfl_xor_sync(0xffffffffu, ps0, 1);
        ps0 += __shfl_xor_sync(0xffffffffu, ps0, 2);
        ps1 += __shfl_xor_sync(0xffffffffu, ps1, 1);
        ps1 += __shfl_xor_sync(0xffffffffu, ps1, 2);
        lrow[0] = lrow[0] * corr0 + ps0;
        lrow[1] = lrow[1] * corr1 + ps1;
        mrow[0] = mn0; mrow[1] = mn1;
        #pragma unroll
        for (int d = 0; d < 16; d++) {
            oacc[d][0] *= corr0; oacc[d][1] *= corr0;
            oacc[d][2] *= corr1; oacc[d][3] *= corr1;
        }
        __syncwarp();

        // ---- O += P V  via Vt (plain LDS.32 B-frags, conflict-free) ----
        #pragma unroll
        for (int kc = 0; kc < 4; kc++) {
            int kb = kc * 16;
            uint32_t a0 = *(const uint32_t*)&Ps[prow0 + kb + 2*tig];
            uint32_t a1 = *(const uint32_t*)&Ps[prow1 + kb + 2*tig];
            uint32_t a2 = *(const uint32_t*)&Ps[prow0 + kb + 8 + 2*tig];
            uint32_t a3 = *(const uint32_t*)&Ps[prow1 + kb + 8 + 2*tig];
            #pragma unroll
            for (int dt = 0; dt < 16; dt++) {
                int swz = (dt & 7) * 8;
                const __half* vrow = &Vt[(dt * 8 + g) * 72];
                uint32_t b0 = *(const uint32_t*)&vrow[(kb + 2*tig)     ^ swz];
                uint32_t b1 = *(const uint32_t*)&vrow[(kb + 2*tig + 8) ^ swz];
                MMA_F16(oacc[dt], a0, a1, a2, a3, b0, b1);
            }
        }
        __syncwarp();
    }

    float inv0 = 1.0f / lrow[0], inv1 = 1.0f / lrow[1];
    int b = bh >> 4, h = bh & 15;
    __half* d0 = O + ((size_t)(b * SEQ + qrow0)) * DM + h * HDIM;
    __half* d1 = O + ((size_t)(b * SEQ + qrow1)) * DM + h * HDIM;
    #pragma unroll
    for (int dt = 0; dt < 16; dt++) {
        int col = dt * 8 + 2 * tig;
        *(__half2*)(d0 + col) = __floats2half2_rn(oacc[dt][0]*inv0, oacc[dt][1]*inv0);
        *(__half2*)(d1 + col) = __floats2half2_rn(oacc[dt][2]*inv1, oacc[dt][3]*inv1);
    }
}

// ---------------- launch -----------------------------------------------------
extern "C" void kernel_launch(void* const* d_in, const int* in_sizes, int n_in,
                              void* d_out, int out_size)
{
    const float* x    = (const float*)d_in[0];
    const float* Wqkv = (const float*)d_in[1];
    const float* bqkv = (const float*)d_in[2];
    const float* Wo   = (const float*)d_in[3];
    const float* bo   = (const float*)d_in[4];
    const float* g1   = (const float*)d_in[5];
    const float* g2   = (const float*)d_in[6];
    const float* Wp   = (const float*)d_in[7];
    const float* bp   = (const float*)d_in[8];
    const float* Wff  = (const float*)d_in[9];
    const float* bff  = (const float*)d_in[10];
    float* out = (float*)d_out;

    __half *pH, *pQKV, *pQ, *pK, *pV, *pO, *pFF, *pW;
    float *pX1;
    cudaGetSymbolAddress((void**)&pH,   g_h);
    cudaGetSymbolAddress((void**)&pQKV, g_qkv);
    cudaGetSymbolAddress((void**)&pQ,   g_q);
    cudaGetSymbolAddress((void**)&pK,   g_k);
    cudaGetSymbolAddress((void**)&pV,   g_v);
    cudaGetSymbolAddress((void**)&pO,   g_o);
    cudaGetSymbolAddress((void**)&pX1,  g_x1);
    cudaGetSymbolAddress((void**)&pFF,  g_ff);
    cudaGetSymbolAddress((void**)&pW,   g_w);

    __half* wqkv = pW;                       // [6144 x 2048]
    __half* wo   = pW + 12582912;            // [2048 x 2048]
    __half* wp   = pW + 16777216;            // [16384 x 2048] (permuted rows)
    __half* wff  = pW + 50331648;            // [2048 x 8192]

    static constexpr int GEMM_SMEM = 110592;
    static constexpr int ATTN_SMEM = 62464;
    cudaFuncSetAttribute(hgemm_kernel<0>, cudaFuncAttributeMaxDynamicSharedMemorySize, GEMM_SMEM);
    cudaFuncSetAttribute(hgemm_kernel<1>, cudaFuncAttributeMaxDynamicSharedMemorySize, GEMM_SMEM);
    cudaFuncSetAttribute(hgemm_kernel<2>, cudaFuncAttributeMaxDynamicSharedMemorySize, GEMM_SMEM);
    cudaFuncSetAttribute(attn_kernel, cudaFuncAttributeMaxDynamicSharedMemorySize, ATTN_SMEM);

    // 0. convert + transpose weights to half (Wp with swiglu row permutation)
    cvtw_t_kernel<false><<<dim3(6144/32,  2048/64), 256>>>(Wqkv, wqkv, 2048, 6144);
    cvtw_t_kernel<false><<<dim3(2048/32,  2048/64), 256>>>(Wo,   wo,   2048, 2048);
    cvtw_t_kernel<true ><<<dim3(16384/32, 2048/64), 256>>>(Wp,   wp,   2048, 16384);
    cvtw_t_kernel<false><<<dim3(2048/32,  8192/64), 256>>>(Wff,  wff,  8192, 2048);

    // 1. h = rms(x, g1)  (half)
    rmsnorm_kernel<<<NROWS, 256>>>(x, g1, pH);
    // 2. qkv = h @ Wqkv + bqkv  (half out)
    hgemm_kernel<1><<<dim3(6144/128, NROWS/256), 256, GEMM_SMEM>>>(
        pH, wqkv, bqkv, nullptr, pQKV, NROWS, 3*DM, DM);
    // 3. rope + split into Q/K/V (half)
    rope_split_kernel<<<(NROWS * NHEAD * 64) / 256, 256>>>(pQKV);
    // 4. causal attention -> O (half, fp16 MMA, LPT order, no ldmatrix)
    attn_kernel<<<dim3(2*NHEAD, SEQ/64), 128, ATTN_SMEM>>>(pQ, pK, pV, pO);
    // 5. x1 = O @ Wo + bo + x  (fp32 out, residual)
    hgemm_kernel<0><<<dim3(DM/128, NROWS/256), 256, GEMM_SMEM>>>(
        pO, wo, bo, x, pX1, NROWS, DM, DM);
    // 6. h2 = rms(x1, g2)  (half)
    rmsnorm_kernel<<<NROWS, 256>>>(pX1, g2, pH);
    // 7+8. ff = swiglu(h2 @ Wp + bp)  fused  (half out)
    hgemm_kernel<2><<<dim3(16384/128, NROWS/256), 256, GEMM_SMEM>>>(
        pH, wp, bp, nullptr, pFF, NROWS, 8*DM, DM);
    // 9. out = ff @ Wff_out + bff + x1  (fp32 out, residual)
    hgemm_kernel<0><<<dim3(DM/128, NROWS/256), 256, GEMM_SMEM>>>(
        pFF, wff, bff, pX1, out, NROWS, DM, 4*DM);
}